// round 12
// baseline (speedup 1.0000x reference)
#include <cuda_runtime.h>
#include <cuda_bf16.h>

// Scratch (device globals — no allocation allowed)
#define NMAX 20000
__device__ __align__(16) float g_ns_acc[NMAX * 64];    // h_ns_int (hs + scattered es)
__device__ __align__(16) float g_nv_acc[NMAX * 192];   // nv_int   (nv1 + scattered ev1)
__device__ __align__(16) float g_nt_norm[NMAX * 64];   // ||nt1||
__device__ __align__(16) float g_mid[NMAX * 96];       // silu(h_cat @ Wc1.T + bc1)

__device__ __forceinline__ float sigm_(float x) { return 1.0f / (1.0f + __expf(-x)); }
__device__ __forceinline__ float silu_(float x) { return x * sigm_(x); }

__device__ __forceinline__ void red_add_v4(float* p, float4 v) {
    asm volatile("red.global.add.v4.f32 [%0], {%1,%2,%3,%4};"
                 :: "l"(p), "f"(v.x), "f"(v.y), "f"(v.z), "f"(v.w) : "memory");
}

// Load W (O x K row-major) into smem transposed: sWt[k*wstride + o]
__device__ __forceinline__ void load_wt(const float* __restrict__ W, float* sWt,
                                        int O, int K, int wstride) {
    for (int i = threadIdx.x; i < O * K; i += blockDim.x) {
        int o = i / K, k = i - o * K;
        sWt[k * wstride + o] = W[i];
    }
}

// Same, but for W rows [o_begin, o_begin+O)
__device__ __forceinline__ void load_wt_part(const float* __restrict__ W, float* sWt,
                                             int o_begin, int O, int K, int wstride) {
    for (int i = threadIdx.x; i < O * K; i += blockDim.x) {
        int o = i / K, k = i - o * K;
        sWt[k * wstride + o] = W[(size_t)(o_begin + o) * K + k];
    }
}

template<int OPL>
__device__ __forceinline__ void zero8(float (&a)[8][OPL]) {
#pragma unroll
    for (int r = 0; r < 8; r++)
#pragma unroll
        for (int o = 0; o < OPL; o++) a[r][o] = 0.0f;
}

// Rolling-prefetch warp micro-GEMM, CONSTANT ADDRESSING:
// - k-step loop fully unrolled -> every k is a compile-time immediate
// - 8 row base pointers precomputed once -> loads are LDG [Rrow + imm], zero
//   per-step ALU (R10's regression was IMAD address math from dynamic ks)
// - per-row rolling prefetch: row r's step-(ks+1) load issues before row r's
//   FMAs for step ks; consumer ~2 steps (~64 FMA issue slots x 8 rows)
//   downstream, overlapping L2 latency with FMA issue.
template<int K, int OPL, bool XG>
__device__ __forceinline__ void wgemm8r(const float* __restrict__ xbase, int xstride,
                                        const float* __restrict__ sWt, int wstride, int ocol,
                                        float (&acc)[8][OPL], int lane) {
    const int o0 = ocol + OPL * lane;
    constexpr int NS = K / 4;
    const float* xr[8];
#pragma unroll
    for (int r = 0; r < 8; r++) xr[r] = xbase + (size_t)r * xstride;

    float4 xb[8];
#pragma unroll
    for (int r = 0; r < 8; r++)
        xb[r] = XG ? __ldg((const float4*)xr[r]) : *(const float4*)xr[r];

#pragma unroll
    for (int ks = 0; ks < NS; ks++) {
        const int k = ks * 4;   // compile-time constant after full unroll
        float w[4][OPL];
#pragma unroll
        for (int kk = 0; kk < 4; kk++) {
            const float* wp = sWt + (k + kk) * wstride + o0;
            if (OPL == 4) {
                float4 t = *(const float4*)wp;
                w[kk][0] = t.x; w[kk][1] = t.y; w[kk][2] = t.z; w[kk][3] = t.w;
            } else if (OPL == 2) {
                float2 t = *(const float2*)wp;
                w[kk][0] = t.x; w[kk][1] = t.y;
            } else {
                w[kk][0] = *wp;
            }
        }
#pragma unroll
        for (int r = 0; r < 8; r++) {
            float4 xn;
            if (ks + 1 < NS)
                xn = XG ? __ldg((const float4*)(xr[r] + k + 4))
                        : *(const float4*)(xr[r] + k + 4);
            float4 x = xb[r];
#pragma unroll
            for (int o = 0; o < OPL; o++)
                acc[r][o] += x.x * w[0][o] + x.y * w[1][o] + x.z * w[2][o] + x.w * w[3][o];
            if (ks + 1 < NS) xb[r] = xn;
        }
    }
}

// ---------------------------------------------------------------------------
// Kernel A: hs -> g_ns_acc, nv1 -> g_nv_acc, ||nt1|| -> g_nt_norm
// ---------------------------------------------------------------------------
#define A_SMEM_BYTES ((128*68 + 64*68 + 64*68 + 64*68 + 8*512) * 4)

__global__ void __launch_bounds__(256, 2) nodeA_kernel(
    const float* __restrict__ h_ns, const float* __restrict__ h_nv,
    const float* __restrict__ h_nt,
    const float* __restrict__ Wns1, const float* __restrict__ bns1,
    const float* __restrict__ Wns2, const float* __restrict__ bns2,
    const float* __restrict__ Wnv1, const float* __restrict__ Wnt1, int N)
{
    extern __shared__ float sm[];
    float* sWns1t = sm;
    float* sWns2t = sWns1t + 128 * 68;
    float* sWnv1t = sWns2t + 64 * 68;
    float* sWnt1t = sWnv1t + 64 * 68;
    float* sBuf   = sWnt1t + 64 * 68;

    load_wt(Wns1, sWns1t, 64, 128, 68);
    load_wt(Wns2, sWns2t, 64, 64, 68);
    load_wt(Wnv1, sWnv1t, 64, 64, 68);
    load_wt(Wnt1, sWnt1t, 64, 64, 68);
    __syncthreads();

    const int lane = threadIdx.x & 31;
    const int warp = threadIdx.x >> 5;
    float* sT = sBuf + warp * 512;

    const float b10 = __ldg(bns1 + 2 * lane), b11 = __ldg(bns1 + 2 * lane + 1);
    const float b20 = __ldg(bns2 + 2 * lane), b21 = __ldg(bns2 + 2 * lane + 1);

    const int gw = blockIdx.x * 8 + warp;
    const int GW = gridDim.x * 8;
    const int ngroups = N >> 3;

    for (int g = gw; g < ngroups; g += GW) {
        const int n0 = g * 8;

        float acc[8][2]; zero8(acc);
        wgemm8r<128, 2, true>(h_ns + (size_t)n0 * 128, 128, sWns1t, 68, 0, acc, lane);
        __syncwarp();
#pragma unroll
        for (int r = 0; r < 8; r++) {
            float2 v; v.x = silu_(acc[r][0] + b10); v.y = silu_(acc[r][1] + b11);
            *(float2*)&sT[r * 64 + 2 * lane] = v;
        }
        __syncwarp();

        float acc2[8][2]; zero8(acc2);
        wgemm8r<64, 2, false>(sT, 64, sWns2t, 68, 0, acc2, lane);
#pragma unroll
        for (int r = 0; r < 8; r++) {
            float2 v; v.x = acc2[r][0] + b20; v.y = acc2[r][1] + b21;
            *(float2*)&g_ns_acc[(size_t)(n0 + r) * 64 + 2 * lane] = v;
        }

#pragma unroll 1
        for (int a = 0; a < 3; a++) {
            float acc3[8][2]; zero8(acc3);
            wgemm8r<64, 2, true>(h_nv + (size_t)n0 * 192 + a * 64, 192, sWnv1t, 68, 0, acc3, lane);
#pragma unroll
            for (int r = 0; r < 8; r++) {
                float2 v; v.x = acc3[r][0]; v.y = acc3[r][1];
                *(float2*)&g_nv_acc[(size_t)(n0 + r) * 192 + a * 64 + 2 * lane] = v;
            }
        }

        float sq0[8], sq1[8];
#pragma unroll
        for (int r = 0; r < 8; r++) { sq0[r] = 0.0f; sq1[r] = 0.0f; }
#pragma unroll 1
        for (int c = 0; c < 9; c++) {
            float acc4[8][2]; zero8(acc4);
            wgemm8r<64, 2, true>(h_nt + (size_t)n0 * 576 + c * 64, 576, sWnt1t, 68, 0, acc4, lane);
#pragma unroll
            for (int r = 0; r < 8; r++) {
                sq0[r] += acc4[r][0] * acc4[r][0];
                sq1[r] += acc4[r][1] * acc4[r][1];
            }
        }
#pragma unroll
        for (int r = 0; r < 8; r++) {
            float2 v; v.x = sqrtf(sq0[r]); v.y = sqrtf(sq1[r]);
            *(float2*)&g_nt_norm[(size_t)(n0 + r) * 64 + 2 * lane] = v;
        }
    }
}

// ---------------------------------------------------------------------------
// Edge kernel (R8 structure): es MLP + ev1, scatter-add (v4 reds)
// ---------------------------------------------------------------------------
#define E_SMEM_BYTES ((128*68 + 64*68 + 64*68 + 8*1024) * 4)

__global__ void __launch_bounds__(256, 2) edge_kernel(
    const float* __restrict__ h_es, const float* __restrict__ h_ev,
    const int* __restrict__ idx1, const int* __restrict__ idx2,
    const float* __restrict__ Wes1, const float* __restrict__ bes1,
    const float* __restrict__ Wes2, const float* __restrict__ bes2,
    const float* __restrict__ Wev1, int E)
{
    extern __shared__ float sm[];
    float* sWes1t = sm;
    float* sWes2t = sWes1t + 128 * 68;
    float* sWev1t = sWes2t + 64 * 68;
    float* sBuf   = sWev1t + 64 * 68;

    load_wt(Wes1, sWes1t, 64, 128, 68);
    load_wt(Wes2, sWes2t, 64, 64, 68);
    load_wt(Wev1, sWev1t, 64, 64, 68);
    __syncthreads();

    const int lane = threadIdx.x & 31;
    const int warp = threadIdx.x >> 5;
    float* sT  = sBuf + warp * 1024;
    float* sEs = sT + 512;

    const float b10 = __ldg(bes1 + 2 * lane), b11 = __ldg(bes1 + 2 * lane + 1);
    const float b20 = __ldg(bes2 + 2 * lane), b21 = __ldg(bes2 + 2 * lane + 1);

    const int gw = blockIdx.x * 8 + warp;
    const int GW = gridDim.x * 8;
    const int ngroups = E >> 3;

    for (int g = gw; g < ngroups; g += GW) {
        const int e0 = g * 8;

        float acc[8][2]; zero8(acc);
        wgemm8r<128, 2, true>(h_es + (size_t)e0 * 128, 128, sWes1t, 68, 0, acc, lane);
        __syncwarp();
#pragma unroll
        for (int r = 0; r < 8; r++) {
            float2 v; v.x = silu_(acc[r][0] + b10); v.y = silu_(acc[r][1] + b11);
            *(float2*)&sT[r * 64 + 2 * lane] = v;
        }
        __syncwarp();

        float acc2[8][2]; zero8(acc2);
        wgemm8r<64, 2, false>(sT, 64, sWes2t, 68, 0, acc2, lane);
#pragma unroll
        for (int r = 0; r < 8; r++) {
            float2 v; v.x = acc2[r][0] + b20; v.y = acc2[r][1] + b21;
            *(float2*)&sEs[r * 64 + 2 * lane] = v;
        }
        __syncwarp();

#pragma unroll
        for (int j = 0; j < 4; j++) {
            int cid = lane + 32 * j;
            int r = cid >> 4, c = (cid & 15) * 4;
            float4 v = *(const float4*)&sEs[r * 64 + c];
            int i1 = __ldg(idx1 + e0 + r), i2 = __ldg(idx2 + e0 + r);
            red_add_v4(g_ns_acc + (size_t)i1 * 64 + c, v);
            red_add_v4(g_ns_acc + (size_t)i2 * 64 + c, v);
        }

#pragma unroll 1
        for (int a = 0; a < 3; a++) {
            float acc3[8][2]; zero8(acc3);
            wgemm8r<64, 2, true>(h_ev + (size_t)e0 * 192 + a * 64, 192, sWev1t, 68, 0, acc3, lane);
            __syncwarp();
#pragma unroll
            for (int r = 0; r < 8; r++) {
                float2 v; v.x = acc3[r][0]; v.y = acc3[r][1];
                *(float2*)&sEs[r * 64 + 2 * lane] = v;
            }
            __syncwarp();
#pragma unroll
            for (int j = 0; j < 4; j++) {
                int cid = lane + 32 * j;
                int r = cid >> 4, c = (cid & 15) * 4;
                float4 v = *(const float4*)&sEs[r * 64 + c];
                int i1 = __ldg(idx1 + e0 + r), i2 = __ldg(idx2 + e0 + r);
                red_add_v4(g_nv_acc + (size_t)i1 * 192 + a * 64 + c, v);
                red_add_v4(g_nv_acc + (size_t)i2 * 192 + a * 64 + c, v);
            }
        }
    }
}

// ---------------------------------------------------------------------------
// Kernel C1
// ---------------------------------------------------------------------------
#define C1_SMEM_BYTES ((192*100 + 8*1536) * 4)

__global__ void __launch_bounds__(256, 1) nodeC1_kernel(
    const float* __restrict__ Wc1, const float* __restrict__ bc1, int N)
{
    extern __shared__ float sm[];
    float* sWc1t = sm;
    float* sCatA = sWc1t + 192 * 100;

    load_wt(Wc1, sWc1t, 96, 192, 100);
    __syncthreads();

    const int lane = threadIdx.x & 31;
    const int warp = threadIdx.x >> 5;
    float* cat = sCatA + warp * 1536;

    const float bA0 = __ldg(bc1 + 2 * lane), bA1 = __ldg(bc1 + 2 * lane + 1);
    const float bB  = __ldg(bc1 + 64 + lane);

    const int gw = blockIdx.x * 8 + warp;
    const int GW = gridDim.x * 8;
    const int ngroups = N >> 3;

    for (int g = gw; g < ngroups; g += GW) {
        const int n0 = g * 8;
        __syncwarp();
#pragma unroll
        for (int r = 0; r < 8; r++) {
            const size_t n = (size_t)(n0 + r);
            float2 s = *(const float2*)&g_ns_acc[n * 64 + 2 * lane];
            *(float2*)&cat[r * 192 + 2 * lane] = s;
            float2 v0 = *(const float2*)&g_nv_acc[n * 192 + 0   + 2 * lane];
            float2 v1 = *(const float2*)&g_nv_acc[n * 192 + 64  + 2 * lane];
            float2 v2 = *(const float2*)&g_nv_acc[n * 192 + 128 + 2 * lane];
            float2 nn;
            nn.x = sqrtf(v0.x * v0.x + v1.x * v1.x + v2.x * v2.x);
            nn.y = sqrtf(v0.y * v0.y + v1.y * v1.y + v2.y * v2.y);
            *(float2*)&cat[r * 192 + 64 + 2 * lane] = nn;
            float2 tn = *(const float2*)&g_nt_norm[n * 64 + 2 * lane];
            *(float2*)&cat[r * 192 + 128 + 2 * lane] = tn;
        }
        __syncwarp();

        float accA[8][2]; zero8(accA);
        wgemm8r<192, 2, false>(cat, 192, sWc1t, 100, 0, accA, lane);
        float accB[8][1]; zero8(accB);
        wgemm8r<192, 1, false>(cat, 192, sWc1t, 100, 64, accB, lane);
#pragma unroll
        for (int r = 0; r < 8; r++) {
            const size_t n = (size_t)(n0 + r);
            float2 m; m.x = silu_(accA[r][0] + bA0); m.y = silu_(accA[r][1] + bA1);
            *(float2*)&g_mid[n * 96 + 2 * lane] = m;
            g_mid[n * 96 + 64 + lane] = silu_(accB[r][0] + bB);
        }
    }
}

// ---------------------------------------------------------------------------
// Kernel C2a: ns_out = g_mid @ Wc2[0:128].T + bc2[0:128] + h_ns
// ---------------------------------------------------------------------------
#define C2A_SMEM_BYTES ((96*132) * 4)

__global__ void __launch_bounds__(256, 2) nodeC2a_kernel(
    const float* __restrict__ h_ns,
    const float* __restrict__ Wc2, const float* __restrict__ bc2,
    float* __restrict__ out, int N)
{
    extern __shared__ float sm[];
    float* sW = sm;

    load_wt_part(Wc2, sW, 0, 128, 96, 132);
    __syncthreads();

    const int lane = threadIdx.x & 31;
    const int warp = threadIdx.x >> 5;

    const float b0 = __ldg(bc2 + 2 * lane),      b1 = __ldg(bc2 + 2 * lane + 1);
    const float b2 = __ldg(bc2 + 64 + 2 * lane), b3 = __ldg(bc2 + 64 + 2 * lane + 1);

    const int gw = blockIdx.x * 8 + warp;
    const int GW = gridDim.x * 8;
    const int ngroups = N >> 3;

    for (int g = gw; g < ngroups; g += GW) {
        const int n0 = g * 8;
        const float* mid = g_mid + (size_t)n0 * 96;

        float accA[8][2]; zero8(accA);
        wgemm8r<96, 2, true>(mid, 96, sW, 132, 0, accA, lane);
        float accB[8][2]; zero8(accB);
        wgemm8r<96, 2, true>(mid, 96, sW, 132, 64, accB, lane);

#pragma unroll
        for (int r = 0; r < 8; r++) {
            const size_t n = (size_t)(n0 + r);
            float2 hA = __ldg((const float2*)(h_ns + n * 128 + 2 * lane));
            float2 hB = __ldg((const float2*)(h_ns + n * 128 + 64 + 2 * lane));
            float2 vA, vB;
            vA.x = accA[r][0] + b0 + hA.x;
            vA.y = accA[r][1] + b1 + hA.y;
            vB.x = accB[r][0] + b2 + hB.x;
            vB.y = accB[r][1] + b3 + hB.y;
            *(float2*)&out[n * 128 + 2 * lane] = vA;
            *(float2*)&out[n * 128 + 64 + 2 * lane] = vB;
        }
    }
}

// ---------------------------------------------------------------------------
// Kernel C2b: gates in registers; nv_out / nt_out epilogues
// ---------------------------------------------------------------------------
#define C2B_SMEM_BYTES ((96*132 + 64*68 + 64*68) * 4)

__global__ void __launch_bounds__(256, 2) nodeC2b_kernel(
    const float* __restrict__ h_nv, const float* __restrict__ h_nt,
    const float* __restrict__ Wnv2, const float* __restrict__ Wnt2,
    const float* __restrict__ Wc2, const float* __restrict__ bc2,
    float* __restrict__ out, int N)
{
    extern __shared__ float sm[];
    float* sWg   = sm;
    float* sWnv2 = sWg + 96 * 132;
    float* sWnt2 = sWnv2 + 64 * 68;

    load_wt_part(Wc2, sWg, 128, 128, 96, 132);
    load_wt(Wnv2, sWnv2, 64, 64, 68);
    load_wt(Wnt2, sWnt2, 64, 64, 68);
    __syncthreads();

    const int lane = threadIdx.x & 31;
    const int warp = threadIdx.x >> 5;

    float* nv_out = out + (size_t)N * 128;
    float* nt_out = out + (size_t)N * 320;

    const float bn0 = __ldg(bc2 + 128 + 2 * lane), bn1 = __ldg(bc2 + 128 + 2 * lane + 1);
    const float bt0 = __ldg(bc2 + 192 + 2 * lane), bt1 = __ldg(bc2 + 192 + 2 * lane + 1);

    const int gw = blockIdx.x * 8 + warp;
    const int GW = gridDim.x * 8;
    const int ngroups = N >> 3;

    for (int g = gw; g < ngroups; g += GW) {
        const int n0 = g * 8;
        const float* mid = g_mid + (size_t)n0 * 96;

        float gA[8][2]; zero8(gA);
        wgemm8r<96, 2, true>(mid, 96, sWg, 132, 0, gA, lane);
#pragma unroll
        for (int r = 0; r < 8; r++) {
            gA[r][0] = sigm_(gA[r][0] + bn0);
            gA[r][1] = sigm_(gA[r][1] + bn1);
        }

#pragma unroll 1
        for (int a = 0; a < 3; a++) {
            float acc[8][2]; zero8(acc);
            wgemm8r<64, 2, true>(h_nv + (size_t)n0 * 192 + a * 64, 192, sWnv2, 68, 0, acc, lane);
#pragma unroll
            for (int r = 0; r < 8; r++) {
                const size_t n = (size_t)(n0 + r);
                float2 h = __ldg((const float2*)(h_nv + n * 192 + a * 64 + 2 * lane));
                float2 v;
                v.x = gA[r][0] * acc[r][0] + h.x;
                v.y = gA[r][1] * acc[r][1] + h.y;
                *(float2*)&nv_out[n * 192 + a * 64 + 2 * lane] = v;
            }
        }

        float gB[8][2]; zero8(gB);
        wgemm8r<96, 2, true>(mid, 96, sWg, 132, 64, gB, lane);
#pragma unroll
        for (int r = 0; r < 8; r++) {
            gB[r][0] = sigm_(gB[r][0] + bt0);
            gB[r][1] = sigm_(gB[r][1] + bt1);
        }

#pragma unroll 1
        for (int c = 0; c < 9; c++) {
            float acc[8][2]; zero8(acc);
            wgemm8r<64, 2, true>(h_nt + (size_t)n0 * 576 + c * 64, 576, sWnt2, 68, 0, acc, lane);
#pragma unroll
            for (int r = 0; r < 8; r++) {
                const size_t n = (size_t)(n0 + r);
                float2 h = __ldg((const float2*)(h_nt + n * 576 + c * 64 + 2 * lane));
                float2 v;
                v.x = gB[r][0] * acc[r][0] + h.x;
                v.y = gB[r][1] * acc[r][1] + h.y;
                *(float2*)&nt_out[n * 576 + c * 64 + 2 * lane] = v;
            }
        }
    }
}

// ---------------------------------------------------------------------------
extern "C" void kernel_launch(void* const* d_in, const int* in_sizes, int n_in,
                              void* d_out, int out_size)
{
    const float* h_ns = (const float*)d_in[0];
    const float* h_nv = (const float*)d_in[1];
    const float* h_nt = (const float*)d_in[2];
    const float* h_es = (const float*)d_in[3];
    const float* h_ev = (const float*)d_in[4];
    const int*   idx1 = (const int*)d_in[5];
    const int*   idx2 = (const int*)d_in[6];
    const float* Wns1 = (const float*)d_in[7];
    const float* bns1 = (const float*)d_in[8];
    const float* Wns2 = (const float*)d_in[9];
    const float* bns2 = (const float*)d_in[10];
    const float* Wes1 = (const float*)d_in[11];
    const float* bes1 = (const float*)d_in[12];
    const float* Wes2 = (const float*)d_in[13];
    const float* bes2 = (const float*)d_in[14];
    const float* Wnv1 = (const float*)d_in[15];
    const float* Wnv2 = (const float*)d_in[16];
    const float* Wev1 = (const float*)d_in[17];
    const float* Wnt1 = (const float*)d_in[18];
    const float* Wnt2 = (const float*)d_in[19];
    const float* Wc1  = (const float*)d_in[20];
    const float* bc1  = (const float*)d_in[21];
    const float* Wc2  = (const float*)d_in[22];
    const float* bc2  = (const float*)d_in[23];
    float* out = (float*)d_out;

    const int N = in_sizes[0] / 128;   // h_ns is (N, 128)
    const int E = in_sizes[5];         // atom_index1 is (E,)

    cudaFuncSetAttribute(nodeA_kernel,   cudaFuncAttributeMaxDynamicSharedMemorySize, A_SMEM_BYTES);
    cudaFuncSetAttribute(edge_kernel,    cudaFuncAttributeMaxDynamicSharedMemorySize, E_SMEM_BYTES);
    cudaFuncSetAttribute(nodeC1_kernel,  cudaFuncAttributeMaxDynamicSharedMemorySize, C1_SMEM_BYTES);
    cudaFuncSetAttribute(nodeC2a_kernel, cudaFuncAttributeMaxDynamicSharedMemorySize, C2A_SMEM_BYTES);
    cudaFuncSetAttribute(nodeC2b_kernel, cudaFuncAttributeMaxDynamicSharedMemorySize, C2B_SMEM_BYTES);

    nodeA_kernel<<<304, 256, A_SMEM_BYTES>>>(
        h_ns, h_nv, h_nt, Wns1, bns1, Wns2, bns2, Wnv1, Wnt1, N);

    edge_kernel<<<304, 256, E_SMEM_BYTES>>>(
        h_es, h_ev, idx1, idx2, Wes1, bes1, Wes2, bes2, Wev1, E);

    nodeC1_kernel<<<152, 256, C1_SMEM_BYTES>>>(Wc1, bc1, N);

    nodeC2a_kernel<<<304, 256, C2A_SMEM_BYTES>>>(h_ns, Wc2, bc2, out, N);

    nodeC2b_kernel<<<304, 256, C2B_SMEM_BYTES>>>(
        h_nv, h_nt, Wnv2, Wnt2, Wc2, bc2, out, N);
}

// round 13
// speedup vs baseline: 1.2488x; 1.2488x over previous
#include <cuda_runtime.h>
#include <cuda_bf16.h>

// Scratch (device globals — no allocation allowed)
#define NMAX 20000
__device__ __align__(16) float g_ns_acc[NMAX * 64];    // h_ns_int (hs + scattered es)
__device__ __align__(16) float g_nv_acc[NMAX * 192];   // nv_int   (nv1 + scattered ev1)
__device__ __align__(16) float g_nt_norm[NMAX * 64];   // ||nt1||
__device__ __align__(16) float g_mid[NMAX * 96];       // silu(h_cat @ Wc1.T + bc1)

__device__ __forceinline__ float sigm_(float x) { return 1.0f / (1.0f + __expf(-x)); }
__device__ __forceinline__ float silu_(float x) { return x * sigm_(x); }

__device__ __forceinline__ void red_add_v4(float* p, float4 v) {
    asm volatile("red.global.add.v4.f32 [%0], {%1,%2,%3,%4};"
                 :: "l"(p), "f"(v.x), "f"(v.y), "f"(v.z), "f"(v.w) : "memory");
}

// Load W (O x K row-major) into smem transposed: sWt[k*wstride + o]
__device__ __forceinline__ void load_wt(const float* __restrict__ W, float* sWt,
                                        int O, int K, int wstride) {
    for (int i = threadIdx.x; i < O * K; i += blockDim.x) {
        int o = i / K, k = i - o * K;
        sWt[k * wstride + o] = W[i];
    }
}

// Same, but for W rows [o_begin, o_begin+O)
__device__ __forceinline__ void load_wt_part(const float* __restrict__ W, float* sWt,
                                             int o_begin, int O, int K, int wstride) {
    for (int i = threadIdx.x; i < O * K; i += blockDim.x) {
        int o = i / K, k = i - o * K;
        sWt[k * wstride + o] = W[(size_t)(o_begin + o) * K + k];
    }
}

template<int OPL>
__device__ __forceinline__ void zero8(float (&a)[8][OPL]) {
#pragma unroll
    for (int r = 0; r < 8; r++)
#pragma unroll
        for (int o = 0; o < OPL; o++) a[r][o] = 0.0f;
}

// Plain warp micro-GEMM (R5/R8 proven): 8 rows x (32*OPL outs), unroll 4.
// Use for K >= 128 — the fully-unrolled variant regresses there (R12).
template<int K, int OPL, bool XG>
__device__ __forceinline__ void wgemm8(const float* __restrict__ xbase, int xstride,
                                       const float* __restrict__ sWt, int wstride, int ocol,
                                       float (&acc)[8][OPL], int lane) {
    const int o0 = ocol + OPL * lane;
#pragma unroll 4
    for (int k = 0; k < K; k += 4) {
        float w[4][OPL];
#pragma unroll
        for (int kk = 0; kk < 4; kk++) {
            const float* wp = sWt + (k + kk) * wstride + o0;
            if (OPL == 4) {
                float4 t = *(const float4*)wp;
                w[kk][0] = t.x; w[kk][1] = t.y; w[kk][2] = t.z; w[kk][3] = t.w;
            } else if (OPL == 2) {
                float2 t = *(const float2*)wp;
                w[kk][0] = t.x; w[kk][1] = t.y;
            } else {
                w[kk][0] = *wp;
            }
        }
#pragma unroll
        for (int r = 0; r < 8; r++) {
            float4 x;
            if (XG) x = __ldg((const float4*)(xbase + (size_t)r * xstride + k));
            else    x = *(const float4*)(xbase + (size_t)r * xstride + k);
#pragma unroll
            for (int o = 0; o < OPL; o++)
                acc[r][o] += x.x * w[0][o] + x.y * w[1][o] + x.z * w[2][o] + x.w * w[3][o];
        }
    }
}

// Rolling-prefetch warp micro-GEMM, constant addressing (R12-measured win at
// K<=96): k-loop fully unrolled (every k an immediate), row base pointers
// precomputed, per-row next-step prefetch overlaps memory latency with FMAs.
// DO NOT use for K>=128 (unroll cliff — R12 total regression).
template<int K, int OPL, bool XG>
__device__ __forceinline__ void wgemm8r(const float* __restrict__ xbase, int xstride,
                                        const float* __restrict__ sWt, int wstride, int ocol,
                                        float (&acc)[8][OPL], int lane) {
    const int o0 = ocol + OPL * lane;
    constexpr int NS = K / 4;
    const float* xr[8];
#pragma unroll
    for (int r = 0; r < 8; r++) xr[r] = xbase + (size_t)r * xstride;

    float4 xb[8];
#pragma unroll
    for (int r = 0; r < 8; r++)
        xb[r] = XG ? __ldg((const float4*)xr[r]) : *(const float4*)xr[r];

#pragma unroll
    for (int ks = 0; ks < NS; ks++) {
        const int k = ks * 4;   // compile-time constant after full unroll
        float w[4][OPL];
#pragma unroll
        for (int kk = 0; kk < 4; kk++) {
            const float* wp = sWt + (k + kk) * wstride + o0;
            if (OPL == 4) {
                float4 t = *(const float4*)wp;
                w[kk][0] = t.x; w[kk][1] = t.y; w[kk][2] = t.z; w[kk][3] = t.w;
            } else if (OPL == 2) {
                float2 t = *(const float2*)wp;
                w[kk][0] = t.x; w[kk][1] = t.y;
            } else {
                w[kk][0] = *wp;
            }
        }
#pragma unroll
        for (int r = 0; r < 8; r++) {
            float4 xn;
            if (ks + 1 < NS)
                xn = XG ? __ldg((const float4*)(xr[r] + k + 4))
                        : *(const float4*)(xr[r] + k + 4);
            float4 x = xb[r];
#pragma unroll
            for (int o = 0; o < OPL; o++)
                acc[r][o] += x.x * w[0][o] + x.y * w[1][o] + x.z * w[2][o] + x.w * w[3][o];
            if (ks + 1 < NS) xb[r] = xn;
        }
    }
}

// ---------------------------------------------------------------------------
// Kernel A: hs -> g_ns_acc, nv1 -> g_nv_acc, ||nt1|| -> g_nt_norm
// K=128 GEMM plain; K=64 GEMMs rolling-prefetch.
// ---------------------------------------------------------------------------
#define A_SMEM_BYTES ((128*68 + 64*68 + 64*68 + 64*68 + 8*512) * 4)

__global__ void __launch_bounds__(256, 2) nodeA_kernel(
    const float* __restrict__ h_ns, const float* __restrict__ h_nv,
    const float* __restrict__ h_nt,
    const float* __restrict__ Wns1, const float* __restrict__ bns1,
    const float* __restrict__ Wns2, const float* __restrict__ bns2,
    const float* __restrict__ Wnv1, const float* __restrict__ Wnt1, int N)
{
    extern __shared__ float sm[];
    float* sWns1t = sm;
    float* sWns2t = sWns1t + 128 * 68;
    float* sWnv1t = sWns2t + 64 * 68;
    float* sWnt1t = sWnv1t + 64 * 68;
    float* sBuf   = sWnt1t + 64 * 68;

    load_wt(Wns1, sWns1t, 64, 128, 68);
    load_wt(Wns2, sWns2t, 64, 64, 68);
    load_wt(Wnv1, sWnv1t, 64, 64, 68);
    load_wt(Wnt1, sWnt1t, 64, 64, 68);
    __syncthreads();

    const int lane = threadIdx.x & 31;
    const int warp = threadIdx.x >> 5;
    float* sT = sBuf + warp * 512;

    const float b10 = __ldg(bns1 + 2 * lane), b11 = __ldg(bns1 + 2 * lane + 1);
    const float b20 = __ldg(bns2 + 2 * lane), b21 = __ldg(bns2 + 2 * lane + 1);

    const int gw = blockIdx.x * 8 + warp;
    const int GW = gridDim.x * 8;
    const int ngroups = N >> 3;

    for (int g = gw; g < ngroups; g += GW) {
        const int n0 = g * 8;

        float acc[8][2]; zero8(acc);
        wgemm8<128, 2, true>(h_ns + (size_t)n0 * 128, 128, sWns1t, 68, 0, acc, lane);
        __syncwarp();
#pragma unroll
        for (int r = 0; r < 8; r++) {
            float2 v; v.x = silu_(acc[r][0] + b10); v.y = silu_(acc[r][1] + b11);
            *(float2*)&sT[r * 64 + 2 * lane] = v;
        }
        __syncwarp();

        float acc2[8][2]; zero8(acc2);
        wgemm8r<64, 2, false>(sT, 64, sWns2t, 68, 0, acc2, lane);
#pragma unroll
        for (int r = 0; r < 8; r++) {
            float2 v; v.x = acc2[r][0] + b20; v.y = acc2[r][1] + b21;
            *(float2*)&g_ns_acc[(size_t)(n0 + r) * 64 + 2 * lane] = v;
        }

#pragma unroll 1
        for (int a = 0; a < 3; a++) {
            float acc3[8][2]; zero8(acc3);
            wgemm8r<64, 2, true>(h_nv + (size_t)n0 * 192 + a * 64, 192, sWnv1t, 68, 0, acc3, lane);
#pragma unroll
            for (int r = 0; r < 8; r++) {
                float2 v; v.x = acc3[r][0]; v.y = acc3[r][1];
                *(float2*)&g_nv_acc[(size_t)(n0 + r) * 192 + a * 64 + 2 * lane] = v;
            }
        }

        float sq0[8], sq1[8];
#pragma unroll
        for (int r = 0; r < 8; r++) { sq0[r] = 0.0f; sq1[r] = 0.0f; }
#pragma unroll 1
        for (int c = 0; c < 9; c++) {
            float acc4[8][2]; zero8(acc4);
            wgemm8r<64, 2, true>(h_nt + (size_t)n0 * 576 + c * 64, 576, sWnt1t, 68, 0, acc4, lane);
#pragma unroll
            for (int r = 0; r < 8; r++) {
                sq0[r] += acc4[r][0] * acc4[r][0];
                sq1[r] += acc4[r][1] * acc4[r][1];
            }
        }
#pragma unroll
        for (int r = 0; r < 8; r++) {
            float2 v; v.x = sqrtf(sq0[r]); v.y = sqrtf(sq1[r]);
            *(float2*)&g_nt_norm[(size_t)(n0 + r) * 64 + 2 * lane] = v;
        }
    }
}

// ---------------------------------------------------------------------------
// Edge kernel: es MLP + ev1, scatter-add (v4 reds).
// K=128 GEMM plain; K=64 GEMMs rolling-prefetch.
// ---------------------------------------------------------------------------
#define E_SMEM_BYTES ((128*68 + 64*68 + 64*68 + 8*1024) * 4)

__global__ void __launch_bounds__(256, 2) edge_kernel(
    const float* __restrict__ h_es, const float* __restrict__ h_ev,
    const int* __restrict__ idx1, const int* __restrict__ idx2,
    const float* __restrict__ Wes1, const float* __restrict__ bes1,
    const float* __restrict__ Wes2, const float* __restrict__ bes2,
    const float* __restrict__ Wev1, int E)
{
    extern __shared__ float sm[];
    float* sWes1t = sm;
    float* sWes2t = sWes1t + 128 * 68;
    float* sWev1t = sWes2t + 64 * 68;
    float* sBuf   = sWev1t + 64 * 68;

    load_wt(Wes1, sWes1t, 64, 128, 68);
    load_wt(Wes2, sWes2t, 64, 64, 68);
    load_wt(Wev1, sWev1t, 64, 64, 68);
    __syncthreads();

    const int lane = threadIdx.x & 31;
    const int warp = threadIdx.x >> 5;
    float* sT  = sBuf + warp * 1024;
    float* sEs = sT + 512;

    const float b10 = __ldg(bes1 + 2 * lane), b11 = __ldg(bes1 + 2 * lane + 1);
    const float b20 = __ldg(bes2 + 2 * lane), b21 = __ldg(bes2 + 2 * lane + 1);

    const int gw = blockIdx.x * 8 + warp;
    const int GW = gridDim.x * 8;
    const int ngroups = E >> 3;

    for (int g = gw; g < ngroups; g += GW) {
        const int e0 = g * 8;

        float acc[8][2]; zero8(acc);
        wgemm8<128, 2, true>(h_es + (size_t)e0 * 128, 128, sWes1t, 68, 0, acc, lane);
        __syncwarp();
#pragma unroll
        for (int r = 0; r < 8; r++) {
            float2 v; v.x = silu_(acc[r][0] + b10); v.y = silu_(acc[r][1] + b11);
            *(float2*)&sT[r * 64 + 2 * lane] = v;
        }
        __syncwarp();

        float acc2[8][2]; zero8(acc2);
        wgemm8r<64, 2, false>(sT, 64, sWes2t, 68, 0, acc2, lane);
#pragma unroll
        for (int r = 0; r < 8; r++) {
            float2 v; v.x = acc2[r][0] + b20; v.y = acc2[r][1] + b21;
            *(float2*)&sEs[r * 64 + 2 * lane] = v;
        }
        __syncwarp();

#pragma unroll
        for (int j = 0; j < 4; j++) {
            int cid = lane + 32 * j;
            int r = cid >> 4, c = (cid & 15) * 4;
            float4 v = *(const float4*)&sEs[r * 64 + c];
            int i1 = __ldg(idx1 + e0 + r), i2 = __ldg(idx2 + e0 + r);
            red_add_v4(g_ns_acc + (size_t)i1 * 64 + c, v);
            red_add_v4(g_ns_acc + (size_t)i2 * 64 + c, v);
        }

#pragma unroll 1
        for (int a = 0; a < 3; a++) {
            float acc3[8][2]; zero8(acc3);
            wgemm8r<64, 2, true>(h_ev + (size_t)e0 * 192 + a * 64, 192, sWev1t, 68, 0, acc3, lane);
            __syncwarp();
#pragma unroll
            for (int r = 0; r < 8; r++) {
                float2 v; v.x = acc3[r][0]; v.y = acc3[r][1];
                *(float2*)&sEs[r * 64 + 2 * lane] = v;
            }
            __syncwarp();
#pragma unroll
            for (int j = 0; j < 4; j++) {
                int cid = lane + 32 * j;
                int r = cid >> 4, c = (cid & 15) * 4;
                float4 v = *(const float4*)&sEs[r * 64 + c];
                int i1 = __ldg(idx1 + e0 + r), i2 = __ldg(idx2 + e0 + r);
                red_add_v4(g_nv_acc + (size_t)i1 * 192 + a * 64 + c, v);
                red_add_v4(g_nv_acc + (size_t)i2 * 192 + a * 64 + c, v);
            }
        }
    }
}

// ---------------------------------------------------------------------------
// Kernel C1: K=192 GEMMs stay plain (past the unroll cliff).
// ---------------------------------------------------------------------------
#define C1_SMEM_BYTES ((192*100 + 8*1536) * 4)

__global__ void __launch_bounds__(256, 1) nodeC1_kernel(
    const float* __restrict__ Wc1, const float* __restrict__ bc1, int N)
{
    extern __shared__ float sm[];
    float* sWc1t = sm;
    float* sCatA = sWc1t + 192 * 100;

    load_wt(Wc1, sWc1t, 96, 192, 100);
    __syncthreads();

    const int lane = threadIdx.x & 31;
    const int warp = threadIdx.x >> 5;
    float* cat = sCatA + warp * 1536;

    const float bA0 = __ldg(bc1 + 2 * lane), bA1 = __ldg(bc1 + 2 * lane + 1);
    const float bB  = __ldg(bc1 + 64 + lane);

    const int gw = blockIdx.x * 8 + warp;
    const int GW = gridDim.x * 8;
    const int ngroups = N >> 3;

    for (int g = gw; g < ngroups; g += GW) {
        const int n0 = g * 8;
        __syncwarp();
#pragma unroll
        for (int r = 0; r < 8; r++) {
            const size_t n = (size_t)(n0 + r);
            float2 s = *(const float2*)&g_ns_acc[n * 64 + 2 * lane];
            *(float2*)&cat[r * 192 + 2 * lane] = s;
            float2 v0 = *(const float2*)&g_nv_acc[n * 192 + 0   + 2 * lane];
            float2 v1 = *(const float2*)&g_nv_acc[n * 192 + 64  + 2 * lane];
            float2 v2 = *(const float2*)&g_nv_acc[n * 192 + 128 + 2 * lane];
            float2 nn;
            nn.x = sqrtf(v0.x * v0.x + v1.x * v1.x + v2.x * v2.x);
            nn.y = sqrtf(v0.y * v0.y + v1.y * v1.y + v2.y * v2.y);
            *(float2*)&cat[r * 192 + 64 + 2 * lane] = nn;
            float2 tn = *(const float2*)&g_nt_norm[n * 64 + 2 * lane];
            *(float2*)&cat[r * 192 + 128 + 2 * lane] = tn;
        }
        __syncwarp();

        float accA[8][2]; zero8(accA);
        wgemm8<192, 2, false>(cat, 192, sWc1t, 100, 0, accA, lane);
        float accB[8][1]; zero8(accB);
        wgemm8<192, 1, false>(cat, 192, sWc1t, 100, 64, accB, lane);
#pragma unroll
        for (int r = 0; r < 8; r++) {
            const size_t n = (size_t)(n0 + r);
            float2 m; m.x = silu_(accA[r][0] + bA0); m.y = silu_(accA[r][1] + bA1);
            *(float2*)&g_mid[n * 96 + 2 * lane] = m;
            g_mid[n * 96 + 64 + lane] = silu_(accB[r][0] + bB);
        }
    }
}

// ---------------------------------------------------------------------------
// Kernel C2a: ns_out = g_mid @ Wc2[0:128].T + bc2[0:128] + h_ns  (K=96 -> r)
// ---------------------------------------------------------------------------
#define C2A_SMEM_BYTES ((96*132) * 4)

__global__ void __launch_bounds__(256, 2) nodeC2a_kernel(
    const float* __restrict__ h_ns,
    const float* __restrict__ Wc2, const float* __restrict__ bc2,
    float* __restrict__ out, int N)
{
    extern __shared__ float sm[];
    float* sW = sm;

    load_wt_part(Wc2, sW, 0, 128, 96, 132);
    __syncthreads();

    const int lane = threadIdx.x & 31;
    const int warp = threadIdx.x >> 5;

    const float b0 = __ldg(bc2 + 2 * lane),      b1 = __ldg(bc2 + 2 * lane + 1);
    const float b2 = __ldg(bc2 + 64 + 2 * lane), b3 = __ldg(bc2 + 64 + 2 * lane + 1);

    const int gw = blockIdx.x * 8 + warp;
    const int GW = gridDim.x * 8;
    const int ngroups = N >> 3;

    for (int g = gw; g < ngroups; g += GW) {
        const int n0 = g * 8;
        const float* mid = g_mid + (size_t)n0 * 96;

        float accA[8][2]; zero8(accA);
        wgemm8r<96, 2, true>(mid, 96, sW, 132, 0, accA, lane);
        float accB[8][2]; zero8(accB);
        wgemm8r<96, 2, true>(mid, 96, sW, 132, 64, accB, lane);

#pragma unroll
        for (int r = 0; r < 8; r++) {
            const size_t n = (size_t)(n0 + r);
            float2 hA = __ldg((const float2*)(h_ns + n * 128 + 2 * lane));
            float2 hB = __ldg((const float2*)(h_ns + n * 128 + 64 + 2 * lane));
            float2 vA, vB;
            vA.x = accA[r][0] + b0 + hA.x;
            vA.y = accA[r][1] + b1 + hA.y;
            vB.x = accB[r][0] + b2 + hB.x;
            vB.y = accB[r][1] + b3 + hB.y;
            *(float2*)&out[n * 128 + 2 * lane] = vA;
            *(float2*)&out[n * 128 + 64 + 2 * lane] = vB;
        }
    }
}

// ---------------------------------------------------------------------------
// Kernel C2b: gates in registers; nv_out / nt_out epilogues (K=96/64 -> r)
// ---------------------------------------------------------------------------
#define C2B_SMEM_BYTES ((96*132 + 64*68 + 64*68) * 4)

__global__ void __launch_bounds__(256, 2) nodeC2b_kernel(
    const float* __restrict__ h_nv, const float* __restrict__ h_nt,
    const float* __restrict__ Wnv2, const float* __restrict__ Wnt2,
    const float* __restrict__ Wc2, const float* __restrict__ bc2,
    float* __restrict__ out, int N)
{
    extern __shared__ float sm[];
    float* sWg   = sm;
    float* sWnv2 = sWg + 96 * 132;
    float* sWnt2 = sWnv2 + 64 * 68;

    load_wt_part(Wc2, sWg, 128, 128, 96, 132);
    load_wt(Wnv2, sWnv2, 64, 64, 68);
    load_wt(Wnt2, sWnt2, 64, 64, 68);
    __syncthreads();

    const int lane = threadIdx.x & 31;
    const int warp = threadIdx.x >> 5;

    float* nv_out = out + (size_t)N * 128;
    float* nt_out = out + (size_t)N * 320;

    const float bn0 = __ldg(bc2 + 128 + 2 * lane), bn1 = __ldg(bc2 + 128 + 2 * lane + 1);
    const float bt0 = __ldg(bc2 + 192 + 2 * lane), bt1 = __ldg(bc2 + 192 + 2 * lane + 1);

    const int gw = blockIdx.x * 8 + warp;
    const int GW = gridDim.x * 8;
    const int ngroups = N >> 3;

    for (int g = gw; g < ngroups; g += GW) {
        const int n0 = g * 8;
        const float* mid = g_mid + (size_t)n0 * 96;

        float gA[8][2]; zero8(gA);
        wgemm8r<96, 2, true>(mid, 96, sWg, 132, 0, gA, lane);
#pragma unroll
        for (int r = 0; r < 8; r++) {
            gA[r][0] = sigm_(gA[r][0] + bn0);
            gA[r][1] = sigm_(gA[r][1] + bn1);
        }

#pragma unroll 1
        for (int a = 0; a < 3; a++) {
            float acc[8][2]; zero8(acc);
            wgemm8r<64, 2, true>(h_nv + (size_t)n0 * 192 + a * 64, 192, sWnv2, 68, 0, acc, lane);
#pragma unroll
            for (int r = 0; r < 8; r++) {
                const size_t n = (size_t)(n0 + r);
                float2 h = __ldg((const float2*)(h_nv + n * 192 + a * 64 + 2 * lane));
                float2 v;
                v.x = gA[r][0] * acc[r][0] + h.x;
                v.y = gA[r][1] * acc[r][1] + h.y;
                *(float2*)&nv_out[n * 192 + a * 64 + 2 * lane] = v;
            }
        }

        float gB[8][2]; zero8(gB);
        wgemm8r<96, 2, true>(mid, 96, sWg, 132, 64, gB, lane);
#pragma unroll
        for (int r = 0; r < 8; r++) {
            gB[r][0] = sigm_(gB[r][0] + bt0);
            gB[r][1] = sigm_(gB[r][1] + bt1);
        }

#pragma unroll 1
        for (int c = 0; c < 9; c++) {
            float acc[8][2]; zero8(acc);
            wgemm8r<64, 2, true>(h_nt + (size_t)n0 * 576 + c * 64, 576, sWnt2, 68, 0, acc, lane);
#pragma unroll
            for (int r = 0; r < 8; r++) {
                const size_t n = (size_t)(n0 + r);
                float2 h = __ldg((const float2*)(h_nt + n * 576 + c * 64 + 2 * lane));
                float2 v;
                v.x = gB[r][0] * acc[r][0] + h.x;
                v.y = gB[r][1] * acc[r][1] + h.y;
                *(float2*)&nt_out[n * 576 + c * 64 + 2 * lane] = v;
            }
        }
    }
}

// ---------------------------------------------------------------------------
extern "C" void kernel_launch(void* const* d_in, const int* in_sizes, int n_in,
                              void* d_out, int out_size)
{
    const float* h_ns = (const float*)d_in[0];
    const float* h_nv = (const float*)d_in[1];
    const float* h_nt = (const float*)d_in[2];
    const float* h_es = (const float*)d_in[3];
    const float* h_ev = (const float*)d_in[4];
    const int*   idx1 = (const int*)d_in[5];
    const int*   idx2 = (const int*)d_in[6];
    const float* Wns1 = (const float*)d_in[7];
    const float* bns1 = (const float*)d_in[8];
    const float* Wns2 = (const float*)d_in[9];
    const float* bns2 = (const float*)d_in[10];
    const float* Wes1 = (const float*)d_in[11];
    const float* bes1 = (const float*)d_in[12];
    const float* Wes2 = (const float*)d_in[13];
    const float* bes2 = (const float*)d_in[14];
    const float* Wnv1 = (const float*)d_in[15];
    const float* Wnv2 = (const float*)d_in[16];
    const float* Wev1 = (const float*)d_in[17];
    const float* Wnt1 = (const float*)d_in[18];
    const float* Wnt2 = (const float*)d_in[19];
    const float* Wc1  = (const float*)d_in[20];
    const float* bc1  = (const float*)d_in[21];
    const float* Wc2  = (const float*)d_in[22];
    const float* bc2  = (const float*)d_in[23];
    float* out = (float*)d_out;

    const int N = in_sizes[0] / 128;   // h_ns is (N, 128)
    const int E = in_sizes[5];         // atom_index1 is (E,)

    cudaFuncSetAttribute(nodeA_kernel,   cudaFuncAttributeMaxDynamicSharedMemorySize, A_SMEM_BYTES);
    cudaFuncSetAttribute(edge_kernel,    cudaFuncAttributeMaxDynamicSharedMemorySize, E_SMEM_BYTES);
    cudaFuncSetAttribute(nodeC1_kernel,  cudaFuncAttributeMaxDynamicSharedMemorySize, C1_SMEM_BYTES);
    cudaFuncSetAttribute(nodeC2a_kernel, cudaFuncAttributeMaxDynamicSharedMemorySize, C2A_SMEM_BYTES);
    cudaFuncSetAttribute(nodeC2b_kernel, cudaFuncAttributeMaxDynamicSharedMemorySize, C2B_SMEM_BYTES);

    nodeA_kernel<<<304, 256, A_SMEM_BYTES>>>(
        h_ns, h_nv, h_nt, Wns1, bns1, Wns2, bns2, Wnv1, Wnt1, N);

    edge_kernel<<<304, 256, E_SMEM_BYTES>>>(
        h_es, h_ev, idx1, idx2, Wes1, bes1, Wes2, bes2, Wev1, E);

    nodeC1_kernel<<<152, 256, C1_SMEM_BYTES>>>(Wc1, bc1, N);

    nodeC2a_kernel<<<304, 256, C2A_SMEM_BYTES>>>(h_ns, Wc2, bc2, out, N);

    nodeC2b_kernel<<<304, 256, C2B_SMEM_BYTES>>>(
        h_nv, h_nt, Wnv2, Wnt2, Wc2, bc2, out, N);
}

// round 14
// speedup vs baseline: 1.9182x; 1.5361x over previous
#include <cuda_runtime.h>
#include <cuda_bf16.h>
#include <cstdint>

// Scratch (device globals — no allocation allowed)
#define NMAX 20000
__device__ __align__(16) float g_ns_acc[NMAX * 64];    // h_ns_int (hs + scattered es)
__device__ __align__(16) float g_nv_acc[NMAX * 192];   // nv_int   (nv1 + scattered ev1)
__device__ __align__(16) float g_nt_norm[NMAX * 64];   // ||nt1||
__device__ __align__(16) float g_mid[NMAX * 96];       // silu(h_cat @ Wc1.T + bc1)

__device__ __forceinline__ float sigm_(float x) { return 1.0f / (1.0f + __expf(-x)); }
__device__ __forceinline__ float silu_(float x) { return x * sigm_(x); }

__device__ __forceinline__ void red_add_v4(float* p, float4 v) {
    asm volatile("red.global.add.v4.f32 [%0], {%1,%2,%3,%4};"
                 :: "l"(p), "f"(v.x), "f"(v.y), "f"(v.z), "f"(v.w) : "memory");
}

// tf32 round (rna), result as float bit-pattern / raw u32
__device__ __forceinline__ float tf32f(float x) {
    uint32_t u; asm("cvt.rna.tf32.f32 %0, %1;" : "=r"(u) : "f"(x));
    return __uint_as_float(u);
}
__device__ __forceinline__ uint32_t tf32u(float x) {
    uint32_t u; asm("cvt.rna.tf32.f32 %0, %1;" : "=r"(u) : "f"(x));
    return u;
}

// m16n8k8 tf32 MMA, fp32 accumulate (HMMA fallback path on sm_103a)
__device__ __forceinline__ void mma16n8k8(float (&c)[4],
                                          uint32_t a0, uint32_t a1, uint32_t a2, uint32_t a3,
                                          uint32_t b0, uint32_t b1) {
    asm volatile("mma.sync.aligned.m16n8k8.row.col.f32.tf32.tf32.f32 "
                 "{%0,%1,%2,%3}, {%4,%5,%6,%7}, {%8,%9}, {%0,%1,%2,%3};"
                 : "+f"(c[0]), "+f"(c[1]), "+f"(c[2]), "+f"(c[3])
                 : "r"(a0), "r"(a1), "r"(a2), "r"(a3), "r"(b0), "r"(b1));
}

// Load W (O x K row-major) into smem transposed: sWt[k*wstride + o]
__device__ __forceinline__ void load_wt(const float* __restrict__ W, float* sWt,
                                        int O, int K, int wstride) {
    for (int i = threadIdx.x; i < O * K; i += blockDim.x) {
        int o = i / K, k = i - o * K;
        sWt[k * wstride + o] = W[i];
    }
}

// Same, but for W rows [o_begin, o_begin+O)
__device__ __forceinline__ void load_wt_part(const float* __restrict__ W, float* sWt,
                                             int o_begin, int O, int K, int wstride) {
    for (int i = threadIdx.x; i < O * K; i += blockDim.x) {
        int o = i / K, k = i - o * K;
        sWt[k * wstride + o] = W[(size_t)(o_begin + o) * K + k];
    }
}

// Load W (O x K row-major) into smem transposed AND tf32-rounded
__device__ __forceinline__ void load_wt_tf32(const float* __restrict__ W, float* sWt,
                                             int O, int K, int wstride) {
    for (int i = threadIdx.x; i < O * K; i += blockDim.x) {
        int o = i / K, k = i - o * K;
        sWt[k * wstride + o] = tf32f(W[i]);
    }
}

template<int OPL>
__device__ __forceinline__ void zero8(float (&a)[8][OPL]) {
#pragma unroll
    for (int r = 0; r < 8; r++)
#pragma unroll
        for (int o = 0; o < OPL; o++) a[r][o] = 0.0f;
}

// Plain warp micro-GEMM (R5/R8 proven): 8 rows x (32*OPL outs), unroll 4.
template<int K, int OPL, bool XG>
__device__ __forceinline__ void wgemm8(const float* __restrict__ xbase, int xstride,
                                       const float* __restrict__ sWt, int wstride, int ocol,
                                       float (&acc)[8][OPL], int lane) {
    const int o0 = ocol + OPL * lane;
#pragma unroll 4
    for (int k = 0; k < K; k += 4) {
        float w[4][OPL];
#pragma unroll
        for (int kk = 0; kk < 4; kk++) {
            const float* wp = sWt + (k + kk) * wstride + o0;
            if (OPL == 4) {
                float4 t = *(const float4*)wp;
                w[kk][0] = t.x; w[kk][1] = t.y; w[kk][2] = t.z; w[kk][3] = t.w;
            } else if (OPL == 2) {
                float2 t = *(const float2*)wp;
                w[kk][0] = t.x; w[kk][1] = t.y;
            } else {
                w[kk][0] = *wp;
            }
        }
#pragma unroll
        for (int r = 0; r < 8; r++) {
            float4 x;
            if (XG) x = __ldg((const float4*)(xbase + (size_t)r * xstride + k));
            else    x = *(const float4*)(xbase + (size_t)r * xstride + k);
#pragma unroll
            for (int o = 0; o < OPL; o++)
                acc[r][o] += x.x * w[0][o] + x.y * w[1][o] + x.z * w[2][o] + x.w * w[3][o];
        }
    }
}

// Rolling-prefetch variant (R12-measured win at K<=96 in small kernels only)
template<int K, int OPL, bool XG>
__device__ __forceinline__ void wgemm8r(const float* __restrict__ xbase, int xstride,
                                        const float* __restrict__ sWt, int wstride, int ocol,
                                        float (&acc)[8][OPL], int lane) {
    const int o0 = ocol + OPL * lane;
    constexpr int NS = K / 4;
    const float* xr[8];
#pragma unroll
    for (int r = 0; r < 8; r++) xr[r] = xbase + (size_t)r * xstride;

    float4 xb[8];
#pragma unroll
    for (int r = 0; r < 8; r++)
        xb[r] = XG ? __ldg((const float4*)xr[r]) : *(const float4*)xr[r];

#pragma unroll
    for (int ks = 0; ks < NS; ks++) {
        const int k = ks * 4;
        float w[4][OPL];
#pragma unroll
        for (int kk = 0; kk < 4; kk++) {
            const float* wp = sWt + (k + kk) * wstride + o0;
            if (OPL == 4) {
                float4 t = *(const float4*)wp;
                w[kk][0] = t.x; w[kk][1] = t.y; w[kk][2] = t.z; w[kk][3] = t.w;
            } else if (OPL == 2) {
                float2 t = *(const float2*)wp;
                w[kk][0] = t.x; w[kk][1] = t.y;
            } else {
                w[kk][0] = *wp;
            }
        }
#pragma unroll
        for (int r = 0; r < 8; r++) {
            float4 xn;
            if (ks + 1 < NS)
                xn = XG ? __ldg((const float4*)(xr[r] + k + 4))
                        : *(const float4*)(xr[r] + k + 4);
            float4 x = xb[r];
#pragma unroll
            for (int o = 0; o < OPL; o++)
                acc[r][o] += x.x * w[0][o] + x.y * w[1][o] + x.z * w[2][o] + x.w * w[3][o];
            if (ks + 1 < NS) xb[r] = xn;
        }
    }
}

// ---------------------------------------------------------------------------
// Kernel A (R8-exact): hs -> g_ns_acc, nv1 -> g_nv_acc, ||nt1|| -> g_nt_norm
// ---------------------------------------------------------------------------
#define A_SMEM_BYTES ((128*68 + 64*68 + 64*68 + 64*68 + 8*512) * 4)

__global__ void __launch_bounds__(256, 2) nodeA_kernel(
    const float* __restrict__ h_ns, const float* __restrict__ h_nv,
    const float* __restrict__ h_nt,
    const float* __restrict__ Wns1, const float* __restrict__ bns1,
    const float* __restrict__ Wns2, const float* __restrict__ bns2,
    const float* __restrict__ Wnv1, const float* __restrict__ Wnt1, int N)
{
    extern __shared__ float sm[];
    float* sWns1t = sm;
    float* sWns2t = sWns1t + 128 * 68;
    float* sWnv1t = sWns2t + 64 * 68;
    float* sWnt1t = sWnv1t + 64 * 68;
    float* sBuf   = sWnt1t + 64 * 68;

    load_wt(Wns1, sWns1t, 64, 128, 68);
    load_wt(Wns2, sWns2t, 64, 64, 68);
    load_wt(Wnv1, sWnv1t, 64, 64, 68);
    load_wt(Wnt1, sWnt1t, 64, 64, 68);
    __syncthreads();

    const int lane = threadIdx.x & 31;
    const int warp = threadIdx.x >> 5;
    float* sT = sBuf + warp * 512;

    const float b10 = __ldg(bns1 + 2 * lane), b11 = __ldg(bns1 + 2 * lane + 1);
    const float b20 = __ldg(bns2 + 2 * lane), b21 = __ldg(bns2 + 2 * lane + 1);

    const int gw = blockIdx.x * 8 + warp;
    const int GW = gridDim.x * 8;
    const int ngroups = N >> 3;

    for (int g = gw; g < ngroups; g += GW) {
        const int n0 = g * 8;

        float acc[8][2]; zero8(acc);
        wgemm8<128, 2, true>(h_ns + (size_t)n0 * 128, 128, sWns1t, 68, 0, acc, lane);
        __syncwarp();
#pragma unroll
        for (int r = 0; r < 8; r++) {
            float2 v; v.x = silu_(acc[r][0] + b10); v.y = silu_(acc[r][1] + b11);
            *(float2*)&sT[r * 64 + 2 * lane] = v;
        }
        __syncwarp();

        float acc2[8][2]; zero8(acc2);
        wgemm8<64, 2, false>(sT, 64, sWns2t, 68, 0, acc2, lane);
#pragma unroll
        for (int r = 0; r < 8; r++) {
            float2 v; v.x = acc2[r][0] + b20; v.y = acc2[r][1] + b21;
            *(float2*)&g_ns_acc[(size_t)(n0 + r) * 64 + 2 * lane] = v;
        }

#pragma unroll 1
        for (int a = 0; a < 3; a++) {
            float acc3[8][2]; zero8(acc3);
            wgemm8<64, 2, true>(h_nv + (size_t)n0 * 192 + a * 64, 192, sWnv1t, 68, 0, acc3, lane);
#pragma unroll
            for (int r = 0; r < 8; r++) {
                float2 v; v.x = acc3[r][0]; v.y = acc3[r][1];
                *(float2*)&g_nv_acc[(size_t)(n0 + r) * 192 + a * 64 + 2 * lane] = v;
            }
        }

        float sq0[8], sq1[8];
#pragma unroll
        for (int r = 0; r < 8; r++) { sq0[r] = 0.0f; sq1[r] = 0.0f; }
#pragma unroll 1
        for (int c = 0; c < 9; c++) {
            float acc4[8][2]; zero8(acc4);
            wgemm8<64, 2, true>(h_nt + (size_t)n0 * 576 + c * 64, 576, sWnt1t, 68, 0, acc4, lane);
#pragma unroll
            for (int r = 0; r < 8; r++) {
                sq0[r] += acc4[r][0] * acc4[r][0];
                sq1[r] += acc4[r][1] * acc4[r][1];
            }
        }
#pragma unroll
        for (int r = 0; r < 8; r++) {
            float2 v; v.x = sqrtf(sq0[r]); v.y = sqrtf(sq1[r]);
            *(float2*)&g_nt_norm[(size_t)(n0 + r) * 64 + 2 * lane] = v;
        }
    }
}

// ---------------------------------------------------------------------------
// Edge kernel (NEW): tf32 mma.sync. Per-warp 16 edges.
//   GEMM1 (K=128): es hidden; GEMM2 (K=64): es; GEMM3 x3 (K=64): ev1.
// Weights tf32-rounded in smem [k][n], stride 72 (B-frag conflict-free).
// T/ES staging per warp: 16 x stride 68 (A-frag conflict-free).
// smem: (128+64+64)*72 + 8*16*68 = 27136 floats (108,544 B) -> 2 CTAs/SM.
// ---------------------------------------------------------------------------
#define EW_ST 72
#define ET_ST 68
#define E_SMEM_BYTES ((128*EW_ST + 64*EW_ST + 64*EW_ST + 8*16*ET_ST) * 4)

__global__ void __launch_bounds__(256, 2) edge_kernel(
    const float* __restrict__ h_es, const float* __restrict__ h_ev,
    const int* __restrict__ idx1, const int* __restrict__ idx2,
    const float* __restrict__ Wes1, const float* __restrict__ bes1,
    const float* __restrict__ Wes2, const float* __restrict__ bes2,
    const float* __restrict__ Wev1, int E)
{
    extern __shared__ float sm[];
    float* sB1  = sm;                    // 128 x 72 (tf32 of Wes1, [k][n])
    float* sB2  = sB1 + 128 * EW_ST;     // 64 x 72
    float* sBev = sB2 + 64 * EW_ST;      // 64 x 72
    float* sTA  = sBev + 64 * EW_ST;     // 8 warps x 16 x 68

    load_wt_tf32(Wes1, sB1, 64, 128, EW_ST);
    load_wt_tf32(Wes2, sB2, 64, 64, EW_ST);
    load_wt_tf32(Wev1, sBev, 64, 64, EW_ST);
    __syncthreads();

    const int lane = threadIdx.x & 31;
    const int warp = threadIdx.x >> 5;
    const int gid = lane >> 2;          // 0..7
    const int tig = lane & 3;           // 0..3
    float* sT = sTA + warp * (16 * ET_ST);

    const int gw = blockIdx.x * 8 + warp;
    const int GW = gridDim.x * 8;
    const int ngroups = E >> 4;          // 16 edges per group

    for (int g = gw; g < ngroups; g += GW) {
        const int e0 = g * 16;

        // ---------------- GEMM1: T = silu(h_es @ Wes1.T + b)  (K=128) ------
        float C[8][4];
#pragma unroll
        for (int t = 0; t < 8; t++) { C[t][0]=0.f; C[t][1]=0.f; C[t][2]=0.f; C[t][3]=0.f; }
        {
            const float* rA0 = h_es + (size_t)(e0 + gid) * 128;
            const float* rA1 = rA0 + 8 * 128;
#pragma unroll
            for (int kc = 0; kc < 16; kc++) {
                const int k0 = kc * 8;
                uint32_t a0 = tf32u(__ldg(rA0 + k0 + tig));
                uint32_t a1 = tf32u(__ldg(rA1 + k0 + tig));
                uint32_t a2 = tf32u(__ldg(rA0 + k0 + tig + 4));
                uint32_t a3 = tf32u(__ldg(rA1 + k0 + tig + 4));
                const float* bp0 = sB1 + (k0 + tig) * EW_ST + gid;
                const float* bp1 = bp0 + 4 * EW_ST;
#pragma unroll
                for (int t = 0; t < 8; t++) {
                    uint32_t b0 = __float_as_uint(bp0[8 * t]);
                    uint32_t b1 = __float_as_uint(bp1[8 * t]);
                    mma16n8k8(C[t], a0, a1, a2, a3, b0, b1);
                }
            }
        }
        __syncwarp();
#pragma unroll
        for (int t = 0; t < 8; t++) {
            float2 bb = __ldg((const float2*)(bes1 + 8 * t + 2 * tig));
            float2 lo, hi;
            lo.x = silu_(C[t][0] + bb.x); lo.y = silu_(C[t][1] + bb.y);
            hi.x = silu_(C[t][2] + bb.x); hi.y = silu_(C[t][3] + bb.y);
            *(float2*)&sT[gid * ET_ST + 8 * t + 2 * tig] = lo;
            *(float2*)&sT[(gid + 8) * ET_ST + 8 * t + 2 * tig] = hi;
        }
        __syncwarp();

        // ---------------- GEMM2: ES = T @ Wes2.T + b  (K=64) ---------------
        float D[8][4];
#pragma unroll
        for (int t = 0; t < 8; t++) { D[t][0]=0.f; D[t][1]=0.f; D[t][2]=0.f; D[t][3]=0.f; }
#pragma unroll
        for (int kc = 0; kc < 8; kc++) {
            const int k0 = kc * 8;
            uint32_t a0 = tf32u(sT[gid * ET_ST + k0 + tig]);
            uint32_t a1 = tf32u(sT[(gid + 8) * ET_ST + k0 + tig]);
            uint32_t a2 = tf32u(sT[gid * ET_ST + k0 + tig + 4]);
            uint32_t a3 = tf32u(sT[(gid + 8) * ET_ST + k0 + tig + 4]);
            const float* bp0 = sB2 + (k0 + tig) * EW_ST + gid;
            const float* bp1 = bp0 + 4 * EW_ST;
#pragma unroll
            for (int t = 0; t < 8; t++) {
                uint32_t b0 = __float_as_uint(bp0[8 * t]);
                uint32_t b1 = __float_as_uint(bp1[8 * t]);
                mma16n8k8(D[t], a0, a1, a2, a3, b0, b1);
            }
        }
        __syncwarp();   // all lanes done reading sT before overwrite
#pragma unroll
        for (int t = 0; t < 8; t++) {
            float2 bb = __ldg((const float2*)(bes2 + 8 * t + 2 * tig));
            float2 lo, hi;
            lo.x = D[t][0] + bb.x; lo.y = D[t][1] + bb.y;
            hi.x = D[t][2] + bb.x; hi.y = D[t][3] + bb.y;
            *(float2*)&sT[gid * ET_ST + 8 * t + 2 * tig] = lo;
            *(float2*)&sT[(gid + 8) * ET_ST + 8 * t + 2 * tig] = hi;
        }
        __syncwarp();

        // scatter ES (16 rows x 64 cols) into g_ns_acc at idx1 and idx2
#pragma unroll
        for (int j = 0; j < 8; j++) {
            int cid = lane + 32 * j;           // 0..255
            int r = cid >> 4, c = (cid & 15) * 4;
            float4 v = *(const float4*)&sT[r * ET_ST + c];
            int i1 = __ldg(idx1 + e0 + r), i2 = __ldg(idx2 + e0 + r);
            red_add_v4(g_ns_acc + (size_t)i1 * 64 + c, v);
            red_add_v4(g_ns_acc + (size_t)i2 * 64 + c, v);
        }

        // ---------------- GEMM3 x3: EV = h_ev @ Wev1.T  (K=64) -------------
#pragma unroll 1
        for (int a = 0; a < 3; a++) {
            float Ea[8][4];
#pragma unroll
            for (int t = 0; t < 8; t++) { Ea[t][0]=0.f; Ea[t][1]=0.f; Ea[t][2]=0.f; Ea[t][3]=0.f; }
            const float* rV0 = h_ev + (size_t)(e0 + gid) * 192 + a * 64;
            const float* rV1 = rV0 + 8 * 192;
#pragma unroll
            for (int kc = 0; kc < 8; kc++) {
                const int k0 = kc * 8;
                uint32_t a0 = tf32u(__ldg(rV0 + k0 + tig));
                uint32_t a1 = tf32u(__ldg(rV1 + k0 + tig));
                uint32_t a2 = tf32u(__ldg(rV0 + k0 + tig + 4));
                uint32_t a3 = tf32u(__ldg(rV1 + k0 + tig + 4));
                const float* bp0 = sBev + (k0 + tig) * EW_ST + gid;
                const float* bp1 = bp0 + 4 * EW_ST;
#pragma unroll
                for (int t = 0; t < 8; t++) {
                    uint32_t b0 = __float_as_uint(bp0[8 * t]);
                    uint32_t b1 = __float_as_uint(bp1[8 * t]);
                    mma16n8k8(Ea[t], a0, a1, a2, a3, b0, b1);
                }
            }
            __syncwarp();   // previous scatter reads of sT done
#pragma unroll
            for (int t = 0; t < 8; t++) {
                float2 lo, hi;
                lo.x = Ea[t][0]; lo.y = Ea[t][1];
                hi.x = Ea[t][2]; hi.y = Ea[t][3];
                *(float2*)&sT[gid * ET_ST + 8 * t + 2 * tig] = lo;
                *(float2*)&sT[(gid + 8) * ET_ST + 8 * t + 2 * tig] = hi;
            }
            __syncwarp();
#pragma unroll
            for (int j = 0; j < 8; j++) {
                int cid = lane + 32 * j;
                int r = cid >> 4, c = (cid & 15) * 4;
                float4 v = *(const float4*)&sT[r * ET_ST + c];
                int i1 = __ldg(idx1 + e0 + r), i2 = __ldg(idx2 + e0 + r);
                red_add_v4(g_nv_acc + (size_t)i1 * 192 + a * 64 + c, v);
                red_add_v4(g_nv_acc + (size_t)i2 * 192 + a * 64 + c, v);
            }
        }
    }
}

// ---------------------------------------------------------------------------
// Kernel C1 (R8-exact)
// ---------------------------------------------------------------------------
#define C1_SMEM_BYTES ((192*100 + 8*1536) * 4)

__global__ void __launch_bounds__(256, 1) nodeC1_kernel(
    const float* __restrict__ Wc1, const float* __restrict__ bc1, int N)
{
    extern __shared__ float sm[];
    float* sWc1t = sm;
    float* sCatA = sWc1t + 192 * 100;

    load_wt(Wc1, sWc1t, 96, 192, 100);
    __syncthreads();

    const int lane = threadIdx.x & 31;
    const int warp = threadIdx.x >> 5;
    float* cat = sCatA + warp * 1536;

    const float bA0 = __ldg(bc1 + 2 * lane), bA1 = __ldg(bc1 + 2 * lane + 1);
    const float bB  = __ldg(bc1 + 64 + lane);

    const int gw = blockIdx.x * 8 + warp;
    const int GW = gridDim.x * 8;
    const int ngroups = N >> 3;

    for (int g = gw; g < ngroups; g += GW) {
        const int n0 = g * 8;
        __syncwarp();
#pragma unroll
        for (int r = 0; r < 8; r++) {
            const size_t n = (size_t)(n0 + r);
            float2 s = *(const float2*)&g_ns_acc[n * 64 + 2 * lane];
            *(float2*)&cat[r * 192 + 2 * lane] = s;
            float2 v0 = *(const float2*)&g_nv_acc[n * 192 + 0   + 2 * lane];
            float2 v1 = *(const float2*)&g_nv_acc[n * 192 + 64  + 2 * lane];
            float2 v2 = *(const float2*)&g_nv_acc[n * 192 + 128 + 2 * lane];
            float2 nn;
            nn.x = sqrtf(v0.x * v0.x + v1.x * v1.x + v2.x * v2.x);
            nn.y = sqrtf(v0.y * v0.y + v1.y * v1.y + v2.y * v2.y);
            *(float2*)&cat[r * 192 + 64 + 2 * lane] = nn;
            float2 tn = *(const float2*)&g_nt_norm[n * 64 + 2 * lane];
            *(float2*)&cat[r * 192 + 128 + 2 * lane] = tn;
        }
        __syncwarp();

        float accA[8][2]; zero8(accA);
        wgemm8<192, 2, false>(cat, 192, sWc1t, 100, 0, accA, lane);
        float accB[8][1]; zero8(accB);
        wgemm8<192, 1, false>(cat, 192, sWc1t, 100, 64, accB, lane);
#pragma unroll
        for (int r = 0; r < 8; r++) {
            const size_t n = (size_t)(n0 + r);
            float2 m; m.x = silu_(accA[r][0] + bA0); m.y = silu_(accA[r][1] + bA1);
            *(float2*)&g_mid[n * 96 + 2 * lane] = m;
            g_mid[n * 96 + 64 + lane] = silu_(accB[r][0] + bB);
        }
    }
}

// ---------------------------------------------------------------------------
// Kernel C2a (R13 version — measured 35us)
// ---------------------------------------------------------------------------
#define C2A_SMEM_BYTES ((96*132) * 4)

__global__ void __launch_bounds__(256, 2) nodeC2a_kernel(
    const float* __restrict__ h_ns,
    const float* __restrict__ Wc2, const float* __restrict__ bc2,
    float* __restrict__ out, int N)
{
    extern __shared__ float sm[];
    float* sW = sm;

    load_wt_part(Wc2, sW, 0, 128, 96, 132);
    __syncthreads();

    const int lane = threadIdx.x & 31;
    const int warp = threadIdx.x >> 5;

    const float b0 = __ldg(bc2 + 2 * lane),      b1 = __ldg(bc2 + 2 * lane + 1);
    const float b2 = __ldg(bc2 + 64 + 2 * lane), b3 = __ldg(bc2 + 64 + 2 * lane + 1);

    const int gw = blockIdx.x * 8 + warp;
    const int GW = gridDim.x * 8;
    const int ngroups = N >> 3;

    for (int g = gw; g < ngroups; g += GW) {
        const int n0 = g * 8;
        const float* mid = g_mid + (size_t)n0 * 96;

        float accA[8][2]; zero8(accA);
        wgemm8r<96, 2, true>(mid, 96, sW, 132, 0, accA, lane);
        float accB[8][2]; zero8(accB);
        wgemm8r<96, 2, true>(mid, 96, sW, 132, 64, accB, lane);

#pragma unroll
        for (int r = 0; r < 8; r++) {
            const size_t n = (size_t)(n0 + r);
            float2 hA = __ldg((const float2*)(h_ns + n * 128 + 2 * lane));
            float2 hB = __ldg((const float2*)(h_ns + n * 128 + 64 + 2 * lane));
            float2 vA, vB;
            vA.x = accA[r][0] + b0 + hA.x;
            vA.y = accA[r][1] + b1 + hA.y;
            vB.x = accB[r][0] + b2 + hB.x;
            vB.y = accB[r][1] + b3 + hB.y;
            *(float2*)&out[n * 128 + 2 * lane] = vA;
            *(float2*)&out[n * 128 + 64 + 2 * lane] = vB;
        }
    }
}

// ---------------------------------------------------------------------------
// Kernel C2b (R13 version)
// ---------------------------------------------------------------------------
#define C2B_SMEM_BYTES ((96*132 + 64*68 + 64*68) * 4)

__global__ void __launch_bounds__(256, 2) nodeC2b_kernel(
    const float* __restrict__ h_nv, const float* __restrict__ h_nt,
    const float* __restrict__ Wnv2, const float* __restrict__ Wnt2,
    const float* __restrict__ Wc2, const float* __restrict__ bc2,
    float* __restrict__ out, int N)
{
    extern __shared__ float sm[];
    float* sWg   = sm;
    float* sWnv2 = sWg + 96 * 132;
    float* sWnt2 = sWnv2 + 64 * 68;

    load_wt_part(Wc2, sWg, 128, 128, 96, 132);
    load_wt(Wnv2, sWnv2, 64, 64, 68);
    load_wt(Wnt2, sWnt2, 64, 64, 68);
    __syncthreads();

    const int lane = threadIdx.x & 31;
    const int warp = threadIdx.x >> 5;

    float* nv_out = out + (size_t)N * 128;
    float* nt_out = out + (size_t)N * 320;

    const float bn0 = __ldg(bc2 + 128 + 2 * lane), bn1 = __ldg(bc2 + 128 + 2 * lane + 1);
    const float bt0 = __ldg(bc2 + 192 + 2 * lane), bt1 = __ldg(bc2 + 192 + 2 * lane + 1);

    const int gw = blockIdx.x * 8 + warp;
    const int GW = gridDim.x * 8;
    const int ngroups = N >> 3;

    for (int g = gw; g < ngroups; g += GW) {
        const int n0 = g * 8;
        const float* mid = g_mid + (size_t)n0 * 96;

        float gA[8][2]; zero8(gA);
        wgemm8r<96, 2, true>(mid, 96, sWg, 132, 0, gA, lane);
#pragma unroll
        for (int r = 0; r < 8; r++) {
            gA[r][0] = sigm_(gA[r][0] + bn0);
            gA[r][1] = sigm_(gA[r][1] + bn1);
        }

#pragma unroll 1
        for (int a = 0; a < 3; a++) {
            float acc[8][2]; zero8(acc);
            wgemm8r<64, 2, true>(h_nv + (size_t)n0 * 192 + a * 64, 192, sWnv2, 68, 0, acc, lane);
#pragma unroll
            for (int r = 0; r < 8; r++) {
                const size_t n = (size_t)(n0 + r);
                float2 h = __ldg((const float2*)(h_nv + n * 192 + a * 64 + 2 * lane));
                float2 v;
                v.x = gA[r][0] * acc[r][0] + h.x;
                v.y = gA[r][1] * acc[r][1] + h.y;
                *(float2*)&nv_out[n * 192 + a * 64 + 2 * lane] = v;
            }
        }

        float gB[8][2]; zero8(gB);
        wgemm8r<96, 2, true>(mid, 96, sWg, 132, 64, gB, lane);
#pragma unroll
        for (int r = 0; r < 8; r++) {
            gB[r][0] = sigm_(gB[r][0] + bt0);
            gB[r][1] = sigm_(gB[r][1] + bt1);
        }

#pragma unroll 1
        for (int c = 0; c < 9; c++) {
            float acc[8][2]; zero8(acc);
            wgemm8r<64, 2, true>(h_nt + (size_t)n0 * 576 + c * 64, 576, sWnt2, 68, 0, acc, lane);
#pragma unroll
            for (int r = 0; r < 8; r++) {
                const size_t n = (size_t)(n0 + r);
                float2 h = __ldg((const float2*)(h_nt + n * 576 + c * 64 + 2 * lane));
                float2 v;
                v.x = gB[r][0] * acc[r][0] + h.x;
                v.y = gB[r][1] * acc[r][1] + h.y;
                *(float2*)&nt_out[n * 576 + c * 64 + 2 * lane] = v;
            }
        }
    }
}

// ---------------------------------------------------------------------------
extern "C" void kernel_launch(void* const* d_in, const int* in_sizes, int n_in,
                              void* d_out, int out_size)
{
    const float* h_ns = (const float*)d_in[0];
    const float* h_nv = (const float*)d_in[1];
    const float* h_nt = (const float*)d_in[2];
    const float* h_es = (const float*)d_in[3];
    const float* h_ev = (const float*)d_in[4];
    const int*   idx1 = (const int*)d_in[5];
    const int*   idx2 = (const int*)d_in[6];
    const float* Wns1 = (const float*)d_in[7];
    const float* bns1 = (const float*)d_in[8];
    const float* Wns2 = (const float*)d_in[9];
    const float* bns2 = (const float*)d_in[10];
    const float* Wes1 = (const float*)d_in[11];
    const float* bes1 = (const float*)d_in[12];
    const float* Wes2 = (const float*)d_in[13];
    const float* bes2 = (const float*)d_in[14];
    const float* Wnv1 = (const float*)d_in[15];
    const float* Wnv2 = (const float*)d_in[16];
    const float* Wev1 = (const float*)d_in[17];
    const float* Wnt1 = (const float*)d_in[18];
    const float* Wnt2 = (const float*)d_in[19];
    const float* Wc1  = (const float*)d_in[20];
    const float* bc1  = (const float*)d_in[21];
    const float* Wc2  = (const float*)d_in[22];
    const float* bc2  = (const float*)d_in[23];
    float* out = (float*)d_out;

    const int N = in_sizes[0] / 128;   // h_ns is (N, 128)
    const int E = in_sizes[5];         // atom_index1 is (E,)

    cudaFuncSetAttribute(nodeA_kernel,   cudaFuncAttributeMaxDynamicSharedMemorySize, A_SMEM_BYTES);
    cudaFuncSetAttribute(edge_kernel,    cudaFuncAttributeMaxDynamicSharedMemorySize, E_SMEM_BYTES);
    cudaFuncSetAttribute(nodeC1_kernel,  cudaFuncAttributeMaxDynamicSharedMemorySize, C1_SMEM_BYTES);
    cudaFuncSetAttribute(nodeC2a_kernel, cudaFuncAttributeMaxDynamicSharedMemorySize, C2A_SMEM_BYTES);
    cudaFuncSetAttribute(nodeC2b_kernel, cudaFuncAttributeMaxDynamicSharedMemorySize, C2B_SMEM_BYTES);

    nodeA_kernel<<<304, 256, A_SMEM_BYTES>>>(
        h_ns, h_nv, h_nt, Wns1, bns1, Wns2, bns2, Wnv1, Wnt1, N);

    edge_kernel<<<304, 256, E_SMEM_BYTES>>>(
        h_es, h_ev, idx1, idx2, Wes1, bes1, Wes2, bes2, Wev1, E);

    nodeC1_kernel<<<152, 256, C1_SMEM_BYTES>>>(Wc1, bc1, N);

    nodeC2a_kernel<<<304, 256, C2A_SMEM_BYTES>>>(h_ns, Wc2, bc2, out, N);

    nodeC2b_kernel<<<304, 256, C2B_SMEM_BYTES>>>(
        h_nv, h_nt, Wnv2, Wnt2, Wc2, bc2, out, N);
}

// round 15
// speedup vs baseline: 2.1911x; 1.1423x over previous
#include <cuda_runtime.h>
#include <cuda_bf16.h>
#include <cstdint>

// Scratch (device globals — no allocation allowed)
#define NMAX 20000
__device__ __align__(16) float g_ns_acc[NMAX * 64];    // h_ns_int (hs + scattered es)
__device__ __align__(16) float g_nv_acc[NMAX * 192];   // nv_int   (nv1 + scattered ev1)
__device__ __align__(16) float g_nt_norm[NMAX * 64];   // ||nt1||
__device__ __align__(16) float g_mid[NMAX * 96];       // silu(h_cat @ Wc1.T + bc1)

__device__ __forceinline__ float sigm_(float x) { return 1.0f / (1.0f + __expf(-x)); }
__device__ __forceinline__ float silu_(float x) { return x * sigm_(x); }

__device__ __forceinline__ void red_add_v4(float* p, float4 v) {
    asm volatile("red.global.add.v4.f32 [%0], {%1,%2,%3,%4};"
                 :: "l"(p), "f"(v.x), "f"(v.y), "f"(v.z), "f"(v.w) : "memory");
}

// tf32 round (rna), result as float bit-pattern / raw u32
__device__ __forceinline__ float tf32f(float x) {
    uint32_t u; asm("cvt.rna.tf32.f32 %0, %1;" : "=r"(u) : "f"(x));
    return __uint_as_float(u);
}
__device__ __forceinline__ uint32_t tf32u(float x) {
    uint32_t u; asm("cvt.rna.tf32.f32 %0, %1;" : "=r"(u) : "f"(x));
    return u;
}

// m16n8k8 tf32 MMA, fp32 accumulate
__device__ __forceinline__ void mma16n8k8(float (&c)[4],
                                          uint32_t a0, uint32_t a1, uint32_t a2, uint32_t a3,
                                          uint32_t b0, uint32_t b1) {
    asm volatile("mma.sync.aligned.m16n8k8.row.col.f32.tf32.tf32.f32 "
                 "{%0,%1,%2,%3}, {%4,%5,%6,%7}, {%8,%9}, {%0,%1,%2,%3};"
                 : "+f"(c[0]), "+f"(c[1]), "+f"(c[2]), "+f"(c[3])
                 : "r"(a0), "r"(a1), "r"(a2), "r"(a3), "r"(b0), "r"(b1));
}

// Load W (O x K row-major) into smem transposed: sWt[k*wstride + o]
__device__ __forceinline__ void load_wt(const float* __restrict__ W, float* sWt,
                                        int O, int K, int wstride) {
    for (int i = threadIdx.x; i < O * K; i += blockDim.x) {
        int o = i / K, k = i - o * K;
        sWt[k * wstride + o] = W[i];
    }
}

// Same, but for W rows [o_begin, o_begin+O)
__device__ __forceinline__ void load_wt_part(const float* __restrict__ W, float* sWt,
                                             int o_begin, int O, int K, int wstride) {
    for (int i = threadIdx.x; i < O * K; i += blockDim.x) {
        int o = i / K, k = i - o * K;
        sWt[k * wstride + o] = W[(size_t)(o_begin + o) * K + k];
    }
}

// Load W (O x K row-major) into smem transposed AND tf32-rounded
__device__ __forceinline__ void load_wt_tf32(const float* __restrict__ W, float* sWt,
                                             int O, int K, int wstride) {
    for (int i = threadIdx.x; i < O * K; i += blockDim.x) {
        int o = i / K, k = i - o * K;
        sWt[k * wstride + o] = tf32f(W[i]);
    }
}

template<int OPL>
__device__ __forceinline__ void zero8(float (&a)[8][OPL]) {
#pragma unroll
    for (int r = 0; r < 8; r++)
#pragma unroll
        for (int o = 0; o < OPL; o++) a[r][o] = 0.0f;
}

// Plain warp micro-GEMM (R5/R8 proven): 8 rows x (32*OPL outs), unroll 4.
template<int K, int OPL, bool XG>
__device__ __forceinline__ void wgemm8(const float* __restrict__ xbase, int xstride,
                                       const float* __restrict__ sWt, int wstride, int ocol,
                                       float (&acc)[8][OPL], int lane) {
    const int o0 = ocol + OPL * lane;
#pragma unroll 4
    for (int k = 0; k < K; k += 4) {
        float w[4][OPL];
#pragma unroll
        for (int kk = 0; kk < 4; kk++) {
            const float* wp = sWt + (k + kk) * wstride + o0;
            if (OPL == 4) {
                float4 t = *(const float4*)wp;
                w[kk][0] = t.x; w[kk][1] = t.y; w[kk][2] = t.z; w[kk][3] = t.w;
            } else if (OPL == 2) {
                float2 t = *(const float2*)wp;
                w[kk][0] = t.x; w[kk][1] = t.y;
            } else {
                w[kk][0] = *wp;
            }
        }
#pragma unroll
        for (int r = 0; r < 8; r++) {
            float4 x;
            if (XG) x = __ldg((const float4*)(xbase + (size_t)r * xstride + k));
            else    x = *(const float4*)(xbase + (size_t)r * xstride + k);
#pragma unroll
            for (int o = 0; o < OPL; o++)
                acc[r][o] += x.x * w[0][o] + x.y * w[1][o] + x.z * w[2][o] + x.w * w[3][o];
        }
    }
}

// Rolling-prefetch variant (R12-measured win at K<=96 in small kernels only)
template<int K, int OPL, bool XG>
__device__ __forceinline__ void wgemm8r(const float* __restrict__ xbase, int xstride,
                                        const float* __restrict__ sWt, int wstride, int ocol,
                                        float (&acc)[8][OPL], int lane) {
    const int o0 = ocol + OPL * lane;
    constexpr int NS = K / 4;
    const float* xr[8];
#pragma unroll
    for (int r = 0; r < 8; r++) xr[r] = xbase + (size_t)r * xstride;

    float4 xb[8];
#pragma unroll
    for (int r = 0; r < 8; r++)
        xb[r] = XG ? __ldg((const float4*)xr[r]) : *(const float4*)xr[r];

#pragma unroll
    for (int ks = 0; ks < NS; ks++) {
        const int k = ks * 4;
        float w[4][OPL];
#pragma unroll
        for (int kk = 0; kk < 4; kk++) {
            const float* wp = sWt + (k + kk) * wstride + o0;
            if (OPL == 4) {
                float4 t = *(const float4*)wp;
                w[kk][0] = t.x; w[kk][1] = t.y; w[kk][2] = t.z; w[kk][3] = t.w;
            } else if (OPL == 2) {
                float2 t = *(const float2*)wp;
                w[kk][0] = t.x; w[kk][1] = t.y;
            } else {
                w[kk][0] = *wp;
            }
        }
#pragma unroll
        for (int r = 0; r < 8; r++) {
            float4 xn;
            if (ks + 1 < NS)
                xn = XG ? __ldg((const float4*)(xr[r] + k + 4))
                        : *(const float4*)(xr[r] + k + 4);
            float4 x = xb[r];
#pragma unroll
            for (int o = 0; o < OPL; o++)
                acc[r][o] += x.x * w[0][o] + x.y * w[1][o] + x.z * w[2][o] + x.w * w[3][o];
            if (ks + 1 < NS) xb[r] = xn;
        }
    }
}

#define EW_ST 72
#define ET_ST 68

// ---------------------------------------------------------------------------
// Kernel A_s (NEW, tf32 mma): hs = MLP(h_ns) -> g_ns_acc. 16 nodes/warp.
// smem: (128+64)*72 + 8*16*68 = 22528 floats (90,112 B) -> 2 CTAs/SM
// ---------------------------------------------------------------------------
#define AS_SMEM_BYTES ((128*EW_ST + 64*EW_ST + 8*16*ET_ST) * 4)

__global__ void __launch_bounds__(256, 2) nodeAs_kernel(
    const float* __restrict__ h_ns,
    const float* __restrict__ Wns1, const float* __restrict__ bns1,
    const float* __restrict__ Wns2, const float* __restrict__ bns2, int N)
{
    extern __shared__ float sm[];
    float* sB1 = sm;                   // 128 x 72 (tf32 Wns1 [k][n])
    float* sB2 = sB1 + 128 * EW_ST;    // 64 x 72
    float* sTA = sB2 + 64 * EW_ST;     // 8 warps x 16 x 68

    load_wt_tf32(Wns1, sB1, 64, 128, EW_ST);
    load_wt_tf32(Wns2, sB2, 64, 64, EW_ST);
    __syncthreads();

    const int lane = threadIdx.x & 31;
    const int warp = threadIdx.x >> 5;
    const int gid = lane >> 2;
    const int tig = lane & 3;
    float* sT = sTA + warp * (16 * ET_ST);

    const int gw = blockIdx.x * 8 + warp;
    const int GW = gridDim.x * 8;
    const int ngroups = N >> 4;

    for (int g = gw; g < ngroups; g += GW) {
        const int n0 = g * 16;

        // GEMM1: T = silu(h_ns @ Wns1.T + b)  (K=128)
        float C[8][4];
#pragma unroll
        for (int t = 0; t < 8; t++) { C[t][0]=0.f; C[t][1]=0.f; C[t][2]=0.f; C[t][3]=0.f; }
        {
            const float* rA0 = h_ns + (size_t)(n0 + gid) * 128;
            const float* rA1 = rA0 + 8 * 128;
#pragma unroll
            for (int kc = 0; kc < 16; kc++) {
                const int k0 = kc * 8;
                uint32_t a0 = tf32u(__ldg(rA0 + k0 + tig));
                uint32_t a1 = tf32u(__ldg(rA1 + k0 + tig));
                uint32_t a2 = tf32u(__ldg(rA0 + k0 + tig + 4));
                uint32_t a3 = tf32u(__ldg(rA1 + k0 + tig + 4));
                const float* bp0 = sB1 + (k0 + tig) * EW_ST + gid;
                const float* bp1 = bp0 + 4 * EW_ST;
#pragma unroll
                for (int t = 0; t < 8; t++) {
                    uint32_t b0 = __float_as_uint(bp0[8 * t]);
                    uint32_t b1 = __float_as_uint(bp1[8 * t]);
                    mma16n8k8(C[t], a0, a1, a2, a3, b0, b1);
                }
            }
        }
        __syncwarp();
#pragma unroll
        for (int t = 0; t < 8; t++) {
            float2 bb = __ldg((const float2*)(bns1 + 8 * t + 2 * tig));
            float2 lo, hi;
            lo.x = silu_(C[t][0] + bb.x); lo.y = silu_(C[t][1] + bb.y);
            hi.x = silu_(C[t][2] + bb.x); hi.y = silu_(C[t][3] + bb.y);
            *(float2*)&sT[gid * ET_ST + 8 * t + 2 * tig] = lo;
            *(float2*)&sT[(gid + 8) * ET_ST + 8 * t + 2 * tig] = hi;
        }
        __syncwarp();

        // GEMM2: hs = T @ Wns2.T + b  (K=64) -> g_ns_acc direct
        float D[8][4];
#pragma unroll
        for (int t = 0; t < 8; t++) { D[t][0]=0.f; D[t][1]=0.f; D[t][2]=0.f; D[t][3]=0.f; }
#pragma unroll
        for (int kc = 0; kc < 8; kc++) {
            const int k0 = kc * 8;
            uint32_t a0 = tf32u(sT[gid * ET_ST + k0 + tig]);
            uint32_t a1 = tf32u(sT[(gid + 8) * ET_ST + k0 + tig]);
            uint32_t a2 = tf32u(sT[gid * ET_ST + k0 + tig + 4]);
            uint32_t a3 = tf32u(sT[(gid + 8) * ET_ST + k0 + tig + 4]);
            const float* bp0 = sB2 + (k0 + tig) * EW_ST + gid;
            const float* bp1 = bp0 + 4 * EW_ST;
#pragma unroll
            for (int t = 0; t < 8; t++) {
                uint32_t b0 = __float_as_uint(bp0[8 * t]);
                uint32_t b1 = __float_as_uint(bp1[8 * t]);
                mma16n8k8(D[t], a0, a1, a2, a3, b0, b1);
            }
        }
#pragma unroll
        for (int t = 0; t < 8; t++) {
            float2 bb = __ldg((const float2*)(bns2 + 8 * t + 2 * tig));
            float2 lo, hi;
            lo.x = D[t][0] + bb.x; lo.y = D[t][1] + bb.y;
            hi.x = D[t][2] + bb.x; hi.y = D[t][3] + bb.y;
            *(float2*)&g_ns_acc[(size_t)(n0 + gid) * 64 + 8 * t + 2 * tig] = lo;
            *(float2*)&g_ns_acc[(size_t)(n0 + gid + 8) * 64 + 8 * t + 2 * tig] = hi;
        }
    }
}

// ---------------------------------------------------------------------------
// Kernel A_vt (NEW, tf32 mma): nv1 -> g_nv_acc (x3), ||nt1|| -> g_nt_norm (9 sq-acc)
// smem: 2*64*72 = 9216 floats (36,864 B)
// ---------------------------------------------------------------------------
#define AVT_SMEM_BYTES ((64*EW_ST + 64*EW_ST) * 4)

__global__ void __launch_bounds__(256, 2) nodeAvt_kernel(
    const float* __restrict__ h_nv, const float* __restrict__ h_nt,
    const float* __restrict__ Wnv1, const float* __restrict__ Wnt1, int N)
{
    extern __shared__ float sm[];
    float* sBnv = sm;                  // 64 x 72
    float* sBnt = sBnv + 64 * EW_ST;   // 64 x 72

    load_wt_tf32(Wnv1, sBnv, 64, 64, EW_ST);
    load_wt_tf32(Wnt1, sBnt, 64, 64, EW_ST);
    __syncthreads();

    const int lane = threadIdx.x & 31;
    const int warp = threadIdx.x >> 5;
    const int gid = lane >> 2;
    const int tig = lane & 3;

    const int gw = blockIdx.x * 8 + warp;
    const int GW = gridDim.x * 8;
    const int ngroups = N >> 4;

    for (int g = gw; g < ngroups; g += GW) {
        const int n0 = g * 16;

        // nv1 (3 components), direct stores
#pragma unroll 1
        for (int a = 0; a < 3; a++) {
            float C[8][4];
#pragma unroll
            for (int t = 0; t < 8; t++) { C[t][0]=0.f; C[t][1]=0.f; C[t][2]=0.f; C[t][3]=0.f; }
            const float* rA0 = h_nv + (size_t)(n0 + gid) * 192 + a * 64;
            const float* rA1 = rA0 + 8 * 192;
#pragma unroll
            for (int kc = 0; kc < 8; kc++) {
                const int k0 = kc * 8;
                uint32_t a0 = tf32u(__ldg(rA0 + k0 + tig));
                uint32_t a1 = tf32u(__ldg(rA1 + k0 + tig));
                uint32_t a2 = tf32u(__ldg(rA0 + k0 + tig + 4));
                uint32_t a3 = tf32u(__ldg(rA1 + k0 + tig + 4));
                const float* bp0 = sBnv + (k0 + tig) * EW_ST + gid;
                const float* bp1 = bp0 + 4 * EW_ST;
#pragma unroll
                for (int t = 0; t < 8; t++) {
                    uint32_t b0 = __float_as_uint(bp0[8 * t]);
                    uint32_t b1 = __float_as_uint(bp1[8 * t]);
                    mma16n8k8(C[t], a0, a1, a2, a3, b0, b1);
                }
            }
#pragma unroll
            for (int t = 0; t < 8; t++) {
                float2 lo, hi;
                lo.x = C[t][0]; lo.y = C[t][1];
                hi.x = C[t][2]; hi.y = C[t][3];
                *(float2*)&g_nv_acc[(size_t)(n0 + gid) * 192 + a * 64 + 8 * t + 2 * tig] = lo;
                *(float2*)&g_nv_acc[(size_t)(n0 + gid + 8) * 192 + a * 64 + 8 * t + 2 * tig] = hi;
            }
        }

        // nt1: 9 components, square-accumulate in fragment registers
        float sq[8][4];
#pragma unroll
        for (int t = 0; t < 8; t++) { sq[t][0]=0.f; sq[t][1]=0.f; sq[t][2]=0.f; sq[t][3]=0.f; }
#pragma unroll 1
        for (int c = 0; c < 9; c++) {
            float C[8][4];
#pragma unroll
            for (int t = 0; t < 8; t++) { C[t][0]=0.f; C[t][1]=0.f; C[t][2]=0.f; C[t][3]=0.f; }
            const float* rA0 = h_nt + (size_t)(n0 + gid) * 576 + c * 64;
            const float* rA1 = rA0 + 8 * 576;
#pragma unroll
            for (int kc = 0; kc < 8; kc++) {
                const int k0 = kc * 8;
                uint32_t a0 = tf32u(__ldg(rA0 + k0 + tig));
                uint32_t a1 = tf32u(__ldg(rA1 + k0 + tig));
                uint32_t a2 = tf32u(__ldg(rA0 + k0 + tig + 4));
                uint32_t a3 = tf32u(__ldg(rA1 + k0 + tig + 4));
                const float* bp0 = sBnt + (k0 + tig) * EW_ST + gid;
                const float* bp1 = bp0 + 4 * EW_ST;
#pragma unroll
                for (int t = 0; t < 8; t++) {
                    uint32_t b0 = __float_as_uint(bp0[8 * t]);
                    uint32_t b1 = __float_as_uint(bp1[8 * t]);
                    mma16n8k8(C[t], a0, a1, a2, a3, b0, b1);
                }
            }
#pragma unroll
            for (int t = 0; t < 8; t++) {
                sq[t][0] += C[t][0] * C[t][0];
                sq[t][1] += C[t][1] * C[t][1];
                sq[t][2] += C[t][2] * C[t][2];
                sq[t][3] += C[t][3] * C[t][3];
            }
        }
#pragma unroll
        for (int t = 0; t < 8; t++) {
            float2 lo, hi;
            lo.x = sqrtf(sq[t][0]); lo.y = sqrtf(sq[t][1]);
            hi.x = sqrtf(sq[t][2]); hi.y = sqrtf(sq[t][3]);
            *(float2*)&g_nt_norm[(size_t)(n0 + gid) * 64 + 8 * t + 2 * tig] = lo;
            *(float2*)&g_nt_norm[(size_t)(n0 + gid + 8) * 64 + 8 * t + 2 * tig] = hi;
        }
    }
}

// ---------------------------------------------------------------------------
// Edge kernel (R14-exact, tf32 mma)
// ---------------------------------------------------------------------------
#define E_SMEM_BYTES ((128*EW_ST + 64*EW_ST + 64*EW_ST + 8*16*ET_ST) * 4)

__global__ void __launch_bounds__(256, 2) edge_kernel(
    const float* __restrict__ h_es, const float* __restrict__ h_ev,
    const int* __restrict__ idx1, const int* __restrict__ idx2,
    const float* __restrict__ Wes1, const float* __restrict__ bes1,
    const float* __restrict__ Wes2, const float* __restrict__ bes2,
    const float* __restrict__ Wev1, int E)
{
    extern __shared__ float sm[];
    float* sB1  = sm;
    float* sB2  = sB1 + 128 * EW_ST;
    float* sBev = sB2 + 64 * EW_ST;
    float* sTA  = sBev + 64 * EW_ST;

    load_wt_tf32(Wes1, sB1, 64, 128, EW_ST);
    load_wt_tf32(Wes2, sB2, 64, 64, EW_ST);
    load_wt_tf32(Wev1, sBev, 64, 64, EW_ST);
    __syncthreads();

    const int lane = threadIdx.x & 31;
    const int warp = threadIdx.x >> 5;
    const int gid = lane >> 2;
    const int tig = lane & 3;
    float* sT = sTA + warp * (16 * ET_ST);

    const int gw = blockIdx.x * 8 + warp;
    const int GW = gridDim.x * 8;
    const int ngroups = E >> 4;

    for (int g = gw; g < ngroups; g += GW) {
        const int e0 = g * 16;

        float C[8][4];
#pragma unroll
        for (int t = 0; t < 8; t++) { C[t][0]=0.f; C[t][1]=0.f; C[t][2]=0.f; C[t][3]=0.f; }
        {
            const float* rA0 = h_es + (size_t)(e0 + gid) * 128;
            const float* rA1 = rA0 + 8 * 128;
#pragma unroll
            for (int kc = 0; kc < 16; kc++) {
                const int k0 = kc * 8;
                uint32_t a0 = tf32u(__ldg(rA0 + k0 + tig));
                uint32_t a1 = tf32u(__ldg(rA1 + k0 + tig));
                uint32_t a2 = tf32u(__ldg(rA0 + k0 + tig + 4));
                uint32_t a3 = tf32u(__ldg(rA1 + k0 + tig + 4));
                const float* bp0 = sB1 + (k0 + tig) * EW_ST + gid;
                const float* bp1 = bp0 + 4 * EW_ST;
#pragma unroll
                for (int t = 0; t < 8; t++) {
                    uint32_t b0 = __float_as_uint(bp0[8 * t]);
                    uint32_t b1 = __float_as_uint(bp1[8 * t]);
                    mma16n8k8(C[t], a0, a1, a2, a3, b0, b1);
                }
            }
        }
        __syncwarp();
#pragma unroll
        for (int t = 0; t < 8; t++) {
            float2 bb = __ldg((const float2*)(bes1 + 8 * t + 2 * tig));
            float2 lo, hi;
            lo.x = silu_(C[t][0] + bb.x); lo.y = silu_(C[t][1] + bb.y);
            hi.x = silu_(C[t][2] + bb.x); hi.y = silu_(C[t][3] + bb.y);
            *(float2*)&sT[gid * ET_ST + 8 * t + 2 * tig] = lo;
            *(float2*)&sT[(gid + 8) * ET_ST + 8 * t + 2 * tig] = hi;
        }
        __syncwarp();

        float D[8][4];
#pragma unroll
        for (int t = 0; t < 8; t++) { D[t][0]=0.f; D[t][1]=0.f; D[t][2]=0.f; D[t][3]=0.f; }
#pragma unroll
        for (int kc = 0; kc < 8; kc++) {
            const int k0 = kc * 8;
            uint32_t a0 = tf32u(sT[gid * ET_ST + k0 + tig]);
            uint32_t a1 = tf32u(sT[(gid + 8) * ET_ST + k0 + tig]);
            uint32_t a2 = tf32u(sT[gid * ET_ST + k0 + tig + 4]);
            uint32_t a3 = tf32u(sT[(gid + 8) * ET_ST + k0 + tig + 4]);
            const float* bp0 = sB2 + (k0 + tig) * EW_ST + gid;
            const float* bp1 = bp0 + 4 * EW_ST;
#pragma unroll
            for (int t = 0; t < 8; t++) {
                uint32_t b0 = __float_as_uint(bp0[8 * t]);
                uint32_t b1 = __float_as_uint(bp1[8 * t]);
                mma16n8k8(D[t], a0, a1, a2, a3, b0, b1);
            }
        }
        __syncwarp();
#pragma unroll
        for (int t = 0; t < 8; t++) {
            float2 bb = __ldg((const float2*)(bes2 + 8 * t + 2 * tig));
            float2 lo, hi;
            lo.x = D[t][0] + bb.x; lo.y = D[t][1] + bb.y;
            hi.x = D[t][2] + bb.x; hi.y = D[t][3] + bb.y;
            *(float2*)&sT[gid * ET_ST + 8 * t + 2 * tig] = lo;
            *(float2*)&sT[(gid + 8) * ET_ST + 8 * t + 2 * tig] = hi;
        }
        __syncwarp();

#pragma unroll
        for (int j = 0; j < 8; j++) {
            int cid = lane + 32 * j;
            int r = cid >> 4, c = (cid & 15) * 4;
            float4 v = *(const float4*)&sT[r * ET_ST + c];
            int i1 = __ldg(idx1 + e0 + r), i2 = __ldg(idx2 + e0 + r);
            red_add_v4(g_ns_acc + (size_t)i1 * 64 + c, v);
            red_add_v4(g_ns_acc + (size_t)i2 * 64 + c, v);
        }

#pragma unroll 1
        for (int a = 0; a < 3; a++) {
            float Ea[8][4];
#pragma unroll
            for (int t = 0; t < 8; t++) { Ea[t][0]=0.f; Ea[t][1]=0.f; Ea[t][2]=0.f; Ea[t][3]=0.f; }
            const float* rV0 = h_ev + (size_t)(e0 + gid) * 192 + a * 64;
            const float* rV1 = rV0 + 8 * 192;
#pragma unroll
            for (int kc = 0; kc < 8; kc++) {
                const int k0 = kc * 8;
                uint32_t a0 = tf32u(__ldg(rV0 + k0 + tig));
                uint32_t a1 = tf32u(__ldg(rV1 + k0 + tig));
                uint32_t a2 = tf32u(__ldg(rV0 + k0 + tig + 4));
                uint32_t a3 = tf32u(__ldg(rV1 + k0 + tig + 4));
                const float* bp0 = sBev + (k0 + tig) * EW_ST + gid;
                const float* bp1 = bp0 + 4 * EW_ST;
#pragma unroll
                for (int t = 0; t < 8; t++) {
                    uint32_t b0 = __float_as_uint(bp0[8 * t]);
                    uint32_t b1 = __float_as_uint(bp1[8 * t]);
                    mma16n8k8(Ea[t], a0, a1, a2, a3, b0, b1);
                }
            }
            __syncwarp();
#pragma unroll
            for (int t = 0; t < 8; t++) {
                float2 lo, hi;
                lo.x = Ea[t][0]; lo.y = Ea[t][1];
                hi.x = Ea[t][2]; hi.y = Ea[t][3];
                *(float2*)&sT[gid * ET_ST + 8 * t + 2 * tig] = lo;
                *(float2*)&sT[(gid + 8) * ET_ST + 8 * t + 2 * tig] = hi;
            }
            __syncwarp();
#pragma unroll
            for (int j = 0; j < 8; j++) {
                int cid = lane + 32 * j;
                int r = cid >> 4, c = (cid & 15) * 4;
                float4 v = *(const float4*)&sT[r * ET_ST + c];
                int i1 = __ldg(idx1 + e0 + r), i2 = __ldg(idx2 + e0 + r);
                red_add_v4(g_nv_acc + (size_t)i1 * 192 + a * 64 + c, v);
                red_add_v4(g_nv_acc + (size_t)i2 * 192 + a * 64 + c, v);
            }
        }
    }
}

// ---------------------------------------------------------------------------
// Kernel C1 (R8-exact)
// ---------------------------------------------------------------------------
#define C1_SMEM_BYTES ((192*100 + 8*1536) * 4)

__global__ void __launch_bounds__(256, 1) nodeC1_kernel(
    const float* __restrict__ Wc1, const float* __restrict__ bc1, int N)
{
    extern __shared__ float sm[];
    float* sWc1t = sm;
    float* sCatA = sWc1t + 192 * 100;

    load_wt(Wc1, sWc1t, 96, 192, 100);
    __syncthreads();

    const int lane = threadIdx.x & 31;
    const int warp = threadIdx.x >> 5;
    float* cat = sCatA + warp * 1536;

    const float bA0 = __ldg(bc1 + 2 * lane), bA1 = __ldg(bc1 + 2 * lane + 1);
    const float bB  = __ldg(bc1 + 64 + lane);

    const int gw = blockIdx.x * 8 + warp;
    const int GW = gridDim.x * 8;
    const int ngroups = N >> 3;

    for (int g = gw; g < ngroups; g += GW) {
        const int n0 = g * 8;
        __syncwarp();
#pragma unroll
        for (int r = 0; r < 8; r++) {
            const size_t n = (size_t)(n0 + r);
            float2 s = *(const float2*)&g_ns_acc[n * 64 + 2 * lane];
            *(float2*)&cat[r * 192 + 2 * lane] = s;
            float2 v0 = *(const float2*)&g_nv_acc[n * 192 + 0   + 2 * lane];
            float2 v1 = *(const float2*)&g_nv_acc[n * 192 + 64  + 2 * lane];
            float2 v2 = *(const float2*)&g_nv_acc[n * 192 + 128 + 2 * lane];
            float2 nn;
            nn.x = sqrtf(v0.x * v0.x + v1.x * v1.x + v2.x * v2.x);
            nn.y = sqrtf(v0.y * v0.y + v1.y * v1.y + v2.y * v2.y);
            *(float2*)&cat[r * 192 + 64 + 2 * lane] = nn;
            float2 tn = *(const float2*)&g_nt_norm[n * 64 + 2 * lane];
            *(float2*)&cat[r * 192 + 128 + 2 * lane] = tn;
        }
        __syncwarp();

        float accA[8][2]; zero8(accA);
        wgemm8<192, 2, false>(cat, 192, sWc1t, 100, 0, accA, lane);
        float accB[8][1]; zero8(accB);
        wgemm8<192, 1, false>(cat, 192, sWc1t, 100, 64, accB, lane);
#pragma unroll
        for (int r = 0; r < 8; r++) {
            const size_t n = (size_t)(n0 + r);
            float2 m; m.x = silu_(accA[r][0] + bA0); m.y = silu_(accA[r][1] + bA1);
            *(float2*)&g_mid[n * 96 + 2 * lane] = m;
            g_mid[n * 96 + 64 + lane] = silu_(accB[r][0] + bB);
        }
    }
}

// ---------------------------------------------------------------------------
// Kernel C2a (R13 version)
// ---------------------------------------------------------------------------
#define C2A_SMEM_BYTES ((96*132) * 4)

__global__ void __launch_bounds__(256, 2) nodeC2a_kernel(
    const float* __restrict__ h_ns,
    const float* __restrict__ Wc2, const float* __restrict__ bc2,
    float* __restrict__ out, int N)
{
    extern __shared__ float sm[];
    float* sW = sm;

    load_wt_part(Wc2, sW, 0, 128, 96, 132);
    __syncthreads();

    const int lane = threadIdx.x & 31;
    const int warp = threadIdx.x >> 5;

    const float b0 = __ldg(bc2 + 2 * lane),      b1 = __ldg(bc2 + 2 * lane + 1);
    const float b2 = __ldg(bc2 + 64 + 2 * lane), b3 = __ldg(bc2 + 64 + 2 * lane + 1);

    const int gw = blockIdx.x * 8 + warp;
    const int GW = gridDim.x * 8;
    const int ngroups = N >> 3;

    for (int g = gw; g < ngroups; g += GW) {
        const int n0 = g * 8;
        const float* mid = g_mid + (size_t)n0 * 96;

        float accA[8][2]; zero8(accA);
        wgemm8r<96, 2, true>(mid, 96, sW, 132, 0, accA, lane);
        float accB[8][2]; zero8(accB);
        wgemm8r<96, 2, true>(mid, 96, sW, 132, 64, accB, lane);

#pragma unroll
        for (int r = 0; r < 8; r++) {
            const size_t n = (size_t)(n0 + r);
            float2 hA = __ldg((const float2*)(h_ns + n * 128 + 2 * lane));
            float2 hB = __ldg((const float2*)(h_ns + n * 128 + 64 + 2 * lane));
            float2 vA, vB;
            vA.x = accA[r][0] + b0 + hA.x;
            vA.y = accA[r][1] + b1 + hA.y;
            vB.x = accB[r][0] + b2 + hB.x;
            vB.y = accB[r][1] + b3 + hB.y;
            *(float2*)&out[n * 128 + 2 * lane] = vA;
            *(float2*)&out[n * 128 + 64 + 2 * lane] = vB;
        }
    }
}

// ---------------------------------------------------------------------------
// Kernel C2b (R13 version)
// ---------------------------------------------------------------------------
#define C2B_SMEM_BYTES ((96*132 + 64*68 + 64*68) * 4)

__global__ void __launch_bounds__(256, 2) nodeC2b_kernel(
    const float* __restrict__ h_nv, const float* __restrict__ h_nt,
    const float* __restrict__ Wnv2, const float* __restrict__ Wnt2,
    const float* __restrict__ Wc2, const float* __restrict__ bc2,
    float* __restrict__ out, int N)
{
    extern __shared__ float sm[];
    float* sWg   = sm;
    float* sWnv2 = sWg + 96 * 132;
    float* sWnt2 = sWnv2 + 64 * 68;

    load_wt_part(Wc2, sWg, 128, 128, 96, 132);
    load_wt(Wnv2, sWnv2, 64, 64, 68);
    load_wt(Wnt2, sWnt2, 64, 64, 68);
    __syncthreads();

    const int lane = threadIdx.x & 31;
    const int warp = threadIdx.x >> 5;

    float* nv_out = out + (size_t)N * 128;
    float* nt_out = out + (size_t)N * 320;

    const float bn0 = __ldg(bc2 + 128 + 2 * lane), bn1 = __ldg(bc2 + 128 + 2 * lane + 1);
    const float bt0 = __ldg(bc2 + 192 + 2 * lane), bt1 = __ldg(bc2 + 192 + 2 * lane + 1);

    const int gw = blockIdx.x * 8 + warp;
    const int GW = gridDim.x * 8;
    const int ngroups = N >> 3;

    for (int g = gw; g < ngroups; g += GW) {
        const int n0 = g * 8;
        const float* mid = g_mid + (size_t)n0 * 96;

        float gA[8][2]; zero8(gA);
        wgemm8r<96, 2, true>(mid, 96, sWg, 132, 0, gA, lane);
#pragma unroll
        for (int r = 0; r < 8; r++) {
            gA[r][0] = sigm_(gA[r][0] + bn0);
            gA[r][1] = sigm_(gA[r][1] + bn1);
        }

#pragma unroll 1
        for (int a = 0; a < 3; a++) {
            float acc[8][2]; zero8(acc);
            wgemm8r<64, 2, true>(h_nv + (size_t)n0 * 192 + a * 64, 192, sWnv2, 68, 0, acc, lane);
#pragma unroll
            for (int r = 0; r < 8; r++) {
                const size_t n = (size_t)(n0 + r);
                float2 h = __ldg((const float2*)(h_nv + n * 192 + a * 64 + 2 * lane));
                float2 v;
                v.x = gA[r][0] * acc[r][0] + h.x;
                v.y = gA[r][1] * acc[r][1] + h.y;
                *(float2*)&nv_out[n * 192 + a * 64 + 2 * lane] = v;
            }
        }

        float gB[8][2]; zero8(gB);
        wgemm8r<96, 2, true>(mid, 96, sWg, 132, 64, gB, lane);
#pragma unroll
        for (int r = 0; r < 8; r++) {
            gB[r][0] = sigm_(gB[r][0] + bt0);
            gB[r][1] = sigm_(gB[r][1] + bt1);
        }

#pragma unroll 1
        for (int c = 0; c < 9; c++) {
            float acc[8][2]; zero8(acc);
            wgemm8r<64, 2, true>(h_nt + (size_t)n0 * 576 + c * 64, 576, sWnt2, 68, 0, acc, lane);
#pragma unroll
            for (int r = 0; r < 8; r++) {
                const size_t n = (size_t)(n0 + r);
                float2 h = __ldg((const float2*)(h_nt + n * 576 + c * 64 + 2 * lane));
                float2 v;
                v.x = gB[r][0] * acc[r][0] + h.x;
                v.y = gB[r][1] * acc[r][1] + h.y;
                *(float2*)&nt_out[n * 576 + c * 64 + 2 * lane] = v;
            }
        }
    }
}

// ---------------------------------------------------------------------------
extern "C" void kernel_launch(void* const* d_in, const int* in_sizes, int n_in,
                              void* d_out, int out_size)
{
    const float* h_ns = (const float*)d_in[0];
    const float* h_nv = (const float*)d_in[1];
    const float* h_nt = (const float*)d_in[2];
    const float* h_es = (const float*)d_in[3];
    const float* h_ev = (const float*)d_in[4];
    const int*   idx1 = (const int*)d_in[5];
    const int*   idx2 = (const int*)d_in[6];
    const float* Wns1 = (const float*)d_in[7];
    const float* bns1 = (const float*)d_in[8];
    const float* Wns2 = (const float*)d_in[9];
    const float* bns2 = (const float*)d_in[10];
    const float* Wes1 = (const float*)d_in[11];
    const float* bes1 = (const float*)d_in[12];
    const float* Wes2 = (const float*)d_in[13];
    const float* bes2 = (const float*)d_in[14];
    const float* Wnv1 = (const float*)d_in[15];
    const float* Wnv2 = (const float*)d_in[16];
    const float* Wev1 = (const float*)d_in[17];
    const float* Wnt1 = (const float*)d_in[18];
    const float* Wnt2 = (const float*)d_in[19];
    const float* Wc1  = (const float*)d_in[20];
    const float* bc1  = (const float*)d_in[21];
    const float* Wc2  = (const float*)d_in[22];
    const float* bc2  = (const float*)d_in[23];
    float* out = (float*)d_out;

    const int N = in_sizes[0] / 128;   // h_ns is (N, 128)
    const int E = in_sizes[5];         // atom_index1 is (E,)

    cudaFuncSetAttribute(nodeAs_kernel,  cudaFuncAttributeMaxDynamicSharedMemorySize, AS_SMEM_BYTES);
    cudaFuncSetAttribute(nodeAvt_kernel, cudaFuncAttributeMaxDynamicSharedMemorySize, AVT_SMEM_BYTES);
    cudaFuncSetAttribute(edge_kernel,    cudaFuncAttributeMaxDynamicSharedMemorySize, E_SMEM_BYTES);
    cudaFuncSetAttribute(nodeC1_kernel,  cudaFuncAttributeMaxDynamicSharedMemorySize, C1_SMEM_BYTES);
    cudaFuncSetAttribute(nodeC2a_kernel, cudaFuncAttributeMaxDynamicSharedMemorySize, C2A_SMEM_BYTES);
    cudaFuncSetAttribute(nodeC2b_kernel, cudaFuncAttributeMaxDynamicSharedMemorySize, C2B_SMEM_BYTES);

    nodeAs_kernel<<<304, 256, AS_SMEM_BYTES>>>(h_ns, Wns1, bns1, Wns2, bns2, N);

    nodeAvt_kernel<<<304, 256, AVT_SMEM_BYTES>>>(h_nv, h_nt, Wnv1, Wnt1, N);

    edge_kernel<<<304, 256, E_SMEM_BYTES>>>(
        h_es, h_ev, idx1, idx2, Wes1, bes1, Wes2, bes2, Wev1, E);

    nodeC1_kernel<<<152, 256, C1_SMEM_BYTES>>>(Wc1, bc1, N);

    nodeC2a_kernel<<<304, 256, C2A_SMEM_BYTES>>>(h_ns, Wc2, bc2, out, N);

    nodeC2b_kernel<<<304, 256, C2B_SMEM_BYTES>>>(
        h_nv, h_nt, Wnv2, Wnt2, Wc2, bc2, out, N);
}

// round 16
// speedup vs baseline: 2.7205x; 1.2416x over previous
#include <cuda_runtime.h>
#include <cuda_bf16.h>
#include <cstdint>

// Scratch (device globals — no allocation allowed)
#define NMAX 20000
__device__ __align__(16) float g_ns_acc[NMAX * 64];    // h_ns_int (hs + scattered es)
__device__ __align__(16) float g_nv_acc[NMAX * 192];   // nv_int   (nv1 + scattered ev1)
__device__ __align__(16) float g_nt_norm[NMAX * 64];   // ||nt1||
__device__ __align__(16) float g_mid[NMAX * 96];       // silu(h_cat @ Wc1.T + bc1)

__device__ __forceinline__ float sigm_(float x) { return 1.0f / (1.0f + __expf(-x)); }
__device__ __forceinline__ float silu_(float x) { return x * sigm_(x); }

__device__ __forceinline__ void red_add_v4(float* p, float4 v) {
    asm volatile("red.global.add.v4.f32 [%0], {%1,%2,%3,%4};"
                 :: "l"(p), "f"(v.x), "f"(v.y), "f"(v.z), "f"(v.w) : "memory");
}

// tf32 round (rna), result as float bit-pattern / raw u32
__device__ __forceinline__ float tf32f(float x) {
    uint32_t u; asm("cvt.rna.tf32.f32 %0, %1;" : "=r"(u) : "f"(x));
    return __uint_as_float(u);
}
__device__ __forceinline__ uint32_t tf32u(float x) {
    uint32_t u; asm("cvt.rna.tf32.f32 %0, %1;" : "=r"(u) : "f"(x));
    return u;
}

// m16n8k8 tf32 MMA, fp32 accumulate
__device__ __forceinline__ void mma16n8k8(float (&c)[4],
                                          uint32_t a0, uint32_t a1, uint32_t a2, uint32_t a3,
                                          uint32_t b0, uint32_t b1) {
    asm volatile("mma.sync.aligned.m16n8k8.row.col.f32.tf32.tf32.f32 "
                 "{%0,%1,%2,%3}, {%4,%5,%6,%7}, {%8,%9}, {%0,%1,%2,%3};"
                 : "+f"(c[0]), "+f"(c[1]), "+f"(c[2]), "+f"(c[3])
                 : "r"(a0), "r"(a1), "r"(a2), "r"(a3), "r"(b0), "r"(b1));
}

// Load W (O x K row-major) into smem transposed AND tf32-rounded: sWt[k*ws + o]
__device__ __forceinline__ void load_wt_tf32(const float* __restrict__ W, float* sWt,
                                             int O, int K, int wstride) {
    for (int i = threadIdx.x; i < O * K; i += blockDim.x) {
        int o = i / K, k = i - o * K;
        sWt[k * wstride + o] = tf32f(W[i]);
    }
}

// Same, rows [o_begin, o_begin+O)
__device__ __forceinline__ void load_wt_part_tf32(const float* __restrict__ W, float* sWt,
                                                  int o_begin, int O, int K, int wstride) {
    for (int i = threadIdx.x; i < O * K; i += blockDim.x) {
        int o = i / K, k = i - o * K;
        sWt[k * wstride + o] = tf32f(W[(size_t)(o_begin + o) * K + k]);
    }
}

#define EW_ST 72
#define ET_ST 68

// ---------------------------------------------------------------------------
// Kernel A_s (tf32 mma): hs = MLP(h_ns) -> g_ns_acc. 16 nodes/warp.
// ---------------------------------------------------------------------------
#define AS_SMEM_BYTES ((128*EW_ST + 64*EW_ST + 8*16*ET_ST) * 4)

__global__ void __launch_bounds__(256, 2) nodeAs_kernel(
    const float* __restrict__ h_ns,
    const float* __restrict__ Wns1, const float* __restrict__ bns1,
    const float* __restrict__ Wns2, const float* __restrict__ bns2, int N)
{
    extern __shared__ float sm[];
    float* sB1 = sm;
    float* sB2 = sB1 + 128 * EW_ST;
    float* sTA = sB2 + 64 * EW_ST;

    load_wt_tf32(Wns1, sB1, 64, 128, EW_ST);
    load_wt_tf32(Wns2, sB2, 64, 64, EW_ST);
    __syncthreads();

    const int lane = threadIdx.x & 31;
    const int warp = threadIdx.x >> 5;
    const int gid = lane >> 2;
    const int tig = lane & 3;
    float* sT = sTA + warp * (16 * ET_ST);

    const int gw = blockIdx.x * 8 + warp;
    const int GW = gridDim.x * 8;
    const int ngroups = N >> 4;

    for (int g = gw; g < ngroups; g += GW) {
        const int n0 = g * 16;

        float C[8][4];
#pragma unroll
        for (int t = 0; t < 8; t++) { C[t][0]=0.f; C[t][1]=0.f; C[t][2]=0.f; C[t][3]=0.f; }
        {
            const float* rA0 = h_ns + (size_t)(n0 + gid) * 128;
            const float* rA1 = rA0 + 8 * 128;
#pragma unroll
            for (int kc = 0; kc < 16; kc++) {
                const int k0 = kc * 8;
                uint32_t a0 = tf32u(__ldg(rA0 + k0 + tig));
                uint32_t a1 = tf32u(__ldg(rA1 + k0 + tig));
                uint32_t a2 = tf32u(__ldg(rA0 + k0 + tig + 4));
                uint32_t a3 = tf32u(__ldg(rA1 + k0 + tig + 4));
                const float* bp0 = sB1 + (k0 + tig) * EW_ST + gid;
                const float* bp1 = bp0 + 4 * EW_ST;
#pragma unroll
                for (int t = 0; t < 8; t++) {
                    uint32_t b0 = __float_as_uint(bp0[8 * t]);
                    uint32_t b1 = __float_as_uint(bp1[8 * t]);
                    mma16n8k8(C[t], a0, a1, a2, a3, b0, b1);
                }
            }
        }
        __syncwarp();
#pragma unroll
        for (int t = 0; t < 8; t++) {
            float2 bb = __ldg((const float2*)(bns1 + 8 * t + 2 * tig));
            float2 lo, hi;
            lo.x = silu_(C[t][0] + bb.x); lo.y = silu_(C[t][1] + bb.y);
            hi.x = silu_(C[t][2] + bb.x); hi.y = silu_(C[t][3] + bb.y);
            *(float2*)&sT[gid * ET_ST + 8 * t + 2 * tig] = lo;
            *(float2*)&sT[(gid + 8) * ET_ST + 8 * t + 2 * tig] = hi;
        }
        __syncwarp();

        float D[8][4];
#pragma unroll
        for (int t = 0; t < 8; t++) { D[t][0]=0.f; D[t][1]=0.f; D[t][2]=0.f; D[t][3]=0.f; }
#pragma unroll
        for (int kc = 0; kc < 8; kc++) {
            const int k0 = kc * 8;
            uint32_t a0 = tf32u(sT[gid * ET_ST + k0 + tig]);
            uint32_t a1 = tf32u(sT[(gid + 8) * ET_ST + k0 + tig]);
            uint32_t a2 = tf32u(sT[gid * ET_ST + k0 + tig + 4]);
            uint32_t a3 = tf32u(sT[(gid + 8) * ET_ST + k0 + tig + 4]);
            const float* bp0 = sB2 + (k0 + tig) * EW_ST + gid;
            const float* bp1 = bp0 + 4 * EW_ST;
#pragma unroll
            for (int t = 0; t < 8; t++) {
                uint32_t b0 = __float_as_uint(bp0[8 * t]);
                uint32_t b1 = __float_as_uint(bp1[8 * t]);
                mma16n8k8(D[t], a0, a1, a2, a3, b0, b1);
            }
        }
#pragma unroll
        for (int t = 0; t < 8; t++) {
            float2 bb = __ldg((const float2*)(bns2 + 8 * t + 2 * tig));
            float2 lo, hi;
            lo.x = D[t][0] + bb.x; lo.y = D[t][1] + bb.y;
            hi.x = D[t][2] + bb.x; hi.y = D[t][3] + bb.y;
            *(float2*)&g_ns_acc[(size_t)(n0 + gid) * 64 + 8 * t + 2 * tig] = lo;
            *(float2*)&g_ns_acc[(size_t)(n0 + gid + 8) * 64 + 8 * t + 2 * tig] = hi;
        }
    }
}

// ---------------------------------------------------------------------------
// Kernel A_vt (tf32 mma): nv1 -> g_nv_acc (x3), ||nt1|| -> g_nt_norm
// ---------------------------------------------------------------------------
#define AVT_SMEM_BYTES ((64*EW_ST + 64*EW_ST) * 4)

__global__ void __launch_bounds__(256, 2) nodeAvt_kernel(
    const float* __restrict__ h_nv, const float* __restrict__ h_nt,
    const float* __restrict__ Wnv1, const float* __restrict__ Wnt1, int N)
{
    extern __shared__ float sm[];
    float* sBnv = sm;
    float* sBnt = sBnv + 64 * EW_ST;

    load_wt_tf32(Wnv1, sBnv, 64, 64, EW_ST);
    load_wt_tf32(Wnt1, sBnt, 64, 64, EW_ST);
    __syncthreads();

    const int lane = threadIdx.x & 31;
    const int warp = threadIdx.x >> 5;
    const int gid = lane >> 2;
    const int tig = lane & 3;

    const int gw = blockIdx.x * 8 + warp;
    const int GW = gridDim.x * 8;
    const int ngroups = N >> 4;

    for (int g = gw; g < ngroups; g += GW) {
        const int n0 = g * 16;

#pragma unroll 1
        for (int a = 0; a < 3; a++) {
            float C[8][4];
#pragma unroll
            for (int t = 0; t < 8; t++) { C[t][0]=0.f; C[t][1]=0.f; C[t][2]=0.f; C[t][3]=0.f; }
            const float* rA0 = h_nv + (size_t)(n0 + gid) * 192 + a * 64;
            const float* rA1 = rA0 + 8 * 192;
#pragma unroll
            for (int kc = 0; kc < 8; kc++) {
                const int k0 = kc * 8;
                uint32_t a0 = tf32u(__ldg(rA0 + k0 + tig));
                uint32_t a1 = tf32u(__ldg(rA1 + k0 + tig));
                uint32_t a2 = tf32u(__ldg(rA0 + k0 + tig + 4));
                uint32_t a3 = tf32u(__ldg(rA1 + k0 + tig + 4));
                const float* bp0 = sBnv + (k0 + tig) * EW_ST + gid;
                const float* bp1 = bp0 + 4 * EW_ST;
#pragma unroll
                for (int t = 0; t < 8; t++) {
                    uint32_t b0 = __float_as_uint(bp0[8 * t]);
                    uint32_t b1 = __float_as_uint(bp1[8 * t]);
                    mma16n8k8(C[t], a0, a1, a2, a3, b0, b1);
                }
            }
#pragma unroll
            for (int t = 0; t < 8; t++) {
                float2 lo, hi;
                lo.x = C[t][0]; lo.y = C[t][1];
                hi.x = C[t][2]; hi.y = C[t][3];
                *(float2*)&g_nv_acc[(size_t)(n0 + gid) * 192 + a * 64 + 8 * t + 2 * tig] = lo;
                *(float2*)&g_nv_acc[(size_t)(n0 + gid + 8) * 192 + a * 64 + 8 * t + 2 * tig] = hi;
            }
        }

        float sq[8][4];
#pragma unroll
        for (int t = 0; t < 8; t++) { sq[t][0]=0.f; sq[t][1]=0.f; sq[t][2]=0.f; sq[t][3]=0.f; }
#pragma unroll 1
        for (int c = 0; c < 9; c++) {
            float C[8][4];
#pragma unroll
            for (int t = 0; t < 8; t++) { C[t][0]=0.f; C[t][1]=0.f; C[t][2]=0.f; C[t][3]=0.f; }
            const float* rA0 = h_nt + (size_t)(n0 + gid) * 576 + c * 64;
            const float* rA1 = rA0 + 8 * 576;
#pragma unroll
            for (int kc = 0; kc < 8; kc++) {
                const int k0 = kc * 8;
                uint32_t a0 = tf32u(__ldg(rA0 + k0 + tig));
                uint32_t a1 = tf32u(__ldg(rA1 + k0 + tig));
                uint32_t a2 = tf32u(__ldg(rA0 + k0 + tig + 4));
                uint32_t a3 = tf32u(__ldg(rA1 + k0 + tig + 4));
                const float* bp0 = sBnt + (k0 + tig) * EW_ST + gid;
                const float* bp1 = bp0 + 4 * EW_ST;
#pragma unroll
                for (int t = 0; t < 8; t++) {
                    uint32_t b0 = __float_as_uint(bp0[8 * t]);
                    uint32_t b1 = __float_as_uint(bp1[8 * t]);
                    mma16n8k8(C[t], a0, a1, a2, a3, b0, b1);
                }
            }
#pragma unroll
            for (int t = 0; t < 8; t++) {
                sq[t][0] += C[t][0] * C[t][0];
                sq[t][1] += C[t][1] * C[t][1];
                sq[t][2] += C[t][2] * C[t][2];
                sq[t][3] += C[t][3] * C[t][3];
            }
        }
#pragma unroll
        for (int t = 0; t < 8; t++) {
            float2 lo, hi;
            lo.x = sqrtf(sq[t][0]); lo.y = sqrtf(sq[t][1]);
            hi.x = sqrtf(sq[t][2]); hi.y = sqrtf(sq[t][3]);
            *(float2*)&g_nt_norm[(size_t)(n0 + gid) * 64 + 8 * t + 2 * tig] = lo;
            *(float2*)&g_nt_norm[(size_t)(n0 + gid + 8) * 64 + 8 * t + 2 * tig] = hi;
        }
    }
}

// ---------------------------------------------------------------------------
// Edge kernel (R14-exact, tf32 mma)
// ---------------------------------------------------------------------------
#define E_SMEM_BYTES ((128*EW_ST + 64*EW_ST + 64*EW_ST + 8*16*ET_ST) * 4)

__global__ void __launch_bounds__(256, 2) edge_kernel(
    const float* __restrict__ h_es, const float* __restrict__ h_ev,
    const int* __restrict__ idx1, const int* __restrict__ idx2,
    const float* __restrict__ Wes1, const float* __restrict__ bes1,
    const float* __restrict__ Wes2, const float* __restrict__ bes2,
    const float* __restrict__ Wev1, int E)
{
    extern __shared__ float sm[];
    float* sB1  = sm;
    float* sB2  = sB1 + 128 * EW_ST;
    float* sBev = sB2 + 64 * EW_ST;
    float* sTA  = sBev + 64 * EW_ST;

    load_wt_tf32(Wes1, sB1, 64, 128, EW_ST);
    load_wt_tf32(Wes2, sB2, 64, 64, EW_ST);
    load_wt_tf32(Wev1, sBev, 64, 64, EW_ST);
    __syncthreads();

    const int lane = threadIdx.x & 31;
    const int warp = threadIdx.x >> 5;
    const int gid = lane >> 2;
    const int tig = lane & 3;
    float* sT = sTA + warp * (16 * ET_ST);

    const int gw = blockIdx.x * 8 + warp;
    const int GW = gridDim.x * 8;
    const int ngroups = E >> 4;

    for (int g = gw; g < ngroups; g += GW) {
        const int e0 = g * 16;

        float C[8][4];
#pragma unroll
        for (int t = 0; t < 8; t++) { C[t][0]=0.f; C[t][1]=0.f; C[t][2]=0.f; C[t][3]=0.f; }
        {
            const float* rA0 = h_es + (size_t)(e0 + gid) * 128;
            const float* rA1 = rA0 + 8 * 128;
#pragma unroll
            for (int kc = 0; kc < 16; kc++) {
                const int k0 = kc * 8;
                uint32_t a0 = tf32u(__ldg(rA0 + k0 + tig));
                uint32_t a1 = tf32u(__ldg(rA1 + k0 + tig));
                uint32_t a2 = tf32u(__ldg(rA0 + k0 + tig + 4));
                uint32_t a3 = tf32u(__ldg(rA1 + k0 + tig + 4));
                const float* bp0 = sB1 + (k0 + tig) * EW_ST + gid;
                const float* bp1 = bp0 + 4 * EW_ST;
#pragma unroll
                for (int t = 0; t < 8; t++) {
                    uint32_t b0 = __float_as_uint(bp0[8 * t]);
                    uint32_t b1 = __float_as_uint(bp1[8 * t]);
                    mma16n8k8(C[t], a0, a1, a2, a3, b0, b1);
                }
            }
        }
        __syncwarp();
#pragma unroll
        for (int t = 0; t < 8; t++) {
            float2 bb = __ldg((const float2*)(bes1 + 8 * t + 2 * tig));
            float2 lo, hi;
            lo.x = silu_(C[t][0] + bb.x); lo.y = silu_(C[t][1] + bb.y);
            hi.x = silu_(C[t][2] + bb.x); hi.y = silu_(C[t][3] + bb.y);
            *(float2*)&sT[gid * ET_ST + 8 * t + 2 * tig] = lo;
            *(float2*)&sT[(gid + 8) * ET_ST + 8 * t + 2 * tig] = hi;
        }
        __syncwarp();

        float D[8][4];
#pragma unroll
        for (int t = 0; t < 8; t++) { D[t][0]=0.f; D[t][1]=0.f; D[t][2]=0.f; D[t][3]=0.f; }
#pragma unroll
        for (int kc = 0; kc < 8; kc++) {
            const int k0 = kc * 8;
            uint32_t a0 = tf32u(sT[gid * ET_ST + k0 + tig]);
            uint32_t a1 = tf32u(sT[(gid + 8) * ET_ST + k0 + tig]);
            uint32_t a2 = tf32u(sT[gid * ET_ST + k0 + tig + 4]);
            uint32_t a3 = tf32u(sT[(gid + 8) * ET_ST + k0 + tig + 4]);
            const float* bp0 = sB2 + (k0 + tig) * EW_ST + gid;
            const float* bp1 = bp0 + 4 * EW_ST;
#pragma unroll
            for (int t = 0; t < 8; t++) {
                uint32_t b0 = __float_as_uint(bp0[8 * t]);
                uint32_t b1 = __float_as_uint(bp1[8 * t]);
                mma16n8k8(D[t], a0, a1, a2, a3, b0, b1);
            }
        }
        __syncwarp();
#pragma unroll
        for (int t = 0; t < 8; t++) {
            float2 bb = __ldg((const float2*)(bes2 + 8 * t + 2 * tig));
            float2 lo, hi;
            lo.x = D[t][0] + bb.x; lo.y = D[t][1] + bb.y;
            hi.x = D[t][2] + bb.x; hi.y = D[t][3] + bb.y;
            *(float2*)&sT[gid * ET_ST + 8 * t + 2 * tig] = lo;
            *(float2*)&sT[(gid + 8) * ET_ST + 8 * t + 2 * tig] = hi;
        }
        __syncwarp();

#pragma unroll
        for (int j = 0; j < 8; j++) {
            int cid = lane + 32 * j;
            int r = cid >> 4, c = (cid & 15) * 4;
            float4 v = *(const float4*)&sT[r * ET_ST + c];
            int i1 = __ldg(idx1 + e0 + r), i2 = __ldg(idx2 + e0 + r);
            red_add_v4(g_ns_acc + (size_t)i1 * 64 + c, v);
            red_add_v4(g_ns_acc + (size_t)i2 * 64 + c, v);
        }

#pragma unroll 1
        for (int a = 0; a < 3; a++) {
            float Ea[8][4];
#pragma unroll
            for (int t = 0; t < 8; t++) { Ea[t][0]=0.f; Ea[t][1]=0.f; Ea[t][2]=0.f; Ea[t][3]=0.f; }
            const float* rV0 = h_ev + (size_t)(e0 + gid) * 192 + a * 64;
            const float* rV1 = rV0 + 8 * 192;
#pragma unroll
            for (int kc = 0; kc < 8; kc++) {
                const int k0 = kc * 8;
                uint32_t a0 = tf32u(__ldg(rV0 + k0 + tig));
                uint32_t a1 = tf32u(__ldg(rV1 + k0 + tig));
                uint32_t a2 = tf32u(__ldg(rV0 + k0 + tig + 4));
                uint32_t a3 = tf32u(__ldg(rV1 + k0 + tig + 4));
                const float* bp0 = sBev + (k0 + tig) * EW_ST + gid;
                const float* bp1 = bp0 + 4 * EW_ST;
#pragma unroll
                for (int t = 0; t < 8; t++) {
                    uint32_t b0 = __float_as_uint(bp0[8 * t]);
                    uint32_t b1 = __float_as_uint(bp1[8 * t]);
                    mma16n8k8(Ea[t], a0, a1, a2, a3, b0, b1);
                }
            }
            __syncwarp();
#pragma unroll
            for (int t = 0; t < 8; t++) {
                float2 lo, hi;
                lo.x = Ea[t][0]; lo.y = Ea[t][1];
                hi.x = Ea[t][2]; hi.y = Ea[t][3];
                *(float2*)&sT[gid * ET_ST + 8 * t + 2 * tig] = lo;
                *(float2*)&sT[(gid + 8) * ET_ST + 8 * t + 2 * tig] = hi;
            }
            __syncwarp();
#pragma unroll
            for (int j = 0; j < 8; j++) {
                int cid = lane + 32 * j;
                int r = cid >> 4, c = (cid & 15) * 4;
                float4 v = *(const float4*)&sT[r * ET_ST + c];
                int i1 = __ldg(idx1 + e0 + r), i2 = __ldg(idx2 + e0 + r);
                red_add_v4(g_nv_acc + (size_t)i1 * 192 + a * 64 + c, v);
                red_add_v4(g_nv_acc + (size_t)i2 * 192 + a * 64 + c, v);
            }
        }
    }
}

// ---------------------------------------------------------------------------
// Kernel C1 (NEW, tf32 mma): h_cat gather + K=192, N=96 GEMM -> g_mid
// smem: 192*104 + 8*16*196 = 45056 floats (180,224 B) -> 1 CTA/SM
// ---------------------------------------------------------------------------
#define C1_W_ST 104
#define C1_T_ST 196
#define C1_SMEM_BYTES ((192*C1_W_ST + 8*16*C1_T_ST) * 4)

__global__ void __launch_bounds__(256, 1) nodeC1_kernel(
    const float* __restrict__ Wc1, const float* __restrict__ bc1, int N)
{
    extern __shared__ float sm[];
    float* sB  = sm;                     // 192 x 104 (tf32 Wc1 [k][n], n<96)
    float* sTA = sB + 192 * C1_W_ST;     // 8 warps x 16 x 196

    load_wt_tf32(Wc1, sB, 96, 192, C1_W_ST);
    __syncthreads();

    const int lane = threadIdx.x & 31;
    const int warp = threadIdx.x >> 5;
    const int gid = lane >> 2;
    const int tig = lane & 3;
    float* sT = sTA + warp * (16 * C1_T_ST);

    const int gw = blockIdx.x * 8 + warp;
    const int GW = gridDim.x * 8;
    const int ngroups = N >> 4;

    for (int g = gw; g < ngroups; g += GW) {
        const int n0 = g * 16;
        __syncwarp();
        // gather h_cat: [ns_acc | ||nv_int|| | nt_norm] into 16 x 196 staging
#pragma unroll 1
        for (int r = 0; r < 16; r++) {
            const size_t n = (size_t)(n0 + r);
            float2 s = *(const float2*)&g_ns_acc[n * 64 + 2 * lane];
            *(float2*)&sT[r * C1_T_ST + 2 * lane] = s;
            float2 v0 = *(const float2*)&g_nv_acc[n * 192 + 0   + 2 * lane];
            float2 v1 = *(const float2*)&g_nv_acc[n * 192 + 64  + 2 * lane];
            float2 v2 = *(const float2*)&g_nv_acc[n * 192 + 128 + 2 * lane];
            float2 nn;
            nn.x = sqrtf(v0.x * v0.x + v1.x * v1.x + v2.x * v2.x);
            nn.y = sqrtf(v0.y * v0.y + v1.y * v1.y + v2.y * v2.y);
            *(float2*)&sT[r * C1_T_ST + 64 + 2 * lane] = nn;
            float2 tn = *(const float2*)&g_nt_norm[n * 64 + 2 * lane];
            *(float2*)&sT[r * C1_T_ST + 128 + 2 * lane] = tn;
        }
        __syncwarp();

        // GEMM: K=192, N=96 (12 col-groups)
        float C[12][4];
#pragma unroll
        for (int t = 0; t < 12; t++) { C[t][0]=0.f; C[t][1]=0.f; C[t][2]=0.f; C[t][3]=0.f; }
#pragma unroll
        for (int kc = 0; kc < 24; kc++) {
            const int k0 = kc * 8;
            uint32_t a0 = tf32u(sT[gid * C1_T_ST + k0 + tig]);
            uint32_t a1 = tf32u(sT[(gid + 8) * C1_T_ST + k0 + tig]);
            uint32_t a2 = tf32u(sT[gid * C1_T_ST + k0 + tig + 4]);
            uint32_t a3 = tf32u(sT[(gid + 8) * C1_T_ST + k0 + tig + 4]);
            const float* bp0 = sB + (k0 + tig) * C1_W_ST + gid;
            const float* bp1 = bp0 + 4 * C1_W_ST;
#pragma unroll
            for (int t = 0; t < 12; t++) {
                uint32_t b0 = __float_as_uint(bp0[8 * t]);
                uint32_t b1 = __float_as_uint(bp1[8 * t]);
                mma16n8k8(C[t], a0, a1, a2, a3, b0, b1);
            }
        }
#pragma unroll
        for (int t = 0; t < 12; t++) {
            float2 bb = __ldg((const float2*)(bc1 + 8 * t + 2 * tig));
            float2 lo, hi;
            lo.x = silu_(C[t][0] + bb.x); lo.y = silu_(C[t][1] + bb.y);
            hi.x = silu_(C[t][2] + bb.x); hi.y = silu_(C[t][3] + bb.y);
            *(float2*)&g_mid[(size_t)(n0 + gid) * 96 + 8 * t + 2 * tig] = lo;
            *(float2*)&g_mid[(size_t)(n0 + gid + 8) * 96 + 8 * t + 2 * tig] = hi;
        }
    }
}

// ---------------------------------------------------------------------------
// Kernel C2a (NEW, tf32 mma): ns_out = g_mid @ Wc2[0:128].T + bc2 + h_ns
// smem: 96*136 = 13056 floats (52,224 B) -> 2 CTAs/SM
// ---------------------------------------------------------------------------
#define C2_W_ST 136
#define C2A_SMEM_BYTES ((96*C2_W_ST) * 4)

__global__ void __launch_bounds__(256, 2) nodeC2a_kernel(
    const float* __restrict__ h_ns,
    const float* __restrict__ Wc2, const float* __restrict__ bc2,
    float* __restrict__ out, int N)
{
    extern __shared__ float sm[];
    float* sB = sm;   // 96 x 136 (tf32 Wc2 rows 0..127, [k][n])

    load_wt_part_tf32(Wc2, sB, 0, 128, 96, C2_W_ST);
    __syncthreads();

    const int lane = threadIdx.x & 31;
    const int warp = threadIdx.x >> 5;
    const int gid = lane >> 2;
    const int tig = lane & 3;

    const int gw = blockIdx.x * 8 + warp;
    const int GW = gridDim.x * 8;
    const int ngroups = N >> 4;

    for (int g = gw; g < ngroups; g += GW) {
        const int n0 = g * 16;
        const float* rA0 = g_mid + (size_t)(n0 + gid) * 96;
        const float* rA1 = rA0 + 8 * 96;

#pragma unroll 1
        for (int half = 0; half < 2; half++) {
            const int oc = half * 64;
            float C[8][4];
#pragma unroll
            for (int t = 0; t < 8; t++) { C[t][0]=0.f; C[t][1]=0.f; C[t][2]=0.f; C[t][3]=0.f; }
#pragma unroll
            for (int kc = 0; kc < 12; kc++) {
                const int k0 = kc * 8;
                uint32_t a0 = tf32u(__ldg(rA0 + k0 + tig));
                uint32_t a1 = tf32u(__ldg(rA1 + k0 + tig));
                uint32_t a2 = tf32u(__ldg(rA0 + k0 + tig + 4));
                uint32_t a3 = tf32u(__ldg(rA1 + k0 + tig + 4));
                const float* bp0 = sB + (k0 + tig) * C2_W_ST + gid + oc;
                const float* bp1 = bp0 + 4 * C2_W_ST;
#pragma unroll
                for (int t = 0; t < 8; t++) {
                    uint32_t b0 = __float_as_uint(bp0[8 * t]);
                    uint32_t b1 = __float_as_uint(bp1[8 * t]);
                    mma16n8k8(C[t], a0, a1, a2, a3, b0, b1);
                }
            }
#pragma unroll
            for (int t = 0; t < 8; t++) {
                const int c = oc + 8 * t + 2 * tig;
                float2 bb = __ldg((const float2*)(bc2 + c));
                float2 h0 = __ldg((const float2*)(h_ns + (size_t)(n0 + gid) * 128 + c));
                float2 h1 = __ldg((const float2*)(h_ns + (size_t)(n0 + gid + 8) * 128 + c));
                float2 lo, hi;
                lo.x = C[t][0] + bb.x + h0.x; lo.y = C[t][1] + bb.y + h0.y;
                hi.x = C[t][2] + bb.x + h1.x; hi.y = C[t][3] + bb.y + h1.y;
                *(float2*)&out[(size_t)(n0 + gid) * 128 + c] = lo;
                *(float2*)&out[(size_t)(n0 + gid + 8) * 128 + c] = hi;
            }
        }
    }
}

// ---------------------------------------------------------------------------
// Kernel C2b (NEW, tf32 mma): register-resident gates + nv/nt epilogues
// smem: 96*136 + 2*64*72 = 22272 floats (89,088 B) -> 2 CTAs/SM
// ---------------------------------------------------------------------------
#define C2B_SMEM_BYTES ((96*C2_W_ST + 64*EW_ST + 64*EW_ST) * 4)

__global__ void __launch_bounds__(256, 2) nodeC2b_kernel(
    const float* __restrict__ h_nv, const float* __restrict__ h_nt,
    const float* __restrict__ Wnv2, const float* __restrict__ Wnt2,
    const float* __restrict__ Wc2, const float* __restrict__ bc2,
    float* __restrict__ out, int N)
{
    extern __shared__ float sm[];
    float* sBg  = sm;                    // 96 x 136 (tf32 Wc2 rows 128..255)
    float* sBnv = sBg + 96 * C2_W_ST;    // 64 x 72
    float* sBnt = sBnv + 64 * EW_ST;     // 64 x 72

    load_wt_part_tf32(Wc2, sBg, 128, 128, 96, C2_W_ST);
    load_wt_tf32(Wnv2, sBnv, 64, 64, EW_ST);
    load_wt_tf32(Wnt2, sBnt, 64, 64, EW_ST);
    __syncthreads();

    const int lane = threadIdx.x & 31;
    const int warp = threadIdx.x >> 5;
    const int gid = lane >> 2;
    const int tig = lane & 3;

    float* nv_out = out + (size_t)N * 128;
    float* nt_out = out + (size_t)N * 320;

    const int gw = blockIdx.x * 8 + warp;
    const int GW = gridDim.x * 8;
    const int ngroups = N >> 4;

    for (int g = gw; g < ngroups; g += GW) {
        const int n0 = g * 16;
        const float* rM0 = g_mid + (size_t)(n0 + gid) * 96;
        const float* rM1 = rM0 + 8 * 96;

        // --- nv gates: sigmoid(mid @ Wc2[128:192].T + b) in fragments ---
        float G[8][4];
#pragma unroll
        for (int t = 0; t < 8; t++) { G[t][0]=0.f; G[t][1]=0.f; G[t][2]=0.f; G[t][3]=0.f; }
#pragma unroll
        for (int kc = 0; kc < 12; kc++) {
            const int k0 = kc * 8;
            uint32_t a0 = tf32u(__ldg(rM0 + k0 + tig));
            uint32_t a1 = tf32u(__ldg(rM1 + k0 + tig));
            uint32_t a2 = tf32u(__ldg(rM0 + k0 + tig + 4));
            uint32_t a3 = tf32u(__ldg(rM1 + k0 + tig + 4));
            const float* bp0 = sBg + (k0 + tig) * C2_W_ST + gid;
            const float* bp1 = bp0 + 4 * C2_W_ST;
#pragma unroll
            for (int t = 0; t < 8; t++) {
                uint32_t b0 = __float_as_uint(bp0[8 * t]);
                uint32_t b1 = __float_as_uint(bp1[8 * t]);
                mma16n8k8(G[t], a0, a1, a2, a3, b0, b1);
            }
        }
#pragma unroll
        for (int t = 0; t < 8; t++) {
            float2 bb = __ldg((const float2*)(bc2 + 128 + 8 * t + 2 * tig));
            G[t][0] = sigm_(G[t][0] + bb.x); G[t][1] = sigm_(G[t][1] + bb.y);
            G[t][2] = sigm_(G[t][2] + bb.x); G[t][3] = sigm_(G[t][3] + bb.y);
        }

        // nv_out = G * (h_nv @ Wnv2.T) + h_nv  (same fragment mapping)
#pragma unroll 1
        for (int a = 0; a < 3; a++) {
            float Ea[8][4];
#pragma unroll
            for (int t = 0; t < 8; t++) { Ea[t][0]=0.f; Ea[t][1]=0.f; Ea[t][2]=0.f; Ea[t][3]=0.f; }
            const float* rV0 = h_nv + (size_t)(n0 + gid) * 192 + a * 64;
            const float* rV1 = rV0 + 8 * 192;
#pragma unroll
            for (int kc = 0; kc < 8; kc++) {
                const int k0 = kc * 8;
                uint32_t a0 = tf32u(__ldg(rV0 + k0 + tig));
                uint32_t a1 = tf32u(__ldg(rV1 + k0 + tig));
                uint32_t a2 = tf32u(__ldg(rV0 + k0 + tig + 4));
                uint32_t a3 = tf32u(__ldg(rV1 + k0 + tig + 4));
                const float* bp0 = sBnv + (k0 + tig) * EW_ST + gid;
                const float* bp1 = bp0 + 4 * EW_ST;
#pragma unroll
                for (int t = 0; t < 8; t++) {
                    uint32_t b0 = __float_as_uint(bp0[8 * t]);
                    uint32_t b1 = __float_as_uint(bp1[8 * t]);
                    mma16n8k8(Ea[t], a0, a1, a2, a3, b0, b1);
                }
            }
#pragma unroll
            for (int t = 0; t < 8; t++) {
                const int c = a * 64 + 8 * t + 2 * tig;
                float2 h0 = __ldg((const float2*)(h_nv + (size_t)(n0 + gid) * 192 + c));
                float2 h1 = __ldg((const float2*)(h_nv + (size_t)(n0 + gid + 8) * 192 + c));
                float2 lo, hi;
                lo.x = G[t][0] * Ea[t][0] + h0.x; lo.y = G[t][1] * Ea[t][1] + h0.y;
                hi.x = G[t][2] * Ea[t][2] + h1.x; hi.y = G[t][3] * Ea[t][3] + h1.y;
                *(float2*)&nv_out[(size_t)(n0 + gid) * 192 + c] = lo;
                *(float2*)&nv_out[(size_t)(n0 + gid + 8) * 192 + c] = hi;
            }
        }

        // --- nt gates ---
#pragma unroll
        for (int t = 0; t < 8; t++) { G[t][0]=0.f; G[t][1]=0.f; G[t][2]=0.f; G[t][3]=0.f; }
#pragma unroll
        for (int kc = 0; kc < 12; kc++) {
            const int k0 = kc * 8;
            uint32_t a0 = tf32u(__ldg(rM0 + k0 + tig));
            uint32_t a1 = tf32u(__ldg(rM1 + k0 + tig));
            uint32_t a2 = tf32u(__ldg(rM0 + k0 + tig + 4));
            uint32_t a3 = tf32u(__ldg(rM1 + k0 + tig + 4));
            const float* bp0 = sBg + (k0 + tig) * C2_W_ST + gid + 64;
            const float* bp1 = bp0 + 4 * C2_W_ST;
#pragma unroll
            for (int t = 0; t < 8; t++) {
                uint32_t b0 = __float_as_uint(bp0[8 * t]);
                uint32_t b1 = __float_as_uint(bp1[8 * t]);
                mma16n8k8(G[t], a0, a1, a2, a3, b0, b1);
            }
        }
#pragma unroll
        for (int t = 0; t < 8; t++) {
            float2 bb = __ldg((const float2*)(bc2 + 192 + 8 * t + 2 * tig));
            G[t][0] = sigm_(G[t][0] + bb.x); G[t][1] = sigm_(G[t][1] + bb.y);
            G[t][2] = sigm_(G[t][2] + bb.x); G[t][3] = sigm_(G[t][3] + bb.y);
        }

        // nt_out = G * (h_nt @ Wnt2.T) + h_nt  (9 components)
#pragma unroll 1
        for (int c9 = 0; c9 < 9; c9++) {
            float Ea[8][4];
#pragma unroll
            for (int t = 0; t < 8; t++) { Ea[t][0]=0.f; Ea[t][1]=0.f; Ea[t][2]=0.f; Ea[t][3]=0.f; }
            const float* rT0 = h_nt + (size_t)(n0 + gid) * 576 + c9 * 64;
            const float* rT1 = rT0 + 8 * 576;
#pragma unroll
            for (int kc = 0; kc < 8; kc++) {
                const int k0 = kc * 8;
                uint32_t a0 = tf32u(__ldg(rT0 + k0 + tig));
                uint32_t a1 = tf32u(__ldg(rT1 + k0 + tig));
                uint32_t a2 = tf32u(__ldg(rT0 + k0 + tig + 4));
                uint32_t a3 = tf32u(__ldg(rT1 + k0 + tig + 4));
                const float* bp0 = sBnt + (k0 + tig) * EW_ST + gid;
                const float* bp1 = bp0 + 4 * EW_ST;
#pragma unroll
                for (int t = 0; t < 8; t++) {
                    uint32_t b0 = __float_as_uint(bp0[8 * t]);
                    uint32_t b1 = __float_as_uint(bp1[8 * t]);
                    mma16n8k8(Ea[t], a0, a1, a2, a3, b0, b1);
                }
            }
#pragma unroll
            for (int t = 0; t < 8; t++) {
                const int c = c9 * 64 + 8 * t + 2 * tig;
                float2 h0 = __ldg((const float2*)(h_nt + (size_t)(n0 + gid) * 576 + c));
                float2 h1 = __ldg((const float2*)(h_nt + (size_t)(n0 + gid + 8) * 576 + c));
                float2 lo, hi;
                lo.x = G[t][0] * Ea[t][0] + h0.x; lo.y = G[t][1] * Ea[t][1] + h0.y;
                hi.x = G[t][2] * Ea[t][2] + h1.x; hi.y = G[t][3] * Ea[t][3] + h1.y;
                *(float2*)&nt_out[(size_t)(n0 + gid) * 576 + c] = lo;
                *(float2*)&nt_out[(size_t)(n0 + gid + 8) * 576 + c] = hi;
            }
        }
    }
}

// ---------------------------------------------------------------------------
extern "C" void kernel_launch(void* const* d_in, const int* in_sizes, int n_in,
                              void* d_out, int out_size)
{
    const float* h_ns = (const float*)d_in[0];
    const float* h_nv = (const float*)d_in[1];
    const float* h_nt = (const float*)d_in[2];
    const float* h_es = (const float*)d_in[3];
    const float* h_ev = (const float*)d_in[4];
    const int*   idx1 = (const int*)d_in[5];
    const int*   idx2 = (const int*)d_in[6];
    const float* Wns1 = (const float*)d_in[7];
    const float* bns1 = (const float*)d_in[8];
    const float* Wns2 = (const float*)d_in[9];
    const float* bns2 = (const float*)d_in[10];
    const float* Wes1 = (const float*)d_in[11];
    const float* bes1 = (const float*)d_in[12];
    const float* Wes2 = (const float*)d_in[13];
    const float* bes2 = (const float*)d_in[14];
    const float* Wnv1 = (const float*)d_in[15];
    const float* Wnv2 = (const float*)d_in[16];
    const float* Wev1 = (const float*)d_in[17];
    const float* Wnt1 = (const float*)d_in[18];
    const float* Wnt2 = (const float*)d_in[19];
    const float* Wc1  = (const float*)d_in[20];
    const float* bc1  = (const float*)d_in[21];
    const float* Wc2  = (const float*)d_in[22];
    const float* bc2  = (const float*)d_in[23];
    float* out = (float*)d_out;

    const int N = in_sizes[0] / 128;   // h_ns is (N, 128)
    const int E = in_sizes[5];         // atom_index1 is (E,)

    cudaFuncSetAttribute(nodeAs_kernel,  cudaFuncAttributeMaxDynamicSharedMemorySize, AS_SMEM_BYTES);
    cudaFuncSetAttribute(nodeAvt_kernel, cudaFuncAttributeMaxDynamicSharedMemorySize, AVT_SMEM_BYTES);
    cudaFuncSetAttribute(edge_kernel,    cudaFuncAttributeMaxDynamicSharedMemorySize, E_SMEM_BYTES);
    cudaFuncSetAttribute(nodeC1_kernel,  cudaFuncAttributeMaxDynamicSharedMemorySize, C1_SMEM_BYTES);
    cudaFuncSetAttribute(nodeC2a_kernel, cudaFuncAttributeMaxDynamicSharedMemorySize, C2A_SMEM_BYTES);
    cudaFuncSetAttribute(nodeC2b_kernel, cudaFuncAttributeMaxDynamicSharedMemorySize, C2B_SMEM_BYTES);

    nodeAs_kernel<<<304, 256, AS_SMEM_BYTES>>>(h_ns, Wns1, bns1, Wns2, bns2, N);

    nodeAvt_kernel<<<304, 256, AVT_SMEM_BYTES>>>(h_nv, h_nt, Wnv1, Wnt1, N);

    edge_kernel<<<304, 256, E_SMEM_BYTES>>>(
        h_es, h_ev, idx1, idx2, Wes1, bes1, Wes2, bes2, Wev1, E);

    nodeC1_kernel<<<152, 256, C1_SMEM_BYTES>>>(Wc1, bc1, N);

    nodeC2a_kernel<<<304, 256, C2A_SMEM_BYTES>>>(h_ns, Wc2, bc2, out, N);

    nodeC2b_kernel<<<304, 256, C2B_SMEM_BYTES>>>(
        h_nv, h_nt, Wnv2, Wnt2, Wc2, bc2, out, N);
}

// round 17
// speedup vs baseline: 2.7870x; 1.0245x over previous
#include <cuda_runtime.h>
#include <cuda_bf16.h>
#include <cstdint>

// Scratch (device globals — no allocation allowed)
#define NMAX 20000
__device__ __align__(16) float g_ns_acc[NMAX * 64];    // h_ns_int (hs + scattered es)
__device__ __align__(16) float g_nv_acc[NMAX * 192];   // nv_int   (nv1 + scattered ev1)
__device__ __align__(16) float g_nt_norm[NMAX * 64];   // ||nt1||
__device__ __align__(16) float g_mid[NMAX * 96];       // silu(h_cat @ Wc1.T + bc1)

__device__ __forceinline__ float sigm_(float x) { return 1.0f / (1.0f + __expf(-x)); }
__device__ __forceinline__ float silu_(float x) { return x * sigm_(x); }

__device__ __forceinline__ void red_add_v4(float* p, float4 v) {
    asm volatile("red.global.add.v4.f32 [%0], {%1,%2,%3,%4};"
                 :: "l"(p), "f"(v.x), "f"(v.y), "f"(v.z), "f"(v.w) : "memory");
}

// tf32 round (rna) for weights (done once at smem load time)
__device__ __forceinline__ float tf32f(float x) {
    uint32_t u; asm("cvt.rna.tf32.f32 %0, %1;" : "=r"(u) : "f"(x));
    return __uint_as_float(u);
}
// A operands: raw fp32 bits — HMMA's tf32 path reads only the tf32 bits
// (truncation; same error magnitude as rna, zero ALU cost).
__device__ __forceinline__ uint32_t rawu(float x) { return __float_as_uint(x); }

// m16n8k8 tf32 MMA, fp32 accumulate
__device__ __forceinline__ void mma16n8k8(float (&c)[4],
                                          uint32_t a0, uint32_t a1, uint32_t a2, uint32_t a3,
                                          uint32_t b0, uint32_t b1) {
    asm volatile("mma.sync.aligned.m16n8k8.row.col.f32.tf32.tf32.f32 "
                 "{%0,%1,%2,%3}, {%4,%5,%6,%7}, {%8,%9}, {%0,%1,%2,%3};"
                 : "+f"(c[0]), "+f"(c[1]), "+f"(c[2]), "+f"(c[3])
                 : "r"(a0), "r"(a1), "r"(a2), "r"(a3), "r"(b0), "r"(b1));
}

// Pair-interleaved tf32 B storage. For k-block kb=k/8, column n, the 8
// k-values live at base ((kb*NW + n)*8), element index tig*2 + half where
// k = kb*8 + half*4 + tig. A thread's (b0,b1) fragment pair is ONE float2:
//   bp = sB + ((kc*NW + gid)<<3) + 2*tig;  pair for col-group t = bp[t*32]
// Conflict-free: fixed t -> lane addrs gid*8+2*tig tile 64 floats exactly.
__device__ __forceinline__ void load_wt_pair_tf32(const float* __restrict__ W, float* sB,
                                                  int o_begin, int O, int K, int NW) {
    for (int i = threadIdx.x; i < O * K; i += blockDim.x) {
        int o = i / K, k = i - o * K;
        int kb = k >> 3, tig = k & 3, half = (k >> 2) & 1;
        sB[((kb * NW + o) << 3) + tig * 2 + half] =
            tf32f(W[(size_t)(o_begin + o) * K + k]);
    }
}

#define ET_ST 68

// ---------------------------------------------------------------------------
// Kernel A_s: hs = MLP(h_ns) -> g_ns_acc. 16 nodes/warp, tf32 mma.
// smem: 128*64 + 64*64 + 8*16*68 = 20992 floats (83,968 B) -> 2 CTAs/SM
// ---------------------------------------------------------------------------
#define AS_SMEM_BYTES ((128*64 + 64*64 + 8*16*ET_ST) * 4)

__global__ void __launch_bounds__(256, 2) nodeAs_kernel(
    const float* __restrict__ h_ns,
    const float* __restrict__ Wns1, const float* __restrict__ bns1,
    const float* __restrict__ Wns2, const float* __restrict__ bns2, int N)
{
    extern __shared__ float sm[];
    float* sB1 = sm;                 // K=128, NW=64 pair layout
    float* sB2 = sB1 + 128 * 64;     // K=64, NW=64
    float* sTA = sB2 + 64 * 64;

    load_wt_pair_tf32(Wns1, sB1, 0, 64, 128, 64);
    load_wt_pair_tf32(Wns2, sB2, 0, 64, 64, 64);
    __syncthreads();

    const int lane = threadIdx.x & 31;
    const int warp = threadIdx.x >> 5;
    const int gid = lane >> 2;
    const int tig = lane & 3;
    float* sT = sTA + warp * (16 * ET_ST);

    const int gw = blockIdx.x * 8 + warp;
    const int GW = gridDim.x * 8;
    const int ngroups = N >> 4;

    for (int g = gw; g < ngroups; g += GW) {
        const int n0 = g * 16;

        float C[8][4];
#pragma unroll
        for (int t = 0; t < 8; t++) { C[t][0]=0.f; C[t][1]=0.f; C[t][2]=0.f; C[t][3]=0.f; }
        {
            const float* rA0 = h_ns + (size_t)(n0 + gid) * 128;
            const float* rA1 = rA0 + 8 * 128;
#pragma unroll
            for (int kc = 0; kc < 16; kc++) {
                const int k0 = kc * 8;
                uint32_t a0 = rawu(__ldg(rA0 + k0 + tig));
                uint32_t a1 = rawu(__ldg(rA1 + k0 + tig));
                uint32_t a2 = rawu(__ldg(rA0 + k0 + tig + 4));
                uint32_t a3 = rawu(__ldg(rA1 + k0 + tig + 4));
                const float2* bp = (const float2*)(sB1 + ((kc * 64 + gid) << 3) + 2 * tig);
#pragma unroll
                for (int t = 0; t < 8; t++) {
                    float2 bv = bp[t * 32];
                    mma16n8k8(C[t], a0, a1, a2, a3, rawu(bv.x), rawu(bv.y));
                }
            }
        }
        __syncwarp();
#pragma unroll
        for (int t = 0; t < 8; t++) {
            float2 bb = __ldg((const float2*)(bns1 + 8 * t + 2 * tig));
            float2 lo, hi;
            lo.x = silu_(C[t][0] + bb.x); lo.y = silu_(C[t][1] + bb.y);
            hi.x = silu_(C[t][2] + bb.x); hi.y = silu_(C[t][3] + bb.y);
            *(float2*)&sT[gid * ET_ST + 8 * t + 2 * tig] = lo;
            *(float2*)&sT[(gid + 8) * ET_ST + 8 * t + 2 * tig] = hi;
        }
        __syncwarp();

        float D[8][4];
#pragma unroll
        for (int t = 0; t < 8; t++) { D[t][0]=0.f; D[t][1]=0.f; D[t][2]=0.f; D[t][3]=0.f; }
#pragma unroll
        for (int kc = 0; kc < 8; kc++) {
            const int k0 = kc * 8;
            uint32_t a0 = rawu(sT[gid * ET_ST + k0 + tig]);
            uint32_t a1 = rawu(sT[(gid + 8) * ET_ST + k0 + tig]);
            uint32_t a2 = rawu(sT[gid * ET_ST + k0 + tig + 4]);
            uint32_t a3 = rawu(sT[(gid + 8) * ET_ST + k0 + tig + 4]);
            const float2* bp = (const float2*)(sB2 + ((kc * 64 + gid) << 3) + 2 * tig);
#pragma unroll
            for (int t = 0; t < 8; t++) {
                float2 bv = bp[t * 32];
                mma16n8k8(D[t], a0, a1, a2, a3, rawu(bv.x), rawu(bv.y));
            }
        }
#pragma unroll
        for (int t = 0; t < 8; t++) {
            float2 bb = __ldg((const float2*)(bns2 + 8 * t + 2 * tig));
            float2 lo, hi;
            lo.x = D[t][0] + bb.x; lo.y = D[t][1] + bb.y;
            hi.x = D[t][2] + bb.x; hi.y = D[t][3] + bb.y;
            *(float2*)&g_ns_acc[(size_t)(n0 + gid) * 64 + 8 * t + 2 * tig] = lo;
            *(float2*)&g_ns_acc[(size_t)(n0 + gid + 8) * 64 + 8 * t + 2 * tig] = hi;
        }
    }
}

// ---------------------------------------------------------------------------
// Kernel A_vt: nv1 -> g_nv_acc (x3), ||nt1|| -> g_nt_norm (9 sq-acc)
// smem: 2*64*64 = 8192 floats (32,768 B)
// ---------------------------------------------------------------------------
#define AVT_SMEM_BYTES ((64*64 + 64*64) * 4)

__global__ void __launch_bounds__(256, 2) nodeAvt_kernel(
    const float* __restrict__ h_nv, const float* __restrict__ h_nt,
    const float* __restrict__ Wnv1, const float* __restrict__ Wnt1, int N)
{
    extern __shared__ float sm[];
    float* sBnv = sm;
    float* sBnt = sBnv + 64 * 64;

    load_wt_pair_tf32(Wnv1, sBnv, 0, 64, 64, 64);
    load_wt_pair_tf32(Wnt1, sBnt, 0, 64, 64, 64);
    __syncthreads();

    const int lane = threadIdx.x & 31;
    const int warp = threadIdx.x >> 5;
    const int gid = lane >> 2;
    const int tig = lane & 3;

    const int gw = blockIdx.x * 8 + warp;
    const int GW = gridDim.x * 8;
    const int ngroups = N >> 4;

    for (int g = gw; g < ngroups; g += GW) {
        const int n0 = g * 16;

#pragma unroll 1
        for (int a = 0; a < 3; a++) {
            float C[8][4];
#pragma unroll
            for (int t = 0; t < 8; t++) { C[t][0]=0.f; C[t][1]=0.f; C[t][2]=0.f; C[t][3]=0.f; }
            const float* rA0 = h_nv + (size_t)(n0 + gid) * 192 + a * 64;
            const float* rA1 = rA0 + 8 * 192;
#pragma unroll
            for (int kc = 0; kc < 8; kc++) {
                const int k0 = kc * 8;
                uint32_t a0 = rawu(__ldg(rA0 + k0 + tig));
                uint32_t a1 = rawu(__ldg(rA1 + k0 + tig));
                uint32_t a2 = rawu(__ldg(rA0 + k0 + tig + 4));
                uint32_t a3 = rawu(__ldg(rA1 + k0 + tig + 4));
                const float2* bp = (const float2*)(sBnv + ((kc * 64 + gid) << 3) + 2 * tig);
#pragma unroll
                for (int t = 0; t < 8; t++) {
                    float2 bv = bp[t * 32];
                    mma16n8k8(C[t], a0, a1, a2, a3, rawu(bv.x), rawu(bv.y));
                }
            }
#pragma unroll
            for (int t = 0; t < 8; t++) {
                float2 lo, hi;
                lo.x = C[t][0]; lo.y = C[t][1];
                hi.x = C[t][2]; hi.y = C[t][3];
                *(float2*)&g_nv_acc[(size_t)(n0 + gid) * 192 + a * 64 + 8 * t + 2 * tig] = lo;
                *(float2*)&g_nv_acc[(size_t)(n0 + gid + 8) * 192 + a * 64 + 8 * t + 2 * tig] = hi;
            }
        }

        float sq[8][4];
#pragma unroll
        for (int t = 0; t < 8; t++) { sq[t][0]=0.f; sq[t][1]=0.f; sq[t][2]=0.f; sq[t][3]=0.f; }
#pragma unroll 1
        for (int c = 0; c < 9; c++) {
            float C[8][4];
#pragma unroll
            for (int t = 0; t < 8; t++) { C[t][0]=0.f; C[t][1]=0.f; C[t][2]=0.f; C[t][3]=0.f; }
            const float* rA0 = h_nt + (size_t)(n0 + gid) * 576 + c * 64;
            const float* rA1 = rA0 + 8 * 576;
#pragma unroll
            for (int kc = 0; kc < 8; kc++) {
                const int k0 = kc * 8;
                uint32_t a0 = rawu(__ldg(rA0 + k0 + tig));
                uint32_t a1 = rawu(__ldg(rA1 + k0 + tig));
                uint32_t a2 = rawu(__ldg(rA0 + k0 + tig + 4));
                uint32_t a3 = rawu(__ldg(rA1 + k0 + tig + 4));
                const float2* bp = (const float2*)(sBnt + ((kc * 64 + gid) << 3) + 2 * tig);
#pragma unroll
                for (int t = 0; t < 8; t++) {
                    float2 bv = bp[t * 32];
                    mma16n8k8(C[t], a0, a1, a2, a3, rawu(bv.x), rawu(bv.y));
                }
            }
#pragma unroll
            for (int t = 0; t < 8; t++) {
                sq[t][0] += C[t][0] * C[t][0];
                sq[t][1] += C[t][1] * C[t][1];
                sq[t][2] += C[t][2] * C[t][2];
                sq[t][3] += C[t][3] * C[t][3];
            }
        }
#pragma unroll
        for (int t = 0; t < 8; t++) {
            float2 lo, hi;
            lo.x = sqrtf(sq[t][0]); lo.y = sqrtf(sq[t][1]);
            hi.x = sqrtf(sq[t][2]); hi.y = sqrtf(sq[t][3]);
            *(float2*)&g_nt_norm[(size_t)(n0 + gid) * 64 + 8 * t + 2 * tig] = lo;
            *(float2*)&g_nt_norm[(size_t)(n0 + gid + 8) * 64 + 8 * t + 2 * tig] = hi;
        }
    }
}

// ---------------------------------------------------------------------------
// Edge kernel: es MLP + ev1, scatter (v4 reds). 16 edges/warp.
// smem: 128*64 + 2*64*64 + 8*16*68 = 25088 floats (100,352 B) -> 2 CTAs/SM
// ---------------------------------------------------------------------------
#define E_SMEM_BYTES ((128*64 + 64*64 + 64*64 + 8*16*ET_ST) * 4)

__global__ void __launch_bounds__(256, 2) edge_kernel(
    const float* __restrict__ h_es, const float* __restrict__ h_ev,
    const int* __restrict__ idx1, const int* __restrict__ idx2,
    const float* __restrict__ Wes1, const float* __restrict__ bes1,
    const float* __restrict__ Wes2, const float* __restrict__ bes2,
    const float* __restrict__ Wev1, int E)
{
    extern __shared__ float sm[];
    float* sB1  = sm;
    float* sB2  = sB1 + 128 * 64;
    float* sBev = sB2 + 64 * 64;
    float* sTA  = sBev + 64 * 64;

    load_wt_pair_tf32(Wes1, sB1, 0, 64, 128, 64);
    load_wt_pair_tf32(Wes2, sB2, 0, 64, 64, 64);
    load_wt_pair_tf32(Wev1, sBev, 0, 64, 64, 64);
    __syncthreads();

    const int lane = threadIdx.x & 31;
    const int warp = threadIdx.x >> 5;
    const int gid = lane >> 2;
    const int tig = lane & 3;
    float* sT = sTA + warp * (16 * ET_ST);

    const int gw = blockIdx.x * 8 + warp;
    const int GW = gridDim.x * 8;
    const int ngroups = E >> 4;

    for (int g = gw; g < ngroups; g += GW) {
        const int e0 = g * 16;

        float C[8][4];
#pragma unroll
        for (int t = 0; t < 8; t++) { C[t][0]=0.f; C[t][1]=0.f; C[t][2]=0.f; C[t][3]=0.f; }
        {
            const float* rA0 = h_es + (size_t)(e0 + gid) * 128;
            const float* rA1 = rA0 + 8 * 128;
#pragma unroll
            for (int kc = 0; kc < 16; kc++) {
                const int k0 = kc * 8;
                uint32_t a0 = rawu(__ldg(rA0 + k0 + tig));
                uint32_t a1 = rawu(__ldg(rA1 + k0 + tig));
                uint32_t a2 = rawu(__ldg(rA0 + k0 + tig + 4));
                uint32_t a3 = rawu(__ldg(rA1 + k0 + tig + 4));
                const float2* bp = (const float2*)(sB1 + ((kc * 64 + gid) << 3) + 2 * tig);
#pragma unroll
                for (int t = 0; t < 8; t++) {
                    float2 bv = bp[t * 32];
                    mma16n8k8(C[t], a0, a1, a2, a3, rawu(bv.x), rawu(bv.y));
                }
            }
        }
        __syncwarp();
#pragma unroll
        for (int t = 0; t < 8; t++) {
            float2 bb = __ldg((const float2*)(bes1 + 8 * t + 2 * tig));
            float2 lo, hi;
            lo.x = silu_(C[t][0] + bb.x); lo.y = silu_(C[t][1] + bb.y);
            hi.x = silu_(C[t][2] + bb.x); hi.y = silu_(C[t][3] + bb.y);
            *(float2*)&sT[gid * ET_ST + 8 * t + 2 * tig] = lo;
            *(float2*)&sT[(gid + 8) * ET_ST + 8 * t + 2 * tig] = hi;
        }
        __syncwarp();

        float D[8][4];
#pragma unroll
        for (int t = 0; t < 8; t++) { D[t][0]=0.f; D[t][1]=0.f; D[t][2]=0.f; D[t][3]=0.f; }
#pragma unroll
        for (int kc = 0; kc < 8; kc++) {
            const int k0 = kc * 8;
            uint32_t a0 = rawu(sT[gid * ET_ST + k0 + tig]);
            uint32_t a1 = rawu(sT[(gid + 8) * ET_ST + k0 + tig]);
            uint32_t a2 = rawu(sT[gid * ET_ST + k0 + tig + 4]);
            uint32_t a3 = rawu(sT[(gid + 8) * ET_ST + k0 + tig + 4]);
            const float2* bp = (const float2*)(sB2 + ((kc * 64 + gid) << 3) + 2 * tig);
#pragma unroll
            for (int t = 0; t < 8; t++) {
                float2 bv = bp[t * 32];
                mma16n8k8(D[t], a0, a1, a2, a3, rawu(bv.x), rawu(bv.y));
            }
        }
        __syncwarp();
#pragma unroll
        for (int t = 0; t < 8; t++) {
            float2 bb = __ldg((const float2*)(bes2 + 8 * t + 2 * tig));
            float2 lo, hi;
            lo.x = D[t][0] + bb.x; lo.y = D[t][1] + bb.y;
            hi.x = D[t][2] + bb.x; hi.y = D[t][3] + bb.y;
            *(float2*)&sT[gid * ET_ST + 8 * t + 2 * tig] = lo;
            *(float2*)&sT[(gid + 8) * ET_ST + 8 * t + 2 * tig] = hi;
        }
        __syncwarp();

#pragma unroll
        for (int j = 0; j < 8; j++) {
            int cid = lane + 32 * j;
            int r = cid >> 4, c = (cid & 15) * 4;
            float4 v = *(const float4*)&sT[r * ET_ST + c];
            int i1 = __ldg(idx1 + e0 + r), i2 = __ldg(idx2 + e0 + r);
            red_add_v4(g_ns_acc + (size_t)i1 * 64 + c, v);
            red_add_v4(g_ns_acc + (size_t)i2 * 64 + c, v);
        }

#pragma unroll 1
        for (int a = 0; a < 3; a++) {
            float Ea[8][4];
#pragma unroll
            for (int t = 0; t < 8; t++) { Ea[t][0]=0.f; Ea[t][1]=0.f; Ea[t][2]=0.f; Ea[t][3]=0.f; }
            const float* rV0 = h_ev + (size_t)(e0 + gid) * 192 + a * 64;
            const float* rV1 = rV0 + 8 * 192;
#pragma unroll
            for (int kc = 0; kc < 8; kc++) {
                const int k0 = kc * 8;
                uint32_t a0 = rawu(__ldg(rV0 + k0 + tig));
                uint32_t a1 = rawu(__ldg(rV1 + k0 + tig));
                uint32_t a2 = rawu(__ldg(rV0 + k0 + tig + 4));
                uint32_t a3 = rawu(__ldg(rV1 + k0 + tig + 4));
                const float2* bp = (const float2*)(sBev + ((kc * 64 + gid) << 3) + 2 * tig);
#pragma unroll
                for (int t = 0; t < 8; t++) {
                    float2 bv = bp[t * 32];
                    mma16n8k8(Ea[t], a0, a1, a2, a3, rawu(bv.x), rawu(bv.y));
                }
            }
            __syncwarp();
#pragma unroll
            for (int t = 0; t < 8; t++) {
                float2 lo, hi;
                lo.x = Ea[t][0]; lo.y = Ea[t][1];
                hi.x = Ea[t][2]; hi.y = Ea[t][3];
                *(float2*)&sT[gid * ET_ST + 8 * t + 2 * tig] = lo;
                *(float2*)&sT[(gid + 8) * ET_ST + 8 * t + 2 * tig] = hi;
            }
            __syncwarp();
#pragma unroll
            for (int j = 0; j < 8; j++) {
                int cid = lane + 32 * j;
                int r = cid >> 4, c = (cid & 15) * 4;
                float4 v = *(const float4*)&sT[r * ET_ST + c];
                int i1 = __ldg(idx1 + e0 + r), i2 = __ldg(idx2 + e0 + r);
                red_add_v4(g_nv_acc + (size_t)i1 * 192 + a * 64 + c, v);
                red_add_v4(g_nv_acc + (size_t)i2 * 192 + a * 64 + c, v);
            }
        }
    }
}

// ---------------------------------------------------------------------------
// Kernel C1: h_cat gather + K=192, N=96 GEMM -> g_mid
// smem: 192*96 + 8*16*196 = 43520 floats (174,080 B) -> 1 CTA/SM
// ---------------------------------------------------------------------------
#define C1_T_ST 196
#define C1_SMEM_BYTES ((192*96 + 8*16*C1_T_ST) * 4)

__global__ void __launch_bounds__(256, 1) nodeC1_kernel(
    const float* __restrict__ Wc1, const float* __restrict__ bc1, int N)
{
    extern __shared__ float sm[];
    float* sB  = sm;                 // K=192, NW=96 pair layout
    float* sTA = sB + 192 * 96;

    load_wt_pair_tf32(Wc1, sB, 0, 96, 192, 96);
    __syncthreads();

    const int lane = threadIdx.x & 31;
    const int warp = threadIdx.x >> 5;
    const int gid = lane >> 2;
    const int tig = lane & 3;
    float* sT = sTA + warp * (16 * C1_T_ST);

    const int gw = blockIdx.x * 8 + warp;
    const int GW = gridDim.x * 8;
    const int ngroups = N >> 4;

    for (int g = gw; g < ngroups; g += GW) {
        const int n0 = g * 16;
        __syncwarp();
#pragma unroll 1
        for (int r = 0; r < 16; r++) {
            const size_t n = (size_t)(n0 + r);
            float2 s = *(const float2*)&g_ns_acc[n * 64 + 2 * lane];
            *(float2*)&sT[r * C1_T_ST + 2 * lane] = s;
            float2 v0 = *(const float2*)&g_nv_acc[n * 192 + 0   + 2 * lane];
            float2 v1 = *(const float2*)&g_nv_acc[n * 192 + 64  + 2 * lane];
            float2 v2 = *(const float2*)&g_nv_acc[n * 192 + 128 + 2 * lane];
            float2 nn;
            nn.x = sqrtf(v0.x * v0.x + v1.x * v1.x + v2.x * v2.x);
            nn.y = sqrtf(v0.y * v0.y + v1.y * v1.y + v2.y * v2.y);
            *(float2*)&sT[r * C1_T_ST + 64 + 2 * lane] = nn;
            float2 tn = *(const float2*)&g_nt_norm[n * 64 + 2 * lane];
            *(float2*)&sT[r * C1_T_ST + 128 + 2 * lane] = tn;
        }
        __syncwarp();

        float C[12][4];
#pragma unroll
        for (int t = 0; t < 12; t++) { C[t][0]=0.f; C[t][1]=0.f; C[t][2]=0.f; C[t][3]=0.f; }
#pragma unroll
        for (int kc = 0; kc < 24; kc++) {
            const int k0 = kc * 8;
            uint32_t a0 = rawu(sT[gid * C1_T_ST + k0 + tig]);
            uint32_t a1 = rawu(sT[(gid + 8) * C1_T_ST + k0 + tig]);
            uint32_t a2 = rawu(sT[gid * C1_T_ST + k0 + tig + 4]);
            uint32_t a3 = rawu(sT[(gid + 8) * C1_T_ST + k0 + tig + 4]);
            const float2* bp = (const float2*)(sB + ((kc * 96 + gid) << 3) + 2 * tig);
#pragma unroll
            for (int t = 0; t < 12; t++) {
                float2 bv = bp[t * 32];
                mma16n8k8(C[t], a0, a1, a2, a3, rawu(bv.x), rawu(bv.y));
            }
        }
#pragma unroll
        for (int t = 0; t < 12; t++) {
            float2 bb = __ldg((const float2*)(bc1 + 8 * t + 2 * tig));
            float2 lo, hi;
            lo.x = silu_(C[t][0] + bb.x); lo.y = silu_(C[t][1] + bb.y);
            hi.x = silu_(C[t][2] + bb.x); hi.y = silu_(C[t][3] + bb.y);
            *(float2*)&g_mid[(size_t)(n0 + gid) * 96 + 8 * t + 2 * tig] = lo;
            *(float2*)&g_mid[(size_t)(n0 + gid + 8) * 96 + 8 * t + 2 * tig] = hi;
        }
    }
}

// ---------------------------------------------------------------------------
// Kernel C2a: ns_out = g_mid @ Wc2[0:128].T + bc2 + h_ns
// smem: 96*128 = 12288 floats (49,152 B) -> 2 CTAs/SM
// ---------------------------------------------------------------------------
#define C2A_SMEM_BYTES ((96*128) * 4)

__global__ void __launch_bounds__(256, 2) nodeC2a_kernel(
    const float* __restrict__ h_ns,
    const float* __restrict__ Wc2, const float* __restrict__ bc2,
    float* __restrict__ out, int N)
{
    extern __shared__ float sm[];
    float* sB = sm;   // K=96, NW=128 pair layout (Wc2 rows 0..127)

    load_wt_pair_tf32(Wc2, sB, 0, 128, 96, 128);
    __syncthreads();

    const int lane = threadIdx.x & 31;
    const int warp = threadIdx.x >> 5;
    const int gid = lane >> 2;
    const int tig = lane & 3;

    const int gw = blockIdx.x * 8 + warp;
    const int GW = gridDim.x * 8;
    const int ngroups = N >> 4;

    for (int g = gw; g < ngroups; g += GW) {
        const int n0 = g * 16;
        const float* rA0 = g_mid + (size_t)(n0 + gid) * 96;
        const float* rA1 = rA0 + 8 * 96;

#pragma unroll 1
        for (int half = 0; half < 2; half++) {
            const int oc = half * 64;
            float C[8][4];
#pragma unroll
            for (int t = 0; t < 8; t++) { C[t][0]=0.f; C[t][1]=0.f; C[t][2]=0.f; C[t][3]=0.f; }
#pragma unroll
            for (int kc = 0; kc < 12; kc++) {
                const int k0 = kc * 8;
                uint32_t a0 = rawu(__ldg(rA0 + k0 + tig));
                uint32_t a1 = rawu(__ldg(rA1 + k0 + tig));
                uint32_t a2 = rawu(__ldg(rA0 + k0 + tig + 4));
                uint32_t a3 = rawu(__ldg(rA1 + k0 + tig + 4));
                const float2* bp = (const float2*)(sB + ((kc * 128 + oc + gid) << 3) + 2 * tig);
#pragma unroll
                for (int t = 0; t < 8; t++) {
                    float2 bv = bp[t * 32];
                    mma16n8k8(C[t], a0, a1, a2, a3, rawu(bv.x), rawu(bv.y));
                }
            }
#pragma unroll
            for (int t = 0; t < 8; t++) {
                const int c = oc + 8 * t + 2 * tig;
                float2 bb = __ldg((const float2*)(bc2 + c));
                float2 h0 = __ldg((const float2*)(h_ns + (size_t)(n0 + gid) * 128 + c));
                float2 h1 = __ldg((const float2*)(h_ns + (size_t)(n0 + gid + 8) * 128 + c));
                float2 lo, hi;
                lo.x = C[t][0] + bb.x + h0.x; lo.y = C[t][1] + bb.y + h0.y;
                hi.x = C[t][2] + bb.x + h1.x; hi.y = C[t][3] + bb.y + h1.y;
                *(float2*)&out[(size_t)(n0 + gid) * 128 + c] = lo;
                *(float2*)&out[(size_t)(n0 + gid + 8) * 128 + c] = hi;
            }
        }
    }
}

// ---------------------------------------------------------------------------
// Kernel C2b: register-resident gates + nv/nt epilogues
// smem: 96*128 + 2*64*64 = 20480 floats (81,920 B) -> 2 CTAs/SM
// ---------------------------------------------------------------------------
#define C2B_SMEM_BYTES ((96*128 + 64*64 + 64*64) * 4)

__global__ void __launch_bounds__(256, 2) nodeC2b_kernel(
    const float* __restrict__ h_nv, const float* __restrict__ h_nt,
    const float* __restrict__ Wnv2, const float* __restrict__ Wnt2,
    const float* __restrict__ Wc2, const float* __restrict__ bc2,
    float* __restrict__ out, int N)
{
    extern __shared__ float sm[];
    float* sBg  = sm;                // K=96, NW=128 (Wc2 rows 128..255)
    float* sBnv = sBg + 96 * 128;
    float* sBnt = sBnv + 64 * 64;

    load_wt_pair_tf32(Wc2, sBg, 128, 128, 96, 128);
    load_wt_pair_tf32(Wnv2, sBnv, 0, 64, 64, 64);
    load_wt_pair_tf32(Wnt2, sBnt, 0, 64, 64, 64);
    __syncthreads();

    const int lane = threadIdx.x & 31;
    const int warp = threadIdx.x >> 5;
    const int gid = lane >> 2;
    const int tig = lane & 3;

    float* nv_out = out + (size_t)N * 128;
    float* nt_out = out + (size_t)N * 320;

    const int gw = blockIdx.x * 8 + warp;
    const int GW = gridDim.x * 8;
    const int ngroups = N >> 4;

    for (int g = gw; g < ngroups; g += GW) {
        const int n0 = g * 16;
        const float* rM0 = g_mid + (size_t)(n0 + gid) * 96;
        const float* rM1 = rM0 + 8 * 96;

        // nv gates (cols 0..63 of the gate half)
        float G[8][4];
#pragma unroll
        for (int t = 0; t < 8; t++) { G[t][0]=0.f; G[t][1]=0.f; G[t][2]=0.f; G[t][3]=0.f; }
#pragma unroll
        for (int kc = 0; kc < 12; kc++) {
            const int k0 = kc * 8;
            uint32_t a0 = rawu(__ldg(rM0 + k0 + tig));
            uint32_t a1 = rawu(__ldg(rM1 + k0 + tig));
            uint32_t a2 = rawu(__ldg(rM0 + k0 + tig + 4));
            uint32_t a3 = rawu(__ldg(rM1 + k0 + tig + 4));
            const float2* bp = (const float2*)(sBg + ((kc * 128 + gid) << 3) + 2 * tig);
#pragma unroll
            for (int t = 0; t < 8; t++) {
                float2 bv = bp[t * 32];
                mma16n8k8(G[t], a0, a1, a2, a3, rawu(bv.x), rawu(bv.y));
            }
        }
#pragma unroll
        for (int t = 0; t < 8; t++) {
            float2 bb = __ldg((const float2*)(bc2 + 128 + 8 * t + 2 * tig));
            G[t][0] = sigm_(G[t][0] + bb.x); G[t][1] = sigm_(G[t][1] + bb.y);
            G[t][2] = sigm_(G[t][2] + bb.x); G[t][3] = sigm_(G[t][3] + bb.y);
        }

#pragma unroll 1
        for (int a = 0; a < 3; a++) {
            float Ea[8][4];
#pragma unroll
            for (int t = 0; t < 8; t++) { Ea[t][0]=0.f; Ea[t][1]=0.f; Ea[t][2]=0.f; Ea[t][3]=0.f; }
            const float* rV0 = h_nv + (size_t)(n0 + gid) * 192 + a * 64;
            const float* rV1 = rV0 + 8 * 192;
#pragma unroll
            for (int kc = 0; kc < 8; kc++) {
                const int k0 = kc * 8;
                uint32_t a0 = rawu(__ldg(rV0 + k0 + tig));
                uint32_t a1 = rawu(__ldg(rV1 + k0 + tig));
                uint32_t a2 = rawu(__ldg(rV0 + k0 + tig + 4));
                uint32_t a3 = rawu(__ldg(rV1 + k0 + tig + 4));
                const float2* bp = (const float2*)(sBnv + ((kc * 64 + gid) << 3) + 2 * tig);
#pragma unroll
                for (int t = 0; t < 8; t++) {
                    float2 bv = bp[t * 32];
                    mma16n8k8(Ea[t], a0, a1, a2, a3, rawu(bv.x), rawu(bv.y));
                }
            }
#pragma unroll
            for (int t = 0; t < 8; t++) {
                const int c = a * 64 + 8 * t + 2 * tig;
                float2 h0 = __ldg((const float2*)(h_nv + (size_t)(n0 + gid) * 192 + c));
                float2 h1 = __ldg((const float2*)(h_nv + (size_t)(n0 + gid + 8) * 192 + c));
                float2 lo, hi;
                lo.x = G[t][0] * Ea[t][0] + h0.x; lo.y = G[t][1] * Ea[t][1] + h0.y;
                hi.x = G[t][2] * Ea[t][2] + h1.x; hi.y = G[t][3] * Ea[t][3] + h1.y;
                *(float2*)&nv_out[(size_t)(n0 + gid) * 192 + c] = lo;
                *(float2*)&nv_out[(size_t)(n0 + gid + 8) * 192 + c] = hi;
            }
        }

        // nt gates (cols 64..127 of the gate half)
#pragma unroll
        for (int t = 0; t < 8; t++) { G[t][0]=0.f; G[t][1]=0.f; G[t][2]=0.f; G[t][3]=0.f; }
#pragma unroll
        for (int kc = 0; kc < 12; kc++) {
            const int k0 = kc * 8;
            uint32_t a0 = rawu(__ldg(rM0 + k0 + tig));
            uint32_t a1 = rawu(__ldg(rM1 + k0 + tig));
            uint32_t a2 = rawu(__ldg(rM0 + k0 + tig + 4));
            uint32_t a3 = rawu(__ldg(rM1 + k0 + tig + 4));
            const float2* bp = (const float2*)(sBg + ((kc * 128 + 64 + gid) << 3) + 2 * tig);
#pragma unroll
            for (int t = 0; t < 8; t++) {
                float2 bv = bp[t * 32];
                mma16n8k8(G[t], a0, a1, a2, a3, rawu(bv.x), rawu(bv.y));
            }
        }
#pragma unroll
        for (int t = 0; t < 8; t++) {
            float2 bb = __ldg((const float2*)(bc2 + 192 + 8 * t + 2 * tig));
            G[t][0] = sigm_(G[t][0] + bb.x); G[t][1] = sigm_(G[t][1] + bb.y);
            G[t][2] = sigm_(G[t][2] + bb.x); G[t][3] = sigm_(G[t][3] + bb.y);
        }

#pragma unroll 1
        for (int c9 = 0; c9 < 9; c9++) {
            float Ea[8][4];
#pragma unroll
            for (int t = 0; t < 8; t++) { Ea[t][0]=0.f; Ea[t][1]=0.f; Ea[t][2]=0.f; Ea[t][3]=0.f; }
            const float* rT0 = h_nt + (size_t)(n0 + gid) * 576 + c9 * 64;
            const float* rT1 = rT0 + 8 * 576;
#pragma unroll
            for (int kc = 0; kc < 8; kc++) {
                const int k0 = kc * 8;
                uint32_t a0 = rawu(__ldg(rT0 + k0 + tig));
                uint32_t a1 = rawu(__ldg(rT1 + k0 + tig));
                uint32_t a2 = rawu(__ldg(rT0 + k0 + tig + 4));
                uint32_t a3 = rawu(__ldg(rT1 + k0 + tig + 4));
                const float2* bp = (const float2*)(sBnt + ((kc * 64 + gid) << 3) + 2 * tig);
#pragma unroll
                for (int t = 0; t < 8; t++) {
                    float2 bv = bp[t * 32];
                    mma16n8k8(Ea[t], a0, a1, a2, a3, rawu(bv.x), rawu(bv.y));
                }
            }
#pragma unroll
            for (int t = 0; t < 8; t++) {
                const int c = c9 * 64 + 8 * t + 2 * tig;
                float2 h0 = __ldg((const float2*)(h_nt + (size_t)(n0 + gid) * 576 + c));
                float2 h1 = __ldg((const float2*)(h_nt + (size_t)(n0 + gid + 8) * 576 + c));
                float2 lo, hi;
                lo.x = G[t][0] * Ea[t][0] + h0.x; lo.y = G[t][1] * Ea[t][1] + h0.y;
                hi.x = G[t][2] * Ea[t][2] + h1.x; hi.y = G[t][3] * Ea[t][3] + h1.y;
                *(float2*)&nt_out[(size_t)(n0 + gid) * 576 + c] = lo;
                *(float2*)&nt_out[(size_t)(n0 + gid + 8) * 576 + c] = hi;
            }
        }
    }
}

// ---------------------------------------------------------------------------
extern "C" void kernel_launch(void* const* d_in, const int* in_sizes, int n_in,
                              void* d_out, int out_size)
{
    const float* h_ns = (const float*)d_in[0];
    const float* h_nv = (const float*)d_in[1];
    const float* h_nt = (const float*)d_in[2];
    const float* h_es = (const float*)d_in[3];
    const float* h_ev = (const float*)d_in[4];
    const int*   idx1 = (const int*)d_in[5];
    const int*   idx2 = (const int*)d_in[6];
    const float* Wns1 = (const float*)d_in[7];
    const float* bns1 = (const float*)d_in[8];
    const float* Wns2 = (const float*)d_in[9];
    const float* bns2 = (const float*)d_in[10];
    const float* Wes1 = (const float*)d_in[11];
    const float* bes1 = (const float*)d_in[12];
    const float* Wes2 = (const float*)d_in[13];
    const float* bes2 = (const float*)d_in[14];
    const float* Wnv1 = (const float*)d_in[15];
    const float* Wnv2 = (const float*)d_in[16];
    const float* Wev1 = (const float*)d_in[17];
    const float* Wnt1 = (const float*)d_in[18];
    const float* Wnt2 = (const float*)d_in[19];
    const float* Wc1  = (const float*)d_in[20];
    const float* bc1  = (const float*)d_in[21];
    const float* Wc2  = (const float*)d_in[22];
    const float* bc2  = (const float*)d_in[23];
    float* out = (float*)d_out;

    const int N = in_sizes[0] / 128;   // h_ns is (N, 128)
    const int E = in_sizes[5];         // atom_index1 is (E,)

    cudaFuncSetAttribute(nodeAs_kernel,  cudaFuncAttributeMaxDynamicSharedMemorySize, AS_SMEM_BYTES);
    cudaFuncSetAttribute(nodeAvt_kernel, cudaFuncAttributeMaxDynamicSharedMemorySize, AVT_SMEM_BYTES);
    cudaFuncSetAttribute(edge_kernel,    cudaFuncAttributeMaxDynamicSharedMemorySize, E_SMEM_BYTES);
    cudaFuncSetAttribute(nodeC1_kernel,  cudaFuncAttributeMaxDynamicSharedMemorySize, C1_SMEM_BYTES);
    cudaFuncSetAttribute(nodeC2a_kernel, cudaFuncAttributeMaxDynamicSharedMemorySize, C2A_SMEM_BYTES);
    cudaFuncSetAttribute(nodeC2b_kernel, cudaFuncAttributeMaxDynamicSharedMemorySize, C2B_SMEM_BYTES);

    nodeAs_kernel<<<304, 256, AS_SMEM_BYTES>>>(h_ns, Wns1, bns1, Wns2, bns2, N);

    nodeAvt_kernel<<<304, 256, AVT_SMEM_BYTES>>>(h_nv, h_nt, Wnv1, Wnt1, N);

    edge_kernel<<<304, 256, E_SMEM_BYTES>>>(
        h_es, h_ev, idx1, idx2, Wes1, bes1, Wes2, bes2, Wev1, E);

    nodeC1_kernel<<<152, 256, C1_SMEM_BYTES>>>(Wc1, bc1, N);

    nodeC2a_kernel<<<304, 256, C2A_SMEM_BYTES>>>(h_ns, Wc2, bc2, out, N);

    nodeC2b_kernel<<<304, 256, C2B_SMEM_BYTES>>>(
        h_nv, h_nt, Wnv2, Wnt2, Wc2, bc2, out, N);
}